// round 4
// baseline (speedup 1.0000x reference)
#include <cuda_runtime.h>
#include <cuda_bf16.h>
#include <math.h>

// Problem constants (LocalSubgraphTransformer)
#define S_   2048
#define K_   32
#define H_   256
#define NH_  8
#define DH_  32
#define L_   4
#define ED_  16
#define FFN_ 512
#define EPS_ 64
#define E_   (S_*EPS_)
#define BUFLD 768

// 32 MB scratch: edge bias [S][h][k=dst][q=src] in bf16
__device__ __nv_bfloat16 g_bias16[(size_t)S_ * NH_ * K_ * K_];

// ---------------------------------------------------------------------------
// Kernel A: per-subgraph edge bias via shared-memory scatter-add
// ---------------------------------------------------------------------------
__global__ __launch_bounds__(256) void edge_bias_kernel(
    const float* __restrict__ ea, const int* __restrict__ eidx,
    const float* __restrict__ eW, const float* __restrict__ eb)
{
    __shared__ float sb[NH_*K_*K_];   // [h][dst][src]
    __shared__ float sa[EPS_*ED_];
    __shared__ float sw[NH_*ED_];
    __shared__ float sbv[NH_];
    const int s = blockIdx.x, tid = threadIdx.x;

    if (tid < NH_*ED_) sw[tid] = eW[tid];
    if (tid < NH_)     sbv[tid] = eb[tid];
    for (int i = tid; i < EPS_*ED_;  i += 256) sa[i] = ea[(size_t)s*EPS_*ED_ + i];
    for (int i = tid; i < NH_*K_*K_; i += 256) sb[i] = 0.f;
    __syncthreads();

    #pragma unroll
    for (int t = tid; t < EPS_*NH_; t += 256) {
        const int i  = t >> 3;    // edge within subgraph
        const int hh = t & 7;     // head
        float p = sbv[hh];
        #pragma unroll
        for (int d = 0; d < ED_; d++) p = fmaf(sa[i*ED_+d], sw[hh*ED_+d], p);
        const int e  = s*EPS_ + i;
        const int sr = eidx[e];        // src = query index
        const int ds = eidx[E_ + e];   // dst = key index
        atomicAdd(&sb[hh*K_*K_ + ds*K_ + sr], p);
    }
    __syncthreads();
    for (int i = tid; i < NH_*K_*K_; i += 256)
        g_bias16[(size_t)s*NH_*K_*K_ + i] = __float2bfloat16(sb[i]);
}

// ---------------------------------------------------------------------------
// Kernel B: fused 4-layer transformer, one CTA per subgraph
// ---------------------------------------------------------------------------
// smem layout (float offsets)
#define OFF_X    0       /* 8192 */
#define OFF_XN   8192    /* 8192 */
#define OFF_BUF  16384   /* 24576: qkv [32][768] or ffn hidden [32][512] */
#define OFF_WT   40960   /* 8192: double-buffered W tile 2 x [128][32] swizzled */
#define OFF_BS16 49152   /* bf16[8192] = 4096 floats: bias [h][k][q] */
#define OFF_KM   53248   /* 32 */
#define OFF_V01  53280   /* 32 */
#define SMEM_FLOATS 53312

__device__ __forceinline__ void ffma2(unsigned long long& c,
                                      unsigned long long a, unsigned long long b) {
    asm("fma.rn.f32x2 %0, %1, %2, %0;" : "+l"(c) : "l"(a), "l"(b));
}

// C[32,N] = A[32,KA] @ W[N,KA]^T + bias ; MODE 0: store, 1: store+relu, 2: dst += C
// A: smem [32][KA]; W: global, staged through swizzled smem tiles via cp.async.
template<int N, int KA, int MODE>
__device__ __forceinline__ void mm32(const float* A, const float* __restrict__ W,
                                     const float* __restrict__ bias, float* dst,
                                     float* WT, int tid)
{
    const int rg = tid >> 5;   // warp -> rows rg*4..rg*4+3
    const int cg = tid & 31;   // lane -> 4 columns
    const int sw = cg & 7;
    const unsigned wt_s = (unsigned)__cvta_generic_to_shared(WT);
    constexpr int T = KA/32;   // k-tiles per pass

    for (int pass = 0; pass < N/128; pass++) {
        const float* Wp = W + (size_t)pass*128*KA;
        // prefetch tile 0 -> buffer 0
        #pragma unroll
        for (int it = 0; it < 4; it++) {
            const int v = it*256 + tid, cr = v >> 3, k4 = v & 7;
            const unsigned d = wt_s + (unsigned)((cr*32 + ((k4 ^ ((cr>>2)&7))<<2))*4);
            const float* g = Wp + cr*KA + k4*4;
            asm volatile("cp.async.cg.shared.global [%0], [%1], 16;" :: "r"(d), "l"(g) : "memory");
        }
        asm volatile("cp.async.commit_group;" ::: "memory");

        unsigned long long acc[4][4];
        #pragma unroll
        for (int j = 0; j < 4; j++)
            #pragma unroll
            for (int i = 0; i < 4; i++) acc[j][i] = 0ull;

        for (int kt = 0; kt < T; kt++) {
            asm volatile("cp.async.wait_group 0;" ::: "memory");
            __syncthreads();
            if (kt + 1 < T) {  // prefetch next tile into other buffer
                const float* Wn = Wp + (kt+1)*32;
                const unsigned bufn = ((kt+1) & 1) ? 4096u*4u : 0u;
                #pragma unroll
                for (int it = 0; it < 4; it++) {
                    const int v = it*256 + tid, cr = v >> 3, k4 = v & 7;
                    const unsigned d = wt_s + bufn +
                        (unsigned)((cr*32 + ((k4 ^ ((cr>>2)&7))<<2))*4);
                    const float* g = Wn + cr*KA + k4*4;
                    asm volatile("cp.async.cg.shared.global [%0], [%1], 16;" :: "r"(d), "l"(g) : "memory");
                }
                asm volatile("cp.async.commit_group;" ::: "memory");
            }
            const float* WTc = WT + ((kt & 1) ? 4096 : 0);
            const float* Ac  = A + kt*32;
            #pragma unroll
            for (int t8 = 0; t8 < 8; t8++) {
                ulonglong2 a[4], w[4];
                #pragma unroll
                for (int j = 0; j < 4; j++)   // broadcast (conflict-free)
                    a[j] = *(const ulonglong2*)(Ac + (rg*4+j)*KA + t8*4);
                #pragma unroll
                for (int i = 0; i < 4; i++)   // swizzled (phase-conflict-free)
                    w[i] = *(const ulonglong2*)(WTc + (cg*4+i)*32 + ((t8 ^ sw)<<2));
                #pragma unroll
                for (int j = 0; j < 4; j++)
                    #pragma unroll
                    for (int i = 0; i < 4; i++) {
                        ffma2(acc[j][i], a[j].x, w[i].x);
                        ffma2(acc[j][i], a[j].y, w[i].y);
                    }
            }
        }
        // epilogue
        const int c0 = pass*128 + cg*4;
        #pragma unroll
        for (int j = 0; j < 4; j++) {
            float4 r;
            float* rp = (float*)&r;
            #pragma unroll
            for (int i = 0; i < 4; i++) {
                float lo, hi;
                asm("mov.b64 {%0,%1}, %2;" : "=f"(lo), "=f"(hi) : "l"(acc[j][i]));
                rp[i] = lo + hi + bias[c0+i];
            }
            if (MODE == 1) {
                r.x = fmaxf(r.x, 0.f); r.y = fmaxf(r.y, 0.f);
                r.z = fmaxf(r.z, 0.f); r.w = fmaxf(r.w, 0.f);
            }
            float4* p = (float4*)(dst + (rg*4+j)*N + c0);
            if (MODE == 2) {
                float4 o = *p;
                r.x += o.x; r.y += o.y; r.z += o.z; r.w += o.w;
            }
            *p = r;
        }
    }
}

// LayerNorm over 32 rows of H_: warp w handles rows w*4..w*4+3
__device__ __forceinline__ void ln32(const float* src, float* dst,
                                     const float* __restrict__ g,
                                     const float* __restrict__ b, int tid)
{
    const int w = tid >> 5, lane = tid & 31;
    #pragma unroll
    for (int j = 0; j < 4; j++) {
        const int r = w*4 + j;
        float sum = 0.f, sq = 0.f;
        #pragma unroll
        for (int i = 0; i < 8; i++) {
            const float v = src[r*H_ + lane + i*32];
            sum += v; sq = fmaf(v, v, sq);
        }
        #pragma unroll
        for (int o = 16; o > 0; o >>= 1) {
            sum += __shfl_xor_sync(0xffffffffu, sum, o);
            sq  += __shfl_xor_sync(0xffffffffu, sq,  o);
        }
        const float mu   = sum * (1.f/H_);
        const float var  = sq * (1.f/H_) - mu*mu;
        const float rstd = rsqrtf(var + 1e-5f);
        #pragma unroll
        for (int i = 0; i < 8; i++) {
            const int c = lane + i*32;
            const float v = src[r*H_ + c];
            dst[r*H_ + c] = fmaf((v - mu)*rstd, g[c], b[c]);
        }
    }
}

// Attention: warp = head, lane = query row. qkv in BUF (ld 768), o -> XN (ld 256)
__device__ __forceinline__ void attn32(const float* BUF_, const __nv_bfloat16* BS,
                                       const float* KM, float* XN_, int tid)
{
    const int head = tid >> 5, lane = tid & 31;
    const float scale = 0.17677669529663687f;  // 1/sqrt(32)

    float4 q4[8];
    const float4* qp = (const float4*)(BUF_ + lane*BUFLD + head*32);
    #pragma unroll
    for (int j = 0; j < 8; j++) q4[j] = qp[j];

    float sc[32];
    float m = -3.0e38f;
    #pragma unroll
    for (int kr = 0; kr < 32; kr++) {
        const float4* kp = (const float4*)(BUF_ + kr*BUFLD + H_ + head*32);
        float s = 0.f;
        #pragma unroll
        for (int j = 0; j < 8; j++) {
            const float4 kk = kp[j];
            s = fmaf(q4[j].x, kk.x, s); s = fmaf(q4[j].y, kk.y, s);
            s = fmaf(q4[j].z, kk.z, s); s = fmaf(q4[j].w, kk.w, s);
        }
        const float bv = __bfloat162float(BS[head*1024 + kr*32 + lane]);
        s = fmaf(s, scale, bv) + KM[kr];
        sc[kr] = s;
        m = fmaxf(m, s);
    }
    float den = 0.f;
    #pragma unroll
    for (int kr = 0; kr < 32; kr++) { const float e = __expf(sc[kr] - m); sc[kr] = e; den += e; }
    const float inv = 1.f / den;
    #pragma unroll
    for (int kr = 0; kr < 32; kr++) sc[kr] *= inv;

    #pragma unroll
    for (int dg = 0; dg < 8; dg++) {
        float4 acc = make_float4(0.f, 0.f, 0.f, 0.f);
        #pragma unroll
        for (int kr = 0; kr < 32; kr++) {
            const float4 v4 = *(const float4*)(BUF_ + kr*BUFLD + 2*H_ + head*32 + dg*4);
            const float w = sc[kr];
            acc.x = fmaf(w, v4.x, acc.x); acc.y = fmaf(w, v4.y, acc.y);
            acc.z = fmaf(w, v4.z, acc.z); acc.w = fmaf(w, v4.w, acc.w);
        }
        *(float4*)(XN_ + lane*H_ + head*32 + dg*4) = acc;
    }
}

__global__ __launch_bounds__(256, 1) void xf_kernel(
    const float* __restrict__ h, const void* __restrict__ validp,
    const float* __restrict__ ln1g, const float* __restrict__ ln1b,
    const float* __restrict__ qkvW, const float* __restrict__ qkvb,
    const float* __restrict__ outW, const float* __restrict__ outb,
    const float* __restrict__ ln2g, const float* __restrict__ ln2b,
    const float* __restrict__ ff1W, const float* __restrict__ ff1b,
    const float* __restrict__ ff2W, const float* __restrict__ ff2b,
    const float* __restrict__ fng, const float* __restrict__ fnb,
    float* __restrict__ out)
{
    extern __shared__ float sm[];
    float* X   = sm + OFF_X;
    float* XN  = sm + OFF_XN;
    float* BUF = sm + OFF_BUF;
    float* WT  = sm + OFF_WT;
    __nv_bfloat16* BS16 = (__nv_bfloat16*)(sm + OFF_BS16);
    float* KM  = sm + OFF_KM;
    float* V01 = sm + OFF_V01;
    const int s = blockIdx.x, tid = threadIdx.x;

    // Detect 'valid' encoding: byte bools vs 32-bit words.
    const unsigned char* vb = (const unsigned char*)validp;
    bool bytemode = false;
    #pragma unroll
    for (int i = 1; i < 128; i += 4) bytemode |= (vb[i] != 0);

    if (tid < K_) {
        bool v;
        if (bytemode) v = vb[s*K_ + tid] != 0;
        else          v = ((const unsigned int*)validp)[s*K_ + tid] != 0u;
        KM[tid]  = v ? 0.f : -1e30f;
        V01[tid] = v ? 1.f : 0.f;
    }
    for (int i = tid; i < K_*H_/4; i += 256)
        ((float4*)X)[i] = ((const float4*)(h + (size_t)s*K_*H_))[i];
    // bias already [h][k][q] bf16: straight vector copy (1024 uint4)
    {
        const uint4* gb = (const uint4*)(g_bias16 + (size_t)s*NH_*K_*K_);
        uint4* sb = (uint4*)BS16;
        for (int i = tid; i < 1024; i += 256) sb[i] = gb[i];
    }
    __syncthreads();

    for (int l = 0; l < L_; l++) {
        ln32(X, XN, ln1g + l*H_, ln1b + l*H_, tid);
        __syncthreads();
        mm32<768, 256, 0>(XN, qkvW + (size_t)l*3*H_*H_, qkvb + l*3*H_, BUF, WT, tid);
        __syncthreads();
        attn32(BUF, BS16, KM, XN, tid);
        __syncthreads();
        mm32<256, 256, 2>(XN, outW + (size_t)l*H_*H_, outb + l*H_, X, WT, tid);
        __syncthreads();
        ln32(X, XN, ln2g + l*H_, ln2b + l*H_, tid);
        __syncthreads();
        mm32<512, 256, 1>(XN, ff1W + (size_t)l*FFN_*H_, ff1b + l*FFN_, BUF, WT, tid);
        __syncthreads();
        mm32<256, 512, 2>(BUF, ff2W + (size_t)l*H_*FFN_, ff2b + l*H_, X, WT, tid);
        __syncthreads();
    }

    // final LN + masked mean over k
    ln32(X, XN, fng, fnb, tid);
    __syncthreads();
    float sum = 0.f, cnt = 0.f;
    #pragma unroll
    for (int r = 0; r < K_; r++) {
        sum = fmaf(XN[r*H_ + tid], V01[r], sum);
        cnt += V01[r];
    }
    out[(size_t)s*H_ + tid] = sum / fmaxf(cnt, 1.f);
}

// ---------------------------------------------------------------------------
extern "C" void kernel_launch(void* const* d_in, const int* in_sizes, int n_in,
                              void* d_out, int out_size)
{
    // inputs: 0 h, 1 valid, 2 edge_index, 3 ea_flat, 4 edge_ptr, 5 S, 6 k,
    // 7 edge_W, 8 edge_b, 9 ln1_g, 10 ln1_b, 11 qkv_W, 12 qkv_b, 13 out_W,
    // 14 out_b, 15 ln2_g, 16 ln2_b, 17 ff1_W, 18 ff1_b, 19 ff2_W, 20 ff2_b,
    // 21 fnorm_g, 22 fnorm_b
    cudaFuncSetAttribute(xf_kernel, cudaFuncAttributeMaxDynamicSharedMemorySize,
                         SMEM_FLOATS * (int)sizeof(float));

    edge_bias_kernel<<<S_, 256>>>(
        (const float*)d_in[3], (const int*)d_in[2],
        (const float*)d_in[7], (const float*)d_in[8]);

    xf_kernel<<<S_, 256, SMEM_FLOATS * sizeof(float)>>>(
        (const float*)d_in[0], d_in[1],
        (const float*)d_in[9],  (const float*)d_in[10],
        (const float*)d_in[11], (const float*)d_in[12],
        (const float*)d_in[13], (const float*)d_in[14],
        (const float*)d_in[15], (const float*)d_in[16],
        (const float*)d_in[17], (const float*)d_in[18],
        (const float*)d_in[19], (const float*)d_in[20],
        (const float*)d_in[21], (const float*)d_in[22],
        (float*)d_out);
}

// round 5
// speedup vs baseline: 1.0027x; 1.0027x over previous
#include <cuda_runtime.h>
#include <cuda_bf16.h>
#include <math.h>

// Problem constants (LocalSubgraphTransformer)
#define S_   2048
#define K_   32
#define H_   256
#define NH_  8
#define DH_  32
#define L_   4
#define ED_  16
#define FFN_ 512
#define EPS_ 64
#define E_   (S_*EPS_)
#define BUFLD 768

// 32 MB scratch: edge bias [S][h][k=dst][q=src] in bf16
__device__ __nv_bfloat16 g_bias16[(size_t)S_ * NH_ * K_ * K_];

// ---------------------------------------------------------------------------
// Kernel A: per-subgraph edge bias via shared-memory scatter-add
// ---------------------------------------------------------------------------
__global__ __launch_bounds__(256) void edge_bias_kernel(
    const float* __restrict__ ea, const int* __restrict__ eidx,
    const float* __restrict__ eW, const float* __restrict__ eb)
{
    __shared__ float sb[NH_*K_*K_];   // [h][dst][src]
    __shared__ float sa[EPS_*ED_];
    __shared__ float sw[NH_*ED_];
    __shared__ float sbv[NH_];
    const int s = blockIdx.x, tid = threadIdx.x;

    if (tid < NH_*ED_) sw[tid] = eW[tid];
    if (tid < NH_)     sbv[tid] = eb[tid];
    for (int i = tid; i < EPS_*ED_;  i += 256) sa[i] = ea[(size_t)s*EPS_*ED_ + i];
    for (int i = tid; i < NH_*K_*K_; i += 256) sb[i] = 0.f;
    __syncthreads();

    #pragma unroll
    for (int t = tid; t < EPS_*NH_; t += 256) {
        const int i  = t >> 3;    // edge within subgraph
        const int hh = t & 7;     // head
        float p = sbv[hh];
        #pragma unroll
        for (int d = 0; d < ED_; d++) p = fmaf(sa[i*ED_+d], sw[hh*ED_+d], p);
        const int e  = s*EPS_ + i;
        const int sr = eidx[e];        // src = query index
        const int ds = eidx[E_ + e];   // dst = key index
        atomicAdd(&sb[hh*K_*K_ + ds*K_ + sr], p);
    }
    __syncthreads();
    for (int i = tid; i < NH_*K_*K_; i += 256)
        g_bias16[(size_t)s*NH_*K_*K_ + i] = __float2bfloat16(sb[i]);
}

// ---------------------------------------------------------------------------
// Kernel B: fused 4-layer transformer, one CTA per subgraph
// ---------------------------------------------------------------------------
// smem layout (float offsets)
#define OFF_X    0       /* 8192 */
#define OFF_XN   8192    /* 8192 */
#define OFF_BUF  16384   /* 24576: qkv [32][768] or ffn hidden [32][512] */
#define OFF_WT   40960   /* 8192: double-buffered W tile 2 x [128][32] swizzled */
#define OFF_BS16 49152   /* bf16[8192] = 4096 floats: bias [h][k][q] */
#define OFF_KM   53248   /* 32 */
#define OFF_V01  53280   /* 32 */
#define SMEM_FLOATS 53312

__device__ __forceinline__ void ffma2(unsigned long long& c,
                                      unsigned long long a, unsigned long long b) {
    asm("fma.rn.f32x2 %0, %1, %2, %0;" : "+l"(c) : "l"(a), "l"(b));
}

// C[32,N] = A[32,KA] @ W[N,KA]^T + bias ; MODE 0: store, 1: store+relu, 2: dst += C
// A: smem [32][KA]; W: global, staged through swizzled smem tiles via cp.async.
// Micro-tile: thread = 8 rows x 2 cols (cols lane-strided, 32 apart).
// Warp w: rows (w&3)*8..+7, cols (w>>2)*64 + lane + {0,32}.
template<int N, int KA, int MODE>
__device__ __forceinline__ void mm32(const float* A, const float* __restrict__ W,
                                     const float* __restrict__ bias, float* dst,
                                     float* WT, int tid)
{
    const int rg   = (tid >> 5) & 3;  // row group: rows rg*8..rg*8+7
    const int cgrp = tid >> 7;        // col group (0/1)
    const int lane = tid & 31;
    const unsigned wt_s = (unsigned)__cvta_generic_to_shared(WT);
    constexpr int T = KA/32;          // k-tiles per pass

    for (int pass = 0; pass < N/128; pass++) {
        const float* Wp = W + (size_t)pass*128*KA;
        // prefetch tile 0 -> buffer 0 (col-major-k rows of 32, XOR-swizzled 16B granules)
        #pragma unroll
        for (int it = 0; it < 4; it++) {
            const int v = it*256 + tid, cr = v >> 3, k4 = v & 7;
            const unsigned d = wt_s + (unsigned)((cr*32 + ((k4 ^ (cr&7))<<2))*4);
            const float* g = Wp + cr*KA + k4*4;
            asm volatile("cp.async.cg.shared.global [%0], [%1], 16;" :: "r"(d), "l"(g) : "memory");
        }
        asm volatile("cp.async.commit_group;" ::: "memory");

        unsigned long long acc[8][2];
        #pragma unroll
        for (int j = 0; j < 8; j++) { acc[j][0] = 0ull; acc[j][1] = 0ull; }

        const int c0 = cgrp*64 + lane;   // tile-local col of this thread (and c0+32)
        const int swz = c0 & 7;

        for (int kt = 0; kt < T; kt++) {
            asm volatile("cp.async.wait_group 0;" ::: "memory");
            __syncthreads();
            if (kt + 1 < T) {  // prefetch next tile into other buffer
                const float* Wn = Wp + (kt+1)*32;
                const unsigned bufn = ((kt+1) & 1) ? 4096u*4u : 0u;
                #pragma unroll
                for (int it = 0; it < 4; it++) {
                    const int v = it*256 + tid, cr = v >> 3, k4 = v & 7;
                    const unsigned d = wt_s + bufn +
                        (unsigned)((cr*32 + ((k4 ^ (cr&7))<<2))*4);
                    const float* g = Wn + cr*KA + k4*4;
                    asm volatile("cp.async.cg.shared.global [%0], [%1], 16;" :: "r"(d), "l"(g) : "memory");
                }
                asm volatile("cp.async.commit_group;" ::: "memory");
            }
            const float* WTc = WT + ((kt & 1) ? 4096 : 0);
            const float* Ac  = A + kt*32;
            #pragma unroll
            for (int t8 = 0; t8 < 8; t8++) {
                const int ko = (t8 ^ swz) << 2;
                const ulonglong2 w0 = *(const ulonglong2*)(WTc + c0*32 + ko);
                const ulonglong2 w1 = *(const ulonglong2*)(WTc + (c0+32)*32 + ko);
                #pragma unroll
                for (int j = 0; j < 8; j++) {
                    const ulonglong2 a = *(const ulonglong2*)(Ac + (rg*8+j)*KA + t8*4);
                    ffma2(acc[j][0], a.x, w0.x);
                    ffma2(acc[j][0], a.y, w0.y);
                    ffma2(acc[j][1], a.x, w1.x);
                    ffma2(acc[j][1], a.y, w1.y);
                }
            }
        }
        // epilogue: scalar stores, bank = lane (conflict-free)
        const int cg0 = pass*128 + cgrp*64 + lane;
        #pragma unroll
        for (int j = 0; j < 8; j++) {
            const int row = rg*8 + j;
            #pragma unroll
            for (int i = 0; i < 2; i++) {
                const int c = cg0 + 32*i;
                float lo, hi;
                asm("mov.b64 {%0,%1}, %2;" : "=f"(lo), "=f"(hi) : "l"(acc[j][i]));
                float v = lo + hi + bias[c];
                if (MODE == 1) v = fmaxf(v, 0.f);
                if (MODE == 2) v += dst[row*N + c];
                dst[row*N + c] = v;
            }
        }
    }
}

// LayerNorm over 32 rows of H_: warp w handles rows w*4..w*4+3
__device__ __forceinline__ void ln32(const float* src, float* dst,
                                     const float* __restrict__ g,
                                     const float* __restrict__ b, int tid)
{
    const int w = tid >> 5, lane = tid & 31;
    #pragma unroll
    for (int j = 0; j < 4; j++) {
        const int r = w*4 + j;
        float sum = 0.f, sq = 0.f;
        #pragma unroll
        for (int i = 0; i < 8; i++) {
            const float v = src[r*H_ + lane + i*32];
            sum += v; sq = fmaf(v, v, sq);
        }
        #pragma unroll
        for (int o = 16; o > 0; o >>= 1) {
            sum += __shfl_xor_sync(0xffffffffu, sum, o);
            sq  += __shfl_xor_sync(0xffffffffu, sq,  o);
        }
        const float mu   = sum * (1.f/H_);
        const float var  = sq * (1.f/H_) - mu*mu;
        const float rstd = rsqrtf(var + 1e-5f);
        #pragma unroll
        for (int i = 0; i < 8; i++) {
            const int c = lane + i*32;
            const float v = src[r*H_ + c];
            dst[r*H_ + c] = fmaf((v - mu)*rstd, g[c], b[c]);
        }
    }
}

// Attention: warp = head, lane = query row. qkv in BUF (ld 768), o -> XN (ld 256)
__device__ __forceinline__ void attn32(const float* BUF_, const __nv_bfloat16* BS,
                                       const float* KM, float* XN_, int tid)
{
    const int head = tid >> 5, lane = tid & 31;
    const float scale = 0.17677669529663687f;  // 1/sqrt(32)

    float4 q4[8];
    const float4* qp = (const float4*)(BUF_ + lane*BUFLD + head*32);
    #pragma unroll
    for (int j = 0; j < 8; j++) q4[j] = qp[j];

    float sc[32];
    float m = -3.0e38f;
    #pragma unroll
    for (int kr = 0; kr < 32; kr++) {
        const float4* kp = (const float4*)(BUF_ + kr*BUFLD + H_ + head*32);
        float s = 0.f;
        #pragma unroll
        for (int j = 0; j < 8; j++) {
            const float4 kk = kp[j];
            s = fmaf(q4[j].x, kk.x, s); s = fmaf(q4[j].y, kk.y, s);
            s = fmaf(q4[j].z, kk.z, s); s = fmaf(q4[j].w, kk.w, s);
        }
        const float bv = __bfloat162float(BS[head*1024 + kr*32 + lane]);
        s = fmaf(s, scale, bv) + KM[kr];
        sc[kr] = s;
        m = fmaxf(m, s);
    }
    float den = 0.f;
    #pragma unroll
    for (int kr = 0; kr < 32; kr++) { const float e = __expf(sc[kr] - m); sc[kr] = e; den += e; }
    const float inv = 1.f / den;
    #pragma unroll
    for (int kr = 0; kr < 32; kr++) sc[kr] *= inv;

    #pragma unroll
    for (int dg = 0; dg < 8; dg++) {
        float4 acc = make_float4(0.f, 0.f, 0.f, 0.f);
        #pragma unroll
        for (int kr = 0; kr < 32; kr++) {
            const float4 v4 = *(const float4*)(BUF_ + kr*BUFLD + 2*H_ + head*32 + dg*4);
            const float w = sc[kr];
            acc.x = fmaf(w, v4.x, acc.x); acc.y = fmaf(w, v4.y, acc.y);
            acc.z = fmaf(w, v4.z, acc.z); acc.w = fmaf(w, v4.w, acc.w);
        }
        *(float4*)(XN_ + lane*H_ + head*32 + dg*4) = acc;
    }
}

__global__ __launch_bounds__(256, 1) void xf_kernel(
    const float* __restrict__ h, const void* __restrict__ validp,
    const float* __restrict__ ln1g, const float* __restrict__ ln1b,
    const float* __restrict__ qkvW, const float* __restrict__ qkvb,
    const float* __restrict__ outW, const float* __restrict__ outb,
    const float* __restrict__ ln2g, const float* __restrict__ ln2b,
    const float* __restrict__ ff1W, const float* __restrict__ ff1b,
    const float* __restrict__ ff2W, const float* __restrict__ ff2b,
    const float* __restrict__ fng, const float* __restrict__ fnb,
    float* __restrict__ out)
{
    extern __shared__ float sm[];
    float* X   = sm + OFF_X;
    float* XN  = sm + OFF_XN;
    float* BUF = sm + OFF_BUF;
    float* WT  = sm + OFF_WT;
    __nv_bfloat16* BS16 = (__nv_bfloat16*)(sm + OFF_BS16);
    float* KM  = sm + OFF_KM;
    float* V01 = sm + OFF_V01;
    const int s = blockIdx.x, tid = threadIdx.x;

    // Detect 'valid' encoding: byte bools vs 32-bit words.
    const unsigned char* vb = (const unsigned char*)validp;
    bool bytemode = false;
    #pragma unroll
    for (int i = 1; i < 128; i += 4) bytemode |= (vb[i] != 0);

    if (tid < K_) {
        bool v;
        if (bytemode) v = vb[s*K_ + tid] != 0;
        else          v = ((const unsigned int*)validp)[s*K_ + tid] != 0u;
        KM[tid]  = v ? 0.f : -1e30f;
        V01[tid] = v ? 1.f : 0.f;
    }
    for (int i = tid; i < K_*H_/4; i += 256)
        ((float4*)X)[i] = ((const float4*)(h + (size_t)s*K_*H_))[i];
    // bias already [h][k][q] bf16: straight vector copy (1024 uint4)
    {
        const uint4* gb = (const uint4*)(g_bias16 + (size_t)s*NH_*K_*K_);
        uint4* sb = (uint4*)BS16;
        for (int i = tid; i < 1024; i += 256) sb[i] = gb[i];
    }
    __syncthreads();

    for (int l = 0; l < L_; l++) {
        ln32(X, XN, ln1g + l*H_, ln1b + l*H_, tid);
        __syncthreads();
        mm32<768, 256, 0>(XN, qkvW + (size_t)l*3*H_*H_, qkvb + l*3*H_, BUF, WT, tid);
        __syncthreads();
        attn32(BUF, BS16, KM, XN, tid);
        __syncthreads();
        mm32<256, 256, 2>(XN, outW + (size_t)l*H_*H_, outb + l*H_, X, WT, tid);
        __syncthreads();
        ln32(X, XN, ln2g + l*H_, ln2b + l*H_, tid);
        __syncthreads();
        mm32<512, 256, 1>(XN, ff1W + (size_t)l*FFN_*H_, ff1b + l*FFN_, BUF, WT, tid);
        __syncthreads();
        mm32<256, 512, 2>(BUF, ff2W + (size_t)l*H_*FFN_, ff2b + l*H_, X, WT, tid);
        __syncthreads();
    }

    // final LN + masked mean over k
    ln32(X, XN, fng, fnb, tid);
    __syncthreads();
    float sum = 0.f, cnt = 0.f;
    #pragma unroll
    for (int r = 0; r < K_; r++) {
        sum = fmaf(XN[r*H_ + tid], V01[r], sum);
        cnt += V01[r];
    }
    out[(size_t)s*H_ + tid] = sum / fmaxf(cnt, 1.f);
}

// ---------------------------------------------------------------------------
extern "C" void kernel_launch(void* const* d_in, const int* in_sizes, int n_in,
                              void* d_out, int out_size)
{
    // inputs: 0 h, 1 valid, 2 edge_index, 3 ea_flat, 4 edge_ptr, 5 S, 6 k,
    // 7 edge_W, 8 edge_b, 9 ln1_g, 10 ln1_b, 11 qkv_W, 12 qkv_b, 13 out_W,
    // 14 out_b, 15 ln2_g, 16 ln2_b, 17 ff1_W, 18 ff1_b, 19 ff2_W, 20 ff2_b,
    // 21 fnorm_g, 22 fnorm_b
    cudaFuncSetAttribute(xf_kernel, cudaFuncAttributeMaxDynamicSharedMemorySize,
                         SMEM_FLOATS * (int)sizeof(float));

    edge_bias_kernel<<<S_, 256>>>(
        (const float*)d_in[3], (const int*)d_in[2],
        (const float*)d_in[7], (const float*)d_in[8]);

    xf_kernel<<<S_, 256, SMEM_FLOATS * sizeof(float)>>>(
        (const float*)d_in[0], d_in[1],
        (const float*)d_in[9],  (const float*)d_in[10],
        (const float*)d_in[11], (const float*)d_in[12],
        (const float*)d_in[13], (const float*)d_in[14],
        (const float*)d_in[15], (const float*)d_in[16],
        (const float*)d_in[17], (const float*)d_in[18],
        (const float*)d_in[19], (const float*)d_in[20],
        (const float*)d_in[21], (const float*)d_in[22],
        (float*)d_out);
}

// round 6
// speedup vs baseline: 1.8819x; 1.8768x over previous
#include <cuda_runtime.h>
#include <cuda_bf16.h>
#include <math.h>

// Problem constants (LocalSubgraphTransformer)
#define S_   2048
#define K_   32
#define H_   256
#define NH_  8
#define DH_  32
#define L_   4
#define ED_  16
#define FFN_ 512
#define EPS_ 64
#define E_   (S_*EPS_)

#define LDA2 776    // XN'' row stride (bf16): 256*3 + 8 pad
#define LDB2 1544   // BUF'' row stride (bf16): 512*3 + 8 pad
#define LDQ  772    // BUF fp32 row stride (conflict-free lane*LDQ)

// ---------------- device scratch ----------------
__device__ __nv_bfloat16 g_bias16[(size_t)S_ * NH_ * K_ * K_];   // [S][h][k][q]
__device__ __nv_bfloat16 g_w2_qkv[(size_t)L_ * 768 * 768];
__device__ __nv_bfloat16 g_w2_out[(size_t)L_ * 256 * 768];
__device__ __nv_bfloat16 g_w2_ff1[(size_t)L_ * 512 * 768];
__device__ __nv_bfloat16 g_w2_ff2[(size_t)L_ * 256 * 1536];

// ---------------------------------------------------------------------------
// Weight conversion: fp32 [R][KA] -> bf16 triple [R][3KA] = [hi | lo | hi]
// ---------------------------------------------------------------------------
__global__ void wconv(const float* __restrict__ src, __nv_bfloat16* __restrict__ dst,
                      int KA, int total)
{
    const int e = blockIdx.x*256 + threadIdx.x;
    if (e >= total) return;
    const int r = e / KA, k = e - r*KA;
    const float w = src[e];
    const __nv_bfloat16 hi = __float2bfloat16(w);
    const __nv_bfloat16 lo = __float2bfloat16(w - __bfloat162float(hi));
    const size_t base = (size_t)r*3*KA;
    dst[base + k]        = hi;
    dst[base + KA + k]   = lo;
    dst[base + 2*KA + k] = hi;
}

// ---------------------------------------------------------------------------
// Kernel A: per-subgraph edge bias via shared-memory scatter-add
// ---------------------------------------------------------------------------
__global__ __launch_bounds__(256) void edge_bias_kernel(
    const float* __restrict__ ea, const int* __restrict__ eidx,
    const float* __restrict__ eW, const float* __restrict__ eb)
{
    __shared__ float sb[NH_*K_*K_];   // [h][dst=k][src=q]
    __shared__ float sa[EPS_*ED_];
    __shared__ float sw[NH_*ED_];
    __shared__ float sbv[NH_];
    const int s = blockIdx.x, tid = threadIdx.x;

    if (tid < NH_*ED_) sw[tid] = eW[tid];
    if (tid < NH_)     sbv[tid] = eb[tid];
    for (int i = tid; i < EPS_*ED_;  i += 256) sa[i] = ea[(size_t)s*EPS_*ED_ + i];
    for (int i = tid; i < NH_*K_*K_; i += 256) sb[i] = 0.f;
    __syncthreads();

    for (int t = tid; t < EPS_*NH_; t += 256) {
        const int i  = t >> 3;
        const int hh = t & 7;
        float p = sbv[hh];
        #pragma unroll
        for (int d = 0; d < ED_; d++) p = fmaf(sa[i*ED_+d], sw[hh*ED_+d], p);
        const int e  = s*EPS_ + i;
        const int sr = eidx[e];        // src = query index
        const int ds = eidx[E_ + e];   // dst = key index
        atomicAdd(&sb[hh*K_*K_ + ds*K_ + sr], p);
    }
    __syncthreads();
    for (int i = tid; i < NH_*K_*K_; i += 256)
        g_bias16[(size_t)s*NH_*K_*K_ + i] = __float2bfloat16(sb[i]);
}

// ---------------------------------------------------------------------------
// smem layout (float offsets)
// ---------------------------------------------------------------------------
#define OFF_X    0        /* 8192 f: X fp32 [32][256] */
#define OFF_BUF  8192     /* 24704 f: union { fp32 [32][772] qkv ; bf16 [32][1544] ffn'' } */
#define OFF_XN2  32896    /* 12416 f: bf16 [32][776] */
#define OFF_WT   45312    /* 8192 f: 2 x (128x64 bf16, XOR-swizzled) */
#define OFF_BS   53504    /* 4096 f: bf16 [8][32][32] */
#define OFF_KM   57600
#define OFF_V01  57632
#define SMEM_FLOATS 57664  /* 230656 bytes */

__device__ __forceinline__ unsigned sptr(const void* p) {
    return (unsigned)__cvta_generic_to_shared(p);
}
__device__ __forceinline__ void ldm_x4(unsigned& a0, unsigned& a1, unsigned& a2,
                                       unsigned& a3, unsigned addr) {
    asm volatile("ldmatrix.sync.aligned.m8n8.x4.shared.b16 {%0,%1,%2,%3},[%4];"
                 : "=r"(a0), "=r"(a1), "=r"(a2), "=r"(a3) : "r"(addr));
}
__device__ __forceinline__ void ldm_x2(unsigned& b0, unsigned& b1, unsigned addr) {
    asm volatile("ldmatrix.sync.aligned.m8n8.x2.shared.b16 {%0,%1},[%2];"
                 : "=r"(b0), "=r"(b1) : "r"(addr));
}
__device__ __forceinline__ void mma16816(float* c, unsigned a0, unsigned a1,
                                         unsigned a2, unsigned a3,
                                         unsigned b0, unsigned b1) {
    asm volatile("mma.sync.aligned.m16n8k16.row.col.f32.bf16.bf16.f32 "
                 "{%0,%1,%2,%3},{%4,%5,%6,%7},{%8,%9},{%0,%1,%2,%3};"
                 : "+f"(c[0]), "+f"(c[1]), "+f"(c[2]), "+f"(c[3])
                 : "r"(a0), "r"(a1), "r"(a2), "r"(a3), "r"(b0), "r"(b1));
}
__device__ __forceinline__ void hilo(float v, __nv_bfloat16& hi, __nv_bfloat16& lo) {
    hi = __float2bfloat16(v);
    lo = __float2bfloat16(v - __bfloat162float(hi));
}

// ---------------------------------------------------------------------------
// Tensor-core GEMM: C[32,N] = A''[32,3KA] (bf16 triple) @ W''[N,3KA]^T + bias
// MODE 0: fp32 -> BUFf (ld LDQ); 1: relu -> tripled bf16 BUF2; 2: += X (ld H_)
// ---------------------------------------------------------------------------
template<int N, int KA, int MODE>
__device__ __forceinline__ void mma_mm(const __nv_bfloat16* A, int lda,
    const __nv_bfloat16* __restrict__ Wg, const float* __restrict__ bias,
    float* Xd, float* BUFf, __nv_bfloat16* BUF2, __nv_bfloat16* WT, int tid)
{
    const int lane = tid & 31, wid = tid >> 5;
    const int mi = wid & 1, ng = wid >> 1;       // m-tile (0/1), n-group (0..3)
    constexpr int K3 = 3*KA;
    constexpr int T  = K3/64;                    // 64-k' tiles
    const unsigned wt_s = sptr(WT);
    // A ldmatrix lane address (bytes)
    const int arow = mi*16 + (lane & 15);
    const unsigned a_s = sptr(A) + (unsigned)(arow*lda*2) + (unsigned)(((lane>>4)&1)*16);
    const int brow0 = ng*32 + (lane & 7);        // B row within pass tile (+t*8)
    const int bhalf = (lane >> 3) & 1;           // 16B granule parity within k16

    for (int pass = 0; pass < N/128; pass++) {
        const __nv_bfloat16* Wp = Wg + (size_t)pass*128*K3;
        // prefetch kt=0 -> buffer 0
        #pragma unroll
        for (int it = 0; it < 4; it++) {
            const int v = it*256 + tid, n = v >> 3, g = v & 7;
            const unsigned d = wt_s + (unsigned)((n*64 + ((g ^ (n&7))<<3))*2);
            const __nv_bfloat16* src = Wp + n*K3 + g*8;
            asm volatile("cp.async.cg.shared.global [%0], [%1], 16;" :: "r"(d), "l"(src) : "memory");
        }
        asm volatile("cp.async.commit_group;" ::: "memory");

        float acc[4][4];
        #pragma unroll
        for (int t = 0; t < 4; t++)
            #pragma unroll
            for (int i = 0; i < 4; i++) acc[t][i] = 0.f;

        for (int kt = 0; kt < T; kt++) {
            asm volatile("cp.async.wait_group 0;" ::: "memory");
            __syncthreads();
            if (kt + 1 < T) {
                const __nv_bfloat16* Wn = Wp + (kt+1)*64;
                const unsigned bufn = ((kt+1) & 1) ? 16384u : 0u;
                #pragma unroll
                for (int it = 0; it < 4; it++) {
                    const int v = it*256 + tid, n = v >> 3, g = v & 7;
                    const unsigned d = wt_s + bufn + (unsigned)((n*64 + ((g ^ (n&7))<<3))*2);
                    const __nv_bfloat16* src = Wn + n*K3 + g*8;
                    asm volatile("cp.async.cg.shared.global [%0], [%1], 16;" :: "r"(d), "l"(src) : "memory");
                }
                asm volatile("cp.async.commit_group;" ::: "memory");
            }
            const unsigned wb = wt_s + ((kt & 1) ? 16384u : 0u);
            #pragma unroll
            for (int ks = 0; ks < 4; ks++) {
                unsigned a0, a1, a2, a3;
                ldm_x4(a0, a1, a2, a3, a_s + (unsigned)((kt*64 + ks*16)*2));
                #pragma unroll
                for (int t = 0; t < 4; t++) {
                    const int n = brow0 + t*8;
                    const int g = 2*ks + bhalf;
                    unsigned b0, b1;
                    ldm_x2(b0, b1, wb + (unsigned)((n*64 + ((g ^ (n&7))<<3))*2));
                    mma16816(acc[t], a0, a1, a2, a3, b0, b1);
                }
            }
        }
        // epilogue: thread owns rows r0, r0+8; cols c, c+1 per tile
        const int r0 = mi*16 + (lane >> 2);
        #pragma unroll
        for (int t = 0; t < 4; t++) {
            const int c = pass*128 + ng*32 + t*8 + 2*(lane & 3);
            const float b0 = bias[c], b1 = bias[c+1];
            #pragma unroll
            for (int rr = 0; rr < 2; rr++) {
                const int r = r0 + rr*8;
                float v0 = acc[t][rr*2+0] + b0;
                float v1 = acc[t][rr*2+1] + b1;
                if (MODE == 0) {
                    BUFf[r*LDQ + c]   = v0;
                    BUFf[r*LDQ + c+1] = v1;
                } else if (MODE == 2) {
                    Xd[r*H_ + c]   += v0;
                    Xd[r*H_ + c+1] += v1;
                } else {
                    v0 = fmaxf(v0, 0.f); v1 = fmaxf(v1, 0.f);
                    __nv_bfloat16 h0, l0, h1, l1;
                    hilo(v0, h0, l0); hilo(v1, h1, l1);
                    __nv_bfloat16* d = BUF2 + r*LDB2;
                    d[c] = h0;        d[c+1] = h1;
                    d[512 + c] = h0;  d[512 + c+1] = h1;
                    d[1024 + c] = l0; d[1024 + c+1] = l1;
                }
            }
        }
    }
}

// ---------------------------------------------------------------------------
// LayerNorm over 32 rows. OM 0: fp32 dst (ld H_); OM 1: tripled bf16 (ld LDA2)
// ---------------------------------------------------------------------------
template<int OM>
__device__ __forceinline__ void ln32(const float* src, void* dstv,
                                     const float* __restrict__ g,
                                     const float* __restrict__ b, int tid)
{
    const int w = tid >> 5, lane = tid & 31;
    #pragma unroll
    for (int j = 0; j < 4; j++) {
        const int r = w*4 + j;
        float sum = 0.f, sq = 0.f;
        #pragma unroll
        for (int i = 0; i < 8; i++) {
            const float v = src[r*H_ + lane + i*32];
            sum += v; sq = fmaf(v, v, sq);
        }
        #pragma unroll
        for (int o = 16; o > 0; o >>= 1) {
            sum += __shfl_xor_sync(0xffffffffu, sum, o);
            sq  += __shfl_xor_sync(0xffffffffu, sq,  o);
        }
        const float mu   = sum * (1.f/H_);
        const float var  = sq * (1.f/H_) - mu*mu;
        const float rstd = rsqrtf(var + 1e-5f);
        #pragma unroll
        for (int i = 0; i < 8; i++) {
            const int c = lane + i*32;
            const float y = fmaf((src[r*H_ + c] - mu)*rstd, g[c], b[c]);
            if (OM == 0) {
                ((float*)dstv)[r*H_ + c] = y;
            } else {
                __nv_bfloat16 hi, lo; hilo(y, hi, lo);
                __nv_bfloat16* d = (__nv_bfloat16*)dstv + r*LDA2;
                d[c] = hi; d[256 + c] = hi; d[512 + c] = lo;
            }
        }
    }
}

// ---------------------------------------------------------------------------
// Attention: warp = head, lane = query row. qkv fp32 in BUFf (ld LDQ);
// output written as tripled bf16 into XN2.
// ---------------------------------------------------------------------------
__device__ __forceinline__ void attn32(const float* BUFf, const __nv_bfloat16* BS,
                                       const float* KM, __nv_bfloat16* XN2, int tid)
{
    const int head = tid >> 5, lane = tid & 31;
    const float scale = 0.17677669529663687f;  // 1/sqrt(32)

    float4 q4[8];
    const float4* qp = (const float4*)(BUFf + lane*LDQ + head*32);
    #pragma unroll
    for (int j = 0; j < 8; j++) q4[j] = qp[j];

    float sc[32];
    float m = -3.0e38f;
    #pragma unroll
    for (int kr = 0; kr < 32; kr++) {
        const float4* kp = (const float4*)(BUFf + kr*LDQ + 256 + head*32);
        float s = 0.f;
        #pragma unroll
        for (int j = 0; j < 8; j++) {
            const float4 kk = kp[j];
            s = fmaf(q4[j].x, kk.x, s); s = fmaf(q4[j].y, kk.y, s);
            s = fmaf(q4[j].z, kk.z, s); s = fmaf(q4[j].w, kk.w, s);
        }
        const float bv = __bfloat162float(BS[head*1024 + kr*32 + lane]);
        s = fmaf(s, scale, bv) + KM[kr];
        sc[kr] = s;
        m = fmaxf(m, s);
    }
    float den = 0.f;
    #pragma unroll
    for (int kr = 0; kr < 32; kr++) { const float e = __expf(sc[kr] - m); sc[kr] = e; den += e; }
    const float inv = 1.f / den;
    #pragma unroll
    for (int kr = 0; kr < 32; kr++) sc[kr] *= inv;

    #pragma unroll
    for (int dg = 0; dg < 8; dg++) {
        float4 acc = make_float4(0.f, 0.f, 0.f, 0.f);
        #pragma unroll
        for (int kr = 0; kr < 32; kr++) {
            const float4 v4 = *(const float4*)(BUFf + kr*LDQ + 512 + head*32 + dg*4);
            const float w = sc[kr];
            acc.x = fmaf(w, v4.x, acc.x); acc.y = fmaf(w, v4.y, acc.y);
            acc.z = fmaf(w, v4.z, acc.z); acc.w = fmaf(w, v4.w, acc.w);
        }
        const float av[4] = {acc.x, acc.y, acc.z, acc.w};
        __nv_bfloat16* d = XN2 + lane*LDA2;
        #pragma unroll
        for (int e = 0; e < 4; e++) {
            const int c = head*32 + dg*4 + e;
            __nv_bfloat16 hi, lo; hilo(av[e], hi, lo);
            d[c] = hi; d[256 + c] = hi; d[512 + c] = lo;
        }
    }
}

// ---------------------------------------------------------------------------
__global__ __launch_bounds__(256, 1) void xf_kernel(
    const float* __restrict__ h, const void* __restrict__ validp,
    const float* __restrict__ ln1g, const float* __restrict__ ln1b,
    const float* __restrict__ qkvb, const float* __restrict__ outb,
    const float* __restrict__ ln2g, const float* __restrict__ ln2b,
    const float* __restrict__ ff1b, const float* __restrict__ ff2b,
    const float* __restrict__ fng, const float* __restrict__ fnb,
    float* __restrict__ out)
{
    extern __shared__ float sm[];
    float* X    = sm + OFF_X;
    float* BUFf = sm + OFF_BUF;
    __nv_bfloat16* BUF2 = (__nv_bfloat16*)(sm + OFF_BUF);
    __nv_bfloat16* XN2  = (__nv_bfloat16*)(sm + OFF_XN2);
    __nv_bfloat16* WT   = (__nv_bfloat16*)(sm + OFF_WT);
    __nv_bfloat16* BS   = (__nv_bfloat16*)(sm + OFF_BS);
    float* KM  = sm + OFF_KM;
    float* V01 = sm + OFF_V01;
    const int s = blockIdx.x, tid = threadIdx.x;

    // Detect 'valid' encoding: byte bools vs 32-bit words.
    const unsigned char* vb = (const unsigned char*)validp;
    bool bytemode = false;
    #pragma unroll
    for (int i = 1; i < 128; i += 4) bytemode |= (vb[i] != 0);

    if (tid < K_) {
        bool v;
        if (bytemode) v = vb[s*K_ + tid] != 0;
        else          v = ((const unsigned int*)validp)[s*K_ + tid] != 0u;
        KM[tid]  = v ? 0.f : -1e30f;
        V01[tid] = v ? 1.f : 0.f;
    }
    for (int i = tid; i < K_*H_/4; i += 256)
        ((float4*)X)[i] = ((const float4*)(h + (size_t)s*K_*H_))[i];
    {
        const uint4* gb = (const uint4*)(g_bias16 + (size_t)s*NH_*K_*K_);
        uint4* sb = (uint4*)BS;
        for (int i = tid; i < 1024; i += 256) sb[i] = gb[i];
    }
    __syncthreads();

    for (int l = 0; l < L_; l++) {
        ln32<1>(X, XN2, ln1g + l*H_, ln1b + l*H_, tid);
        __syncthreads();
        mma_mm<768, 256, 0>(XN2, LDA2, g_w2_qkv + (size_t)l*768*768,
                            qkvb + l*768, X, BUFf, BUF2, WT, tid);
        __syncthreads();
        attn32(BUFf, BS, KM, XN2, tid);
        __syncthreads();
        mma_mm<256, 256, 2>(XN2, LDA2, g_w2_out + (size_t)l*256*768,
                            outb + l*H_, X, BUFf, BUF2, WT, tid);
        __syncthreads();
        ln32<1>(X, XN2, ln2g + l*H_, ln2b + l*H_, tid);
        __syncthreads();
        mma_mm<512, 256, 1>(XN2, LDA2, g_w2_ff1 + (size_t)l*512*768,
                            ff1b + l*FFN_, X, BUFf, BUF2, WT, tid);
        __syncthreads();
        mma_mm<256, 512, 2>(BUF2, LDB2, g_w2_ff2 + (size_t)l*256*1536,
                            ff2b + l*H_, X, BUFf, BUF2, WT, tid);
        __syncthreads();
    }

    // final LN (fp32 into BUFf region, ld H_) + masked mean over k
    ln32<0>(X, BUFf, fng, fnb, tid);
    __syncthreads();
    float sum = 0.f, cnt = 0.f;
    #pragma unroll
    for (int r = 0; r < K_; r++) {
        sum = fmaf(BUFf[r*H_ + tid], V01[r], sum);
        cnt += V01[r];
    }
    out[(size_t)s*H_ + tid] = sum / fmaxf(cnt, 1.f);
}

// ---------------------------------------------------------------------------
extern "C" void kernel_launch(void* const* d_in, const int* in_sizes, int n_in,
                              void* d_out, int out_size)
{
    // inputs: 0 h, 1 valid, 2 edge_index, 3 ea_flat, 4 edge_ptr, 5 S, 6 k,
    // 7 edge_W, 8 edge_b, 9 ln1_g, 10 ln1_b, 11 qkv_W, 12 qkv_b, 13 out_W,
    // 14 out_b, 15 ln2_g, 16 ln2_b, 17 ff1_W, 18 ff1_b, 19 ff2_W, 20 ff2_b,
    // 21 fnorm_g, 22 fnorm_b
    cudaFuncSetAttribute(xf_kernel, cudaFuncAttributeMaxDynamicSharedMemorySize,
                         SMEM_FLOATS * (int)sizeof(float));

    __nv_bfloat16 *w2_qkv, *w2_out, *w2_ff1, *w2_ff2;
    cudaGetSymbolAddress((void**)&w2_qkv, g_w2_qkv);
    cudaGetSymbolAddress((void**)&w2_out, g_w2_out);
    cudaGetSymbolAddress((void**)&w2_ff1, g_w2_ff1);
    cudaGetSymbolAddress((void**)&w2_ff2, g_w2_ff2);

    wconv<<<(L_*768*256 + 255)/256, 256>>>((const float*)d_in[11], w2_qkv, 256, L_*768*256);
    wconv<<<(L_*256*256 + 255)/256, 256>>>((const float*)d_in[13], w2_out, 256, L_*256*256);
    wconv<<<(L_*512*256 + 255)/256, 256>>>((const float*)d_in[17], w2_ff1, 256, L_*512*256);
    wconv<<<(L_*256*512 + 255)/256, 256>>>((const float*)d_in[19], w2_ff2, 512, L_*256*512);

    edge_bias_kernel<<<S_, 256>>>(
        (const float*)d_in[3], (const int*)d_in[2],
        (const float*)d_in[7], (const float*)d_in[8]);

    xf_kernel<<<S_, 256, SMEM_FLOATS * sizeof(float)>>>(
        (const float*)d_in[0], d_in[1],
        (const float*)d_in[9],  (const float*)d_in[10],
        (const float*)d_in[12], (const float*)d_in[14],
        (const float*)d_in[15], (const float*)d_in[16],
        (const float*)d_in[18], (const float*)d_in[20],
        (const float*)d_in[21], (const float*)d_in[22],
        (float*)d_out);
}

// round 8
// speedup vs baseline: 2.3378x; 1.2422x over previous
#include <cuda_runtime.h>
#include <cuda_bf16.h>
#include <math.h>

// Problem constants (LocalSubgraphTransformer)
#define S_   2048
#define K_   32
#define H_   256
#define NH_  8
#define DH_  32
#define L_   4
#define ED_  16
#define FFN_ 512
#define EPS_ 64
#define E_   (S_*EPS_)

#define LDA2 520    // XN2 row stride (bf16): hi 256 | lo 256 | pad 8  (260w mod 32 = 4)
#define LDB2 1032   // BUF2 row stride (bf16): hi 512 | lo 512 | pad 8 (516w mod 32 = 4)
#define LDQ  772    // qkv fp32 row stride

// ---------------- device scratch ----------------
__device__ __nv_bfloat16 g_bias16[(size_t)S_ * NH_ * K_ * K_];   // [S][h][k][q]
__device__ __nv_bfloat16 g_w2_qkv[(size_t)L_ * 768 * 512];
__device__ __nv_bfloat16 g_w2_out[(size_t)L_ * 256 * 512];
__device__ __nv_bfloat16 g_w2_ff1[(size_t)L_ * 512 * 512];
__device__ __nv_bfloat16 g_w2_ff2[(size_t)L_ * 256 * 1024];

// ---------------------------------------------------------------------------
// Weight conversion: fp32 [R][KA] -> bf16 split [R][2KA] = [hi | lo]
// ---------------------------------------------------------------------------
__global__ void wconv(const float* __restrict__ src, __nv_bfloat16* __restrict__ dst,
                      int KA, int total)
{
    const int e = blockIdx.x*256 + threadIdx.x;
    if (e >= total) return;
    const int r = e / KA, k = e - r*KA;
    const float w = src[e];
    const __nv_bfloat16 hi = __float2bfloat16(w);
    const __nv_bfloat16 lo = __float2bfloat16(w - __bfloat162float(hi));
    const size_t base = (size_t)r*2*KA;
    dst[base + k]      = hi;
    dst[base + KA + k] = lo;
}

// ---------------------------------------------------------------------------
// Kernel A: per-subgraph edge bias via shared-memory scatter-add
// ---------------------------------------------------------------------------
__global__ __launch_bounds__(256) void edge_bias_kernel(
    const float* __restrict__ ea, const int* __restrict__ eidx,
    const float* __restrict__ eW, const float* __restrict__ eb)
{
    __shared__ float sb[NH_*K_*K_];   // [h][dst=k][src=q]
    __shared__ float sa[EPS_*ED_];
    __shared__ float sw[NH_*ED_];
    __shared__ float sbv[NH_];
    const int s = blockIdx.x, tid = threadIdx.x;

    if (tid < NH_*ED_) sw[tid] = eW[tid];
    if (tid < NH_)     sbv[tid] = eb[tid];
    for (int i = tid; i < EPS_*ED_;  i += 256) sa[i] = ea[(size_t)s*EPS_*ED_ + i];
    for (int i = tid; i < NH_*K_*K_; i += 256) sb[i] = 0.f;
    __syncthreads();

    for (int t = tid; t < EPS_*NH_; t += 256) {
        const int i  = t >> 3;
        const int hh = t & 7;
        float p = sbv[hh];
        #pragma unroll
        for (int d = 0; d < ED_; d++) p = fmaf(sa[i*ED_+d], sw[hh*ED_+d], p);
        const int e  = s*EPS_ + i;
        const int sr = eidx[e];        // src = query index
        const int ds = eidx[E_ + e];   // dst = key index
        atomicAdd(&sb[hh*K_*K_ + ds*K_ + sr], p);
    }
    __syncthreads();
    for (int i = tid; i < NH_*K_*K_; i += 256)
        g_bias16[(size_t)s*NH_*K_*K_ + i] = __float2bfloat16(sb[i]);
}

// ---------------------------------------------------------------------------
// smem layout (float offsets)
// ---------------------------------------------------------------------------
#define OFF_X    0        /* 8192 f: X fp32 [32][256] */
#define OFF_BUF  8192     /* 24704 f: union { fp32 [32][772] qkv ; bf16 [32][1032] ffn2 } */
#define OFF_XN2  32896    /* 8320 f: bf16 [32][520] */
#define OFF_WT   41216    /* 8192 f: 2 x (128 x 64 bf16, XOR-swizzled) */
#define OFF_BS   49408    /* 4096 f: bf16 [8][32][32] */
#define OFF_KM   53504
#define OFF_V01  53536
#define SMEM_FLOATS 53568  /* 214272 bytes */

__device__ __forceinline__ unsigned sptr(const void* p) {
    return (unsigned)__cvta_generic_to_shared(p);
}
__device__ __forceinline__ void ldm_x4(unsigned& a0, unsigned& a1, unsigned& a2,
                                       unsigned& a3, unsigned addr) {
    asm volatile("ldmatrix.sync.aligned.m8n8.x4.shared.b16 {%0,%1,%2,%3},[%4];"
                 : "=r"(a0), "=r"(a1), "=r"(a2), "=r"(a3) : "r"(addr));
}
__device__ __forceinline__ void mma16816(float* c, const unsigned* a,
                                         unsigned b0, unsigned b1) {
    asm volatile("mma.sync.aligned.m16n8k16.row.col.f32.bf16.bf16.f32 "
                 "{%0,%1,%2,%3},{%4,%5,%6,%7},{%8,%9},{%0,%1,%2,%3};"
                 : "+f"(c[0]), "+f"(c[1]), "+f"(c[2]), "+f"(c[3])
                 : "r"(a[0]), "r"(a[1]), "r"(a[2]), "r"(a[3]), "r"(b0), "r"(b1));
}
__device__ __forceinline__ void hilo(float v, __nv_bfloat16& hi, __nv_bfloat16& lo) {
    hi = __float2bfloat16(v);
    lo = __float2bfloat16(v - __bfloat162float(hi));
}

// ---------------------------------------------------------------------------
// Tensor-core GEMM with explicit hi/lo split:
// C = A_hi W_hi^T + A_hi W_lo^T + A_lo W_hi^T + bias
// A: smem bf16 [32][hi KA | lo KA] (ld lda); W: global bf16 [N][hi KA | lo KA].
// Warp tile m32 x n16; 8 warps cover n128 per pass.
// MODE 0: fp32 -> BUFf (ld LDQ); 1: relu -> hi/lo BUF2; 2: += X (ld H_)
// ---------------------------------------------------------------------------
template<int N, int KA, int MODE>
__device__ __forceinline__ void mm3(const __nv_bfloat16* A, int lda,
    const __nv_bfloat16* __restrict__ Wg, const float* __restrict__ bias,
    float* Xd, float* BUFf, __nv_bfloat16* BUF2, __nv_bfloat16* WT, int tid)
{
    const int lane = tid & 31, wid = tid >> 5;
    constexpr int K2 = 2*KA;
    constexpr int T  = KA/32;                    // k32 stages
    const unsigned wt_s = sptr(WT);
    // A ldmatrix base: row = lane&15, 16B col = (lane>>4)
    const unsigned a_s = sptr(A) + (unsigned)(((lane & 15)*lda + ((lane >> 4) << 3))*2);
    // B ldmatrix: rows wid*16 + (lane&7) + ((lane>>4)<<3), granule parity (lane>>3)&1
    const int brow = wid*16 + (lane & 7) + (((lane >> 4) & 1) << 3);
    const int bg   = (lane >> 3) & 1;

    for (int pass = 0; pass < N/128; pass++) {
        const __nv_bfloat16* Wp = Wg + (size_t)pass*128*K2;
        // prefetch stage 0 -> buffer 0 (rows of 64 bf16 = [hi k32 | lo k32], swizzled)
        #pragma unroll
        for (int it = 0; it < 4; it++) {
            const int v = it*256 + tid, n = v >> 3, g = v & 7;
            const unsigned d = wt_s + (unsigned)((n*64 + ((g ^ (n&7))<<3))*2);
            const __nv_bfloat16* src = Wp + n*K2 + (g < 4 ? g*8 : KA + (g-4)*8);
            asm volatile("cp.async.cg.shared.global [%0], [%1], 16;" :: "r"(d), "l"(src) : "memory");
        }
        asm volatile("cp.async.commit_group;" ::: "memory");

        float acc[2][2][4];   // [m-tile][n8-tile][4]
        #pragma unroll
        for (int mi = 0; mi < 2; mi++)
            #pragma unroll
            for (int j = 0; j < 2; j++)
                #pragma unroll
                for (int i = 0; i < 4; i++) acc[mi][j][i] = 0.f;

        for (int kt = 0; kt < T; kt++) {
            asm volatile("cp.async.wait_group 0;" ::: "memory");
            __syncthreads();
            if (kt + 1 < T) {
                const unsigned bufn = ((kt+1) & 1) ? 16384u : 0u;
                #pragma unroll
                for (int it = 0; it < 4; it++) {
                    const int v = it*256 + tid, n = v >> 3, g = v & 7;
                    const unsigned d = wt_s + bufn + (unsigned)((n*64 + ((g ^ (n&7))<<3))*2);
                    const __nv_bfloat16* src = Wp + n*K2 + (kt+1)*32 +
                        (g < 4 ? g*8 : KA + (g-4)*8);
                    asm volatile("cp.async.cg.shared.global [%0], [%1], 16;" :: "r"(d), "l"(src) : "memory");
                }
                asm volatile("cp.async.commit_group;" ::: "memory");
            }
            const unsigned wb = wt_s + ((kt & 1) ? 16384u : 0u);

            // A fragments: [mi][ks] hi and lo (8 x ldmatrix.x4)
            unsigned ah[2][2][4], al[2][2][4];
            #pragma unroll
            for (int mi = 0; mi < 2; mi++)
                #pragma unroll
                for (int ks = 0; ks < 2; ks++) {
                    const unsigned base = a_s + (unsigned)((mi*16*lda + kt*32 + ks*16)*2);
                    ldm_x4(ah[mi][ks][0], ah[mi][ks][1], ah[mi][ks][2], ah[mi][ks][3], base);
                    ldm_x4(al[mi][ks][0], al[mi][ks][1], al[mi][ks][2], al[mi][ks][3],
                           base + (unsigned)(KA*2));
                }
            // B fragments: hi/lo per ks (4 x ldmatrix.x4), each n16 x k16
            unsigned bh[2][4], bl[2][4];
            #pragma unroll
            for (int ks = 0; ks < 2; ks++) {
                const int gh = 2*ks + bg;
                const int gl = 4 + 2*ks + bg;
                ldm_x4(bh[ks][0], bh[ks][1], bh[ks][2], bh[ks][3],
                       wb + (unsigned)((brow*64 + ((gh ^ (brow&7))<<3))*2));
                ldm_x4(bl[ks][0], bl[ks][1], bl[ks][2], bl[ks][3],
                       wb + (unsigned)((brow*64 + ((gl ^ (brow&7))<<3))*2));
            }
            // 3 pairings x 2 mi x 2 ks x 2 n8-tiles = 24 mma
            #pragma unroll
            for (int mi = 0; mi < 2; mi++)
                #pragma unroll
                for (int ks = 0; ks < 2; ks++) {
                    mma16816(acc[mi][0], ah[mi][ks], bh[ks][0], bh[ks][1]);
                    mma16816(acc[mi][1], ah[mi][ks], bh[ks][2], bh[ks][3]);
                    mma16816(acc[mi][0], ah[mi][ks], bl[ks][0], bl[ks][1]);
                    mma16816(acc[mi][1], ah[mi][ks], bl[ks][2], bl[ks][3]);
                    mma16816(acc[mi][0], al[mi][ks], bh[ks][0], bh[ks][1]);
                    mma16816(acc[mi][1], al[mi][ks], bh[ks][2], bh[ks][3]);
                }
        }
        // epilogue: thread owns rows (mi*16 + lane>>2, +8), cols c, c+1 per n8 tile
        #pragma unroll
        for (int mi = 0; mi < 2; mi++)
            #pragma unroll
            for (int j = 0; j < 2; j++) {
                const int c = pass*128 + wid*16 + j*8 + 2*(lane & 3);
                const float b0 = bias[c], b1 = bias[c+1];
                #pragma unroll
                for (int rr = 0; rr < 2; rr++) {
                    const int r = mi*16 + (lane >> 2) + rr*8;
                    float v0 = acc[mi][j][rr*2+0] + b0;
                    float v1 = acc[mi][j][rr*2+1] + b1;
                    if (MODE == 0) {
                        BUFf[r*LDQ + c]   = v0;
                        BUFf[r*LDQ + c+1] = v1;
                    } else if (MODE == 2) {
                        Xd[r*H_ + c]   += v0;
                        Xd[r*H_ + c+1] += v1;
                    } else {
                        v0 = fmaxf(v0, 0.f); v1 = fmaxf(v1, 0.f);
                        __nv_bfloat16 h0, l0, h1, l1;
                        hilo(v0, h0, l0); hilo(v1, h1, l1);
                        __nv_bfloat16* d = BUF2 + r*LDB2;
                        d[c] = h0;       d[c+1] = h1;
                        d[512 + c] = l0; d[512 + c+1] = l1;
                    }
                }
            }
    }
}

// ---------------------------------------------------------------------------
// LayerNorm over 32 rows. OM 0: fp32 dst (ld H_); OM 1: hi/lo bf16 (ld LDA2)
// ---------------------------------------------------------------------------
template<int OM>
__device__ __forceinline__ void ln32(const float* src, void* dstv,
                                     const float* __restrict__ g,
                                     const float* __restrict__ b, int tid)
{
    const int w = tid >> 5, lane = tid & 31;
    #pragma unroll
    for (int j = 0; j < 4; j++) {
        const int r = w*4 + j;
        float sum = 0.f, sq = 0.f;
        #pragma unroll
        for (int i = 0; i < 8; i++) {
            const float v = src[r*H_ + lane + i*32];
            sum += v; sq = fmaf(v, v, sq);
        }
        #pragma unroll
        for (int o = 16; o > 0; o >>= 1) {
            sum += __shfl_xor_sync(0xffffffffu, sum, o);
            sq  += __shfl_xor_sync(0xffffffffu, sq,  o);
        }
        const float mu   = sum * (1.f/H_);
        const float var  = sq * (1.f/H_) - mu*mu;
        const float rstd = rsqrtf(var + 1e-5f);
        #pragma unroll
        for (int i = 0; i < 8; i++) {
            const int c = lane + i*32;
            const float y = fmaf((src[r*H_ + c] - mu)*rstd, g[c], b[c]);
            if (OM == 0) {
                ((float*)dstv)[r*H_ + c] = y;
            } else {
                __nv_bfloat16 hi, lo; hilo(y, hi, lo);
                __nv_bfloat16* d = (__nv_bfloat16*)dstv + r*LDA2;
                d[c] = hi; d[256 + c] = lo;
            }
        }
    }
}

// ---------------------------------------------------------------------------
// Attention: warp = head, lane = query row. qkv fp32 in BUFf (ld LDQ);
// output written as hi/lo bf16 into XN2.
// ---------------------------------------------------------------------------
__device__ __forceinline__ void attn32(const float* BUFf, const __nv_bfloat16* BS,
                                       const float* KM, __nv_bfloat16* XN2, int tid)
{
    const int head = tid >> 5, lane = tid & 31;
    const float scale = 0.17677669529663687f;  // 1/sqrt(32)

    float4 q4[8];
    const float4* qp = (const float4*)(BUFf + lane*LDQ + head*32);
    #pragma unroll
    for (int j = 0; j < 8; j++) q4[j] = qp[j];

    float sc[32];
    float m = -3.0e38f;
    #pragma unroll
    for (int kr = 0; kr < 32; kr++) {
        const float4* kp = (const float4*)(BUFf + kr*LDQ + 256 + head*32);
        float s = 0.f;
        #pragma unroll
        for (int j = 0; j < 8; j++) {
            const float4 kk = kp[j];
            s = fmaf(q4[j].x, kk.x, s); s = fmaf(q4[j].y, kk.y, s);
            s = fmaf(q4[j].z, kk.z, s); s = fmaf(q4[j].w, kk.w, s);
        }
        const float bv = __bfloat162float(BS[head*1024 + kr*32 + lane]);
        s = fmaf(s, scale, bv) + KM[kr];
        sc[kr] = s;
        m = fmaxf(m, s);
    }
    float den = 0.f;
    #pragma unroll
    for (int kr = 0; kr < 32; kr++) { const float e = __expf(sc[kr] - m); sc[kr] = e; den += e; }
    const float inv = 1.f / den;
    #pragma unroll
    for (int kr = 0; kr < 32; kr++) sc[kr] *= inv;

    #pragma unroll
    for (int dg = 0; dg < 8; dg++) {
        float4 acc = make_float4(0.f, 0.f, 0.f, 0.f);
        #pragma unroll
        for (int kr = 0; kr < 32; kr++) {
            const float4 v4 = *(const float4*)(BUFf + kr*LDQ + 512 + head*32 + dg*4);
            const float w = sc[kr];
            acc.x = fmaf(w, v4.x, acc.x); acc.y = fmaf(w, v4.y, acc.y);
            acc.z = fmaf(w, v4.z, acc.z); acc.w = fmaf(w, v4.w, acc.w);
        }
        const float av[4] = {acc.x, acc.y, acc.z, acc.w};
        __nv_bfloat16* d = XN2 + lane*LDA2;
        #pragma unroll
        for (int e = 0; e < 4; e++) {
            const int c = head*32 + dg*4 + e;
            __nv_bfloat16 hi, lo; hilo(av[e], hi, lo);
            d[c] = hi; d[256 + c] = lo;
        }
    }
}

// ---------------------------------------------------------------------------
__global__ __launch_bounds__(256, 1) void xf_kernel(
    const float* __restrict__ h, const void* __restrict__ validp,
    const float* __restrict__ ln1g, const float* __restrict__ ln1b,
    const float* __restrict__ qkvb, const float* __restrict__ outb,
    const float* __restrict__ ln2g, const float* __restrict__ ln2b,
    const float* __restrict__ ff1b, const float* __restrict__ ff2b,
    const float* __restrict__ fng, const float* __restrict__ fnb,
    float* __restrict__ out)
{
    extern __shared__ float sm[];
    float* X    = sm + OFF_X;
    float* BUFf = sm + OFF_BUF;
    __nv_bfloat16* BUF2 = (__nv_bfloat16*)(sm + OFF_BUF);
    __nv_bfloat16* XN2  = (__nv_bfloat16*)(sm + OFF_XN2);
    __nv_bfloat16* WT   = (__nv_bfloat16*)(sm + OFF_WT);
    __nv_bfloat16* BS   = (__nv_bfloat16*)(sm + OFF_BS);
    float* KM  = sm + OFF_KM;
    float* V01 = sm + OFF_V01;
    const int s = blockIdx.x, tid = threadIdx.x;

    // Detect 'valid' encoding: byte bools vs 32-bit words.
    const unsigned char* vb = (const unsigned char*)validp;
    bool bytemode = false;
    #pragma unroll
    for (int i = 1; i < 128; i += 4) bytemode |= (vb[i] != 0);

    if (tid < K_) {
        bool v;
        if (bytemode) v = vb[s*K_ + tid] != 0;
        else          v = ((const unsigned int*)validp)[s*K_ + tid] != 0u;
        KM[tid]  = v ? 0.f : -1e30f;
        V01[tid] = v ? 1.f : 0.f;
    }
    for (int i = tid; i < K_*H_/4; i += 256)
        ((float4*)X)[i] = ((const float4*)(h + (size_t)s*K_*H_))[i];
    {
        const uint4* gb = (const uint4*)(g_bias16 + (size_t)s*NH_*K_*K_);
        uint4* sb = (uint4*)BS;
        for (int i = tid; i < 1024; i += 256) sb[i] = gb[i];
    }
    __syncthreads();

    for (int l = 0; l < L_; l++) {
        ln32<1>(X, XN2, ln1g + l*H_, ln1b + l*H_, tid);
        __syncthreads();
        mm3<768, 256, 0>(XN2, LDA2, g_w2_qkv + (size_t)l*768*512,
                         qkvb + l*768, X, BUFf, BUF2, WT, tid);
        __syncthreads();
        attn32(BUFf, BS, KM, XN2, tid);
        __syncthreads();
        mm3<256, 256, 2>(XN2, LDA2, g_w2_out + (size_t)l*256*512,
                         outb + l*H_, X, BUFf, BUF2, WT, tid);
        __syncthreads();
        ln32<1>(X, XN2, ln2g + l*H_, ln2b + l*H_, tid);
        __syncthreads();
        mm3<512, 256, 1>(XN2, LDA2, g_w2_ff1 + (size_t)l*512*512,
                         ff1b + l*FFN_, X, BUFf, BUF2, WT, tid);
        __syncthreads();
        mm3<256, 512, 2>(BUF2, LDB2, g_w2_ff2 + (size_t)l*256*1024,
                         ff2b + l*H_, X, BUFf, BUF2, WT, tid);
        __syncthreads();
    }

    // final LN (fp32 into BUFf region, ld H_) + masked mean over k
    ln32<0>(X, BUFf, fng, fnb, tid);
    __syncthreads();
    float sum = 0.f, cnt = 0.f;
    #pragma unroll
    for (int r = 0; r < K_; r++) {
        sum = fmaf(BUFf[r*H_ + tid], V01[r], sum);
        cnt += V01[r];
    }
    out[(size_t)s*H_ + tid] = sum / fmaxf(cnt, 1.f);
}

// ---------------------------------------------------------------------------
extern "C" void kernel_launch(void* const* d_in, const int* in_sizes, int n_in,
                              void* d_out, int out_size)
{
    // inputs: 0 h, 1 valid, 2 edge_index, 3 ea_flat, 4 edge_ptr, 5 S, 6 k,
    // 7 edge_W, 8 edge_b, 9 ln1_g, 10 ln1_b, 11 qkv_W, 12 qkv_b, 13 out_W,
    // 14 out_b, 15 ln2_g, 16 ln2_b, 17 ff1_W, 18 ff1_b, 19 ff2_W, 20 ff2_b,
    // 21 fnorm_g, 22 fnorm_b
    cudaFuncSetAttribute(xf_kernel, cudaFuncAttributeMaxDynamicSharedMemorySize,
                         SMEM_FLOATS * (int)sizeof(float));

    __nv_bfloat16 *w2_qkv, *w2_out, *w2_ff1, *w2_ff2;
    cudaGetSymbolAddress((void**)&w2_qkv, g_w2_qkv);
    cudaGetSymbolAddress((void**)&w2_out, g_w2_out);
    cudaGetSymbolAddress((void**)&w2_ff1, g_w2_ff1);
    cudaGetSymbolAddress((void**)&w2_ff2, g_w2_ff2);

    wconv<<<(L_*768*256 + 255)/256, 256>>>((const float*)d_in[11], w2_qkv, 256, L_*768*256);
    wconv<<<(L_*256*256 + 255)/256, 256>>>((const float*)d_in[13], w2_out, 256, L_*256*256);
    wconv<<<(L_*512*256 + 255)/256, 256>>>((const float*)d_in[17], w2_ff1, 256, L_*512*256);
    wconv<<<(L_*256*512 + 255)/256, 256>>>((const float*)d_in[19], w2_ff2, 512, L_*256*512);

    edge_bias_kernel<<<S_, 256>>>(
        (const float*)d_in[3], (const int*)d_in[2],
        (const float*)d_in[7], (const float*)d_in[8]);

    xf_kernel<<<S_, 256, SMEM_FLOATS * sizeof(float)>>>(
        (const float*)d_in[0], d_in[1],
        (const float*)d_in[9],  (const float*)d_in[10],
        (const float*)d_in[12], (const float*)d_in[14],
        (const float*)d_in[15], (const float*)d_in[16],
        (const float*)d_in[18], (const float*)d_in[20],
        (const float*)d_in[21], (const float*)d_in[22],
        (float*)d_out);
}

// round 9
// speedup vs baseline: 3.0822x; 1.3184x over previous
#include <cuda_runtime.h>
#include <cuda_bf16.h>
#include <math.h>

// Problem constants (LocalSubgraphTransformer)
#define S_   2048
#define K_   32
#define H_   256
#define NH_  8
#define DH_  32
#define L_   4
#define ED_  16
#define FFN_ 512
#define EPS_ 64
#define E_   (S_*EPS_)

#define LDA2 520    // XN2 row stride (bf16): hi 256 | lo 256 | pad 8
#define LDB2 1032   // BUF2 row stride (bf16): hi 512 | lo 512 | pad 8
#define LDQ  772    // qkv fp32 row stride

// ---------------- device scratch ----------------
__device__ __nv_bfloat16 g_bias16[(size_t)S_ * NH_ * K_ * K_];   // [S][h][k][q]
// weights in mma B-fragment order, hi/lo: N*2*KA bf16 each
__device__ unsigned g_w2_qkv[(size_t)L_ * 768 * 256];   // u32 words = N*2KA/2
__device__ unsigned g_w2_out[(size_t)L_ * 256 * 256];
__device__ unsigned g_w2_ff1[(size_t)L_ * 512 * 256];
__device__ unsigned g_w2_ff2[(size_t)L_ * 256 * 512];

// ---------------------------------------------------------------------------
// Weight conversion: fp32 [L][N][KA] row-major -> B-fragment layout.
// Unit (16 B = 4 words) uid = ((((pass*T + kt)*8 + ng)*2 + j)*2 + hl)*32 + lane
//   n = pass*128 + ng*16 + j*8 + (lane>>2)
//   word w: k = kt*32 + (w>>1)*16 + (lane&3)*2 + (w&1)*8, covers {k, k+1}
//   hl=0: hi part, hl=1: lo residual
// ---------------------------------------------------------------------------
__global__ void wconv_frag(const float* __restrict__ src, uint4* __restrict__ dst,
                           int N, int KA, int total_units)
{
    const int e = blockIdx.x*256 + threadIdx.x;
    if (e >= total_units) return;
    const int UPL = N*KA/4;            // units per layer
    const int l = e / UPL;
    int u = e - l*UPL;
    const int lane = u & 31; u >>= 5;
    const int hl = u & 1; u >>= 1;
    const int j = u & 1; u >>= 1;
    const int ng = u & 7; u >>= 3;
    const int T = KA/32;
    const int kt = u % T;
    const int pass = u / T;
    const int n = pass*128 + ng*16 + j*8 + (lane>>2);
    const float* sp = src + ((size_t)l*N + n)*KA;

    unsigned words[4];
    #pragma unroll
    for (int w = 0; w < 4; w++) {
        const int k = kt*32 + (w>>1)*16 + (lane&3)*2 + (w&1)*8;
        const float f0 = sp[k], f1 = sp[k+1];
        __nv_bfloat16 v0, v1;
        if (hl == 0) { v0 = __float2bfloat16(f0); v1 = __float2bfloat16(f1); }
        else {
            const __nv_bfloat16 h0 = __float2bfloat16(f0), h1 = __float2bfloat16(f1);
            v0 = __float2bfloat16(f0 - __bfloat162float(h0));
            v1 = __float2bfloat16(f1 - __bfloat162float(h1));
        }
        unsigned lo16 = (unsigned)*(unsigned short*)&v0;
        unsigned hi16 = (unsigned)*(unsigned short*)&v1;
        words[w] = lo16 | (hi16 << 16);
    }
    dst[e] = make_uint4(words[0], words[1], words[2], words[3]);
}

// ---------------------------------------------------------------------------
// Kernel A: per-subgraph edge bias via shared-memory scatter-add
// ---------------------------------------------------------------------------
__global__ __launch_bounds__(256) void edge_bias_kernel(
    const float* __restrict__ ea, const int* __restrict__ eidx,
    const float* __restrict__ eW, const float* __restrict__ eb)
{
    __shared__ float sb[NH_*K_*K_];   // [h][dst=k][src=q]
    __shared__ float sa[EPS_*ED_];
    __shared__ float sw[NH_*ED_];
    __shared__ float sbv[NH_];
    const int s = blockIdx.x, tid = threadIdx.x;

    if (tid < NH_*ED_) sw[tid] = eW[tid];
    if (tid < NH_)     sbv[tid] = eb[tid];
    for (int i = tid; i < EPS_*ED_;  i += 256) sa[i] = ea[(size_t)s*EPS_*ED_ + i];
    for (int i = tid; i < NH_*K_*K_; i += 256) sb[i] = 0.f;
    __syncthreads();

    for (int t = tid; t < EPS_*NH_; t += 256) {
        const int i  = t >> 3;
        const int hh = t & 7;
        float p = sbv[hh];
        #pragma unroll
        for (int d = 0; d < ED_; d++) p = fmaf(sa[i*ED_+d], sw[hh*ED_+d], p);
        const int e  = s*EPS_ + i;
        const int sr = eidx[e];        // src = query index
        const int ds = eidx[E_ + e];   // dst = key index
        atomicAdd(&sb[hh*K_*K_ + ds*K_ + sr], p);
    }
    __syncthreads();
    for (int i = tid; i < NH_*K_*K_; i += 256)
        g_bias16[(size_t)s*NH_*K_*K_ + i] = __float2bfloat16(sb[i]);
}

// ---------------------------------------------------------------------------
// smem layout (float offsets)  -- WT staging buffer removed
// ---------------------------------------------------------------------------
#define OFF_X    0        /* 8192 f: X fp32 [32][256] */
#define OFF_BUF  8192     /* 24704 f: union { fp32 [32][772] qkv ; bf16 [32][1032] ffn2 } */
#define OFF_XN2  32896    /* 8320 f: bf16 [32][520] */
#define OFF_BS   41216    /* 4096 f: bf16 [8][32][32] */
#define OFF_KM   45312
#define OFF_V01  45344
#define SMEM_FLOATS 45376  /* 181504 bytes */

__device__ __forceinline__ unsigned sptr(const void* p) {
    return (unsigned)__cvta_generic_to_shared(p);
}
__device__ __forceinline__ void ldm_x4(unsigned& a0, unsigned& a1, unsigned& a2,
                                       unsigned& a3, unsigned addr) {
    asm volatile("ldmatrix.sync.aligned.m8n8.x4.shared.b16 {%0,%1,%2,%3},[%4];"
                 : "=r"(a0), "=r"(a1), "=r"(a2), "=r"(a3) : "r"(addr));
}
__device__ __forceinline__ void mma16816(float* c, const unsigned* a,
                                         unsigned b0, unsigned b1) {
    asm volatile("mma.sync.aligned.m16n8k16.row.col.f32.bf16.bf16.f32 "
                 "{%0,%1,%2,%3},{%4,%5,%6,%7},{%8,%9},{%0,%1,%2,%3};"
                 : "+f"(c[0]), "+f"(c[1]), "+f"(c[2]), "+f"(c[3])
                 : "r"(a[0]), "r"(a[1]), "r"(a[2]), "r"(a[3]), "r"(b0), "r"(b1));
}
__device__ __forceinline__ void hilo(float v, __nv_bfloat16& hi, __nv_bfloat16& lo) {
    hi = __float2bfloat16(v);
    lo = __float2bfloat16(v - __bfloat162float(hi));
}

// ---------------------------------------------------------------------------
// Tensor-core GEMM, hi/lo split, B via direct LDG from fragment-layout weights.
// C = A_hi W_hi^T + A_hi W_lo^T + A_lo W_hi^T + bias
// A: smem bf16 [32][hi KA | lo KA] (ld lda). Warp tile m32 x n16.
// Processes passes in pairs (n256 blocks) to amortize A fragment loads.
// MODE 0: fp32 -> BUFf (ld LDQ); 1: relu -> hi/lo BUF2; 2: += X (ld H_)
// ---------------------------------------------------------------------------
template<int N, int KA, int MODE>
__device__ __forceinline__ void mm3(const __nv_bfloat16* A, int lda,
    const uint4* __restrict__ Wf, const float* __restrict__ bias,
    float* Xd, float* BUFf, __nv_bfloat16* BUF2, int tid)
{
    const int lane = tid & 31, wid = tid >> 5;
    constexpr int T = KA/32;          // k32 stages
    constexpr int NB = N/256;         // pass-pair blocks
    // A ldmatrix base: row = lane&15, 16B col = (lane>>4)
    const unsigned a_s = sptr(A) + (unsigned)(((lane & 15)*lda + ((lane >> 4) << 3))*2);

    for (int blk = 0; blk < NB; blk++) {
        float acc[2][2][2][4];   // [p][mi][j][4]
        #pragma unroll
        for (int p = 0; p < 2; p++)
            #pragma unroll
            for (int mi = 0; mi < 2; mi++)
                #pragma unroll
                for (int j = 0; j < 2; j++)
                    #pragma unroll
                    for (int i = 0; i < 4; i++) acc[p][mi][j][i] = 0.f;

        #pragma unroll 4
        for (int kt = 0; kt < T; kt++) {
            // A fragments: [mi][ks] hi and lo (8 x ldmatrix.x4), shared by both passes
            unsigned ah[2][2][4], al[2][2][4];
            #pragma unroll
            for (int mi = 0; mi < 2; mi++)
                #pragma unroll
                for (int ks = 0; ks < 2; ks++) {
                    const unsigned base = a_s + (unsigned)((mi*16*lda + kt*32 + ks*16)*2);
                    ldm_x4(ah[mi][ks][0], ah[mi][ks][1], ah[mi][ks][2], ah[mi][ks][3], base);
                    ldm_x4(al[mi][ks][0], al[mi][ks][1], al[mi][ks][2], al[mi][ks][3],
                           base + (unsigned)(KA*2));
                }
            #pragma unroll
            for (int p = 0; p < 2; p++) {
                // B fragments: uid = ((((pass*T+kt)*8+wid)*2+j)*2+hl)*32 + lane
                const int ub = ((((blk*2 + p)*T + kt)*8 + wid)*2)*2;
                uint4 bh[2], bl[2];
                #pragma unroll
                for (int j = 0; j < 2; j++) {
                    bh[j] = Wf[(size_t)(ub + j*2 + 0)*32 + lane];
                    bl[j] = Wf[(size_t)(ub + j*2 + 1)*32 + lane];
                }
                #pragma unroll
                for (int mi = 0; mi < 2; mi++) {
                    // ks=0 uses words .x,.y ; ks=1 uses .z,.w
                    mma16816(acc[p][mi][0], ah[mi][0], bh[0].x, bh[0].y);
                    mma16816(acc[p][mi][1], ah[mi][0], bh[1].x, bh[1].y);
                    mma16816(acc[p][mi][0], ah[mi][1], bh[0].z, bh[0].w);
                    mma16816(acc[p][mi][1], ah[mi][1], bh[1].z, bh[1].w);
                    mma16816(acc[p][mi][0], ah[mi][0], bl[0].x, bl[0].y);
                    mma16816(acc[p][mi][1], ah[mi][0], bl[1].x, bl[1].y);
                    mma16816(acc[p][mi][0], ah[mi][1], bl[0].z, bl[0].w);
                    mma16816(acc[p][mi][1], ah[mi][1], bl[1].z, bl[1].w);
                    mma16816(acc[p][mi][0], al[mi][0], bh[0].x, bh[0].y);
                    mma16816(acc[p][mi][1], al[mi][0], bh[1].x, bh[1].y);
                    mma16816(acc[p][mi][0], al[mi][1], bh[0].z, bh[0].w);
                    mma16816(acc[p][mi][1], al[mi][1], bh[1].z, bh[1].w);
                }
            }
        }
        // epilogue
        #pragma unroll
        for (int p = 0; p < 2; p++)
            #pragma unroll
            for (int mi = 0; mi < 2; mi++)
                #pragma unroll
                for (int j = 0; j < 2; j++) {
                    const int c = (blk*2 + p)*128 + wid*16 + j*8 + 2*(lane & 3);
                    const float b0 = bias[c], b1 = bias[c+1];
                    #pragma unroll
                    for (int rr = 0; rr < 2; rr++) {
                        const int r = mi*16 + (lane >> 2) + rr*8;
                        float v0 = acc[p][mi][j][rr*2+0] + b0;
                        float v1 = acc[p][mi][j][rr*2+1] + b1;
                        if (MODE == 0) {
                            BUFf[r*LDQ + c]   = v0;
                            BUFf[r*LDQ + c+1] = v1;
                        } else if (MODE == 2) {
                            Xd[r*H_ + c]   += v0;
                            Xd[r*H_ + c+1] += v1;
                        } else {
                            v0 = fmaxf(v0, 0.f); v1 = fmaxf(v1, 0.f);
                            __nv_bfloat16 h0, l0, h1, l1;
                            hilo(v0, h0, l0); hilo(v1, h1, l1);
                            __nv_bfloat16* d = BUF2 + r*LDB2;
                            d[c] = h0;       d[c+1] = h1;
                            d[512 + c] = l0; d[512 + c+1] = l1;
                        }
                    }
                }
    }
}

// ---------------------------------------------------------------------------
// LayerNorm over 32 rows. OM 0: fp32 dst (ld H_); OM 1: hi/lo bf16 (ld LDA2)
// ---------------------------------------------------------------------------
template<int OM>
__device__ __forceinline__ void ln32(const float* src, void* dstv,
                                     const float* __restrict__ g,
                                     const float* __restrict__ b, int tid)
{
    const int w = tid >> 5, lane = tid & 31;
    #pragma unroll
    for (int j = 0; j < 4; j++) {
        const int r = w*4 + j;
        float sum = 0.f, sq = 0.f;
        #pragma unroll
        for (int i = 0; i < 8; i++) {
            const float v = src[r*H_ + lane + i*32];
            sum += v; sq = fmaf(v, v, sq);
        }
        #pragma unroll
        for (int o = 16; o > 0; o >>= 1) {
            sum += __shfl_xor_sync(0xffffffffu, sum, o);
            sq  += __shfl_xor_sync(0xffffffffu, sq,  o);
        }
        const float mu   = sum * (1.f/H_);
        const float var  = sq * (1.f/H_) - mu*mu;
        const float rstd = rsqrtf(var + 1e-5f);
        #pragma unroll
        for (int i = 0; i < 8; i++) {
            const int c = lane + i*32;
            const float y = fmaf((src[r*H_ + c] - mu)*rstd, g[c], b[c]);
            if (OM == 0) {
                ((float*)dstv)[r*H_ + c] = y;
            } else {
                __nv_bfloat16 hi, lo; hilo(y, hi, lo);
                __nv_bfloat16* d = (__nv_bfloat16*)dstv + r*LDA2;
                d[c] = hi; d[256 + c] = lo;
            }
        }
    }
}

// ---------------------------------------------------------------------------
// Attention: warp = head, lane = query row. qkv fp32 in BUFf (ld LDQ);
// output written as hi/lo bf16 into XN2.
// ---------------------------------------------------------------------------
__device__ __forceinline__ void attn32(const float* BUFf, const __nv_bfloat16* BS,
                                       const float* KM, __nv_bfloat16* XN2, int tid)
{
    const int head = tid >> 5, lane = tid & 31;
    const float scale = 0.17677669529663687f;  // 1/sqrt(32)

    float4 q4[8];
    const float4* qp = (const float4*)(BUFf + lane*LDQ + head*32);
    #pragma unroll
    for (int j = 0; j < 8; j++) q4[j] = qp[j];

    float sc[32];
    float m = -3.0e38f;
    #pragma unroll
    for (int kr = 0; kr < 32; kr++) {
        const float4* kp = (const float4*)(BUFf + kr*LDQ + 256 + head*32);
        float s = 0.f;
        #pragma unroll
        for (int j = 0; j < 8; j++) {
            const float4 kk = kp[j];
            s = fmaf(q4[j].x, kk.x, s); s = fmaf(q4[j].y, kk.y, s);
            s = fmaf(q4[j].z, kk.z, s); s = fmaf(q4[j].w, kk.w, s);
        }
        const float bv = __bfloat162float(BS[head*1024 + kr*32 + lane]);
        s = fmaf(s, scale, bv) + KM[kr];
        sc[kr] = s;
        m = fmaxf(m, s);
    }
    float den = 0.f;
    #pragma unroll
    for (int kr = 0; kr < 32; kr++) { const float e = __expf(sc[kr] - m); sc[kr] = e; den += e; }
    const float inv = 1.f / den;
    #pragma unroll
    for (int kr = 0; kr < 32; kr++) sc[kr] *= inv;

    #pragma unroll
    for (int dg = 0; dg < 8; dg++) {
        float4 acc = make_float4(0.f, 0.f, 0.f, 0.f);
        #pragma unroll
        for (int kr = 0; kr < 32; kr++) {
            const float4 v4 = *(const float4*)(BUFf + kr*LDQ + 512 + head*32 + dg*4);
            const float w = sc[kr];
            acc.x = fmaf(w, v4.x, acc.x); acc.y = fmaf(w, v4.y, acc.y);
            acc.z = fmaf(w, v4.z, acc.z); acc.w = fmaf(w, v4.w, acc.w);
        }
        const float av[4] = {acc.x, acc.y, acc.z, acc.w};
        __nv_bfloat16* d = XN2 + lane*LDA2;
        #pragma unroll
        for (int e = 0; e < 4; e++) {
            const int c = head*32 + dg*4 + e;
            __nv_bfloat16 hi, lo; hilo(av[e], hi, lo);
            d[c] = hi; d[256 + c] = lo;
        }
    }
}

// ---------------------------------------------------------------------------
__global__ __launch_bounds__(256, 1) void xf_kernel(
    const float* __restrict__ h, const void* __restrict__ validp,
    const float* __restrict__ ln1g, const float* __restrict__ ln1b,
    const float* __restrict__ qkvb, const float* __restrict__ outb,
    const float* __restrict__ ln2g, const float* __restrict__ ln2b,
    const float* __restrict__ ff1b, const float* __restrict__ ff2b,
    const float* __restrict__ fng, const float* __restrict__ fnb,
    float* __restrict__ out)
{
    extern __shared__ float sm[];
    float* X    = sm + OFF_X;
    float* BUFf = sm + OFF_BUF;
    __nv_bfloat16* BUF2 = (__nv_bfloat16*)(sm + OFF_BUF);
    __nv_bfloat16* XN2  = (__nv_bfloat16*)(sm + OFF_XN2);
    __nv_bfloat16* BS   = (__nv_bfloat16*)(sm + OFF_BS);
    float* KM  = sm + OFF_KM;
    float* V01 = sm + OFF_V01;
    const int s = blockIdx.x, tid = threadIdx.x;

    // Detect 'valid' encoding: byte bools vs 32-bit words.
    const unsigned char* vb = (const unsigned char*)validp;
    bool bytemode = false;
    #pragma unroll
    for (int i = 1; i < 128; i += 4) bytemode |= (vb[i] != 0);

    if (tid < K_) {
        bool v;
        if (bytemode) v = vb[s*K_ + tid] != 0;
        else          v = ((const unsigned int*)validp)[s*K_ + tid] != 0u;
        KM[tid]  = v ? 0.f : -1e30f;
        V01[tid] = v ? 1.f : 0.f;
    }
    for (int i = tid; i < K_*H_/4; i += 256)
        ((float4*)X)[i] = ((const float4*)(h + (size_t)s*K_*H_))[i];
    {
        const uint4* gb = (const uint4*)(g_bias16 + (size_t)s*NH_*K_*K_);
        uint4* sb = (uint4*)BS;
        for (int i = tid; i < 1024; i += 256) sb[i] = gb[i];
    }
    __syncthreads();

    for (int l = 0; l < L_; l++) {
        ln32<1>(X, XN2, ln1g + l*H_, ln1b + l*H_, tid);
        __syncthreads();
        mm3<768, 256, 0>(XN2, LDA2, (const uint4*)(g_w2_qkv + (size_t)l*768*256),
                         qkvb + l*768, X, BUFf, BUF2, tid);
        __syncthreads();
        attn32(BUFf, BS, KM, XN2, tid);
        __syncthreads();
        mm3<256, 256, 2>(XN2, LDA2, (const uint4*)(g_w2_out + (size_t)l*256*256),
                         outb + l*H_, X, BUFf, BUF2, tid);
        __syncthreads();
        ln32<1>(X, XN2, ln2g + l*H_, ln2b + l*H_, tid);
        __syncthreads();
        mm3<512, 256, 1>(XN2, LDA2, (const uint4*)(g_w2_ff1 + (size_t)l*512*256),
                         ff1b + l*FFN_, X, BUFf, BUF2, tid);
        __syncthreads();
        mm3<256, 512, 2>(BUF2, LDB2, (const uint4*)(g_w2_ff2 + (size_t)l*256*512),
                         ff2b + l*H_, X, BUFf, BUF2, tid);
        __syncthreads();
    }

    // final LN (fp32 into BUFf region, ld H_) + masked mean over k
    ln32<0>(X, BUFf, fng, fnb, tid);
    __syncthreads();
    float sum = 0.f, cnt = 0.f;
    #pragma unroll
    for (int r = 0; r < K_; r++) {
        sum = fmaf(BUFf[r*H_ + tid], V01[r], sum);
        cnt += V01[r];
    }
    out[(size_t)s*H_ + tid] = sum / fmaxf(cnt, 1.f);
}

// ---------------------------------------------------------------------------
extern "C" void kernel_launch(void* const* d_in, const int* in_sizes, int n_in,
                              void* d_out, int out_size)
{
    // inputs: 0 h, 1 valid, 2 edge_index, 3 ea_flat, 4 edge_ptr, 5 S, 6 k,
    // 7 edge_W, 8 edge_b, 9 ln1_g, 10 ln1_b, 11 qkv_W, 12 qkv_b, 13 out_W,
    // 14 out_b, 15 ln2_g, 16 ln2_b, 17 ff1_W, 18 ff1_b, 19 ff2_W, 20 ff2_b,
    // 21 fnorm_g, 22 fnorm_b
    cudaFuncSetAttribute(xf_kernel, cudaFuncAttributeMaxDynamicSharedMemorySize,
                         SMEM_FLOATS * (int)sizeof(float));

    unsigned *w2_qkv, *w2_out, *w2_ff1, *w2_ff2;
    cudaGetSymbolAddress((void**)&w2_qkv, g_w2_qkv);
    cudaGetSymbolAddress((void**)&w2_out, g_w2_out);
    cudaGetSymbolAddress((void**)&w2_ff1, g_w2_ff1);
    cudaGetSymbolAddress((void**)&w2_ff2, g_w2_ff2);

    // total_units = L * N*KA/4 per gemm
    wconv_frag<<<(L_*768*256/4 + 255)/256, 256>>>(
        (const float*)d_in[11], (uint4*)w2_qkv, 768, 256, L_*768*256/4);
    wconv_frag<<<(L_*256*256/4 + 255)/256, 256>>>(
        (const float*)d_in[13], (uint4*)w2_out, 256, 256, L_*256*256/4);
    wconv_frag<<<(L_*512*256/4 + 255)/256, 256>>>(
        (const float*)d_in[17], (uint4*)w2_ff1, 512, 256, L_*512*256/4);
    wconv_frag<<<(L_*256*512/4 + 255)/256, 256>>>(
        (const float*)d_in[19], (uint4*)w2_ff2, 256, 512, L_*256*512/4);

    edge_bias_kernel<<<S_, 256>>>(
        (const float*)d_in[3], (const int*)d_in[2],
        (const float*)d_in[7], (const float*)d_in[8]);

    xf_kernel<<<S_, 256, SMEM_FLOATS * sizeof(float)>>>(
        (const float*)d_in[0], d_in[1],
        (const float*)d_in[9],  (const float*)d_in[10],
        (const float*)d_in[12], (const float*)d_in[14],
        (const float*)d_in[15], (const float*)d_in[16],
        (const float*)d_in[18], (const float*)d_in[20],
        (const float*)d_in[21], (const float*)d_in[22],
        (float*)d_out);
}

// round 10
// speedup vs baseline: 3.1879x; 1.0343x over previous
#include <cuda_runtime.h>
#include <cuda_bf16.h>
#include <math.h>

// Problem constants (LocalSubgraphTransformer)
#define S_   2048
#define K_   32
#define H_   256
#define NH_  8
#define DH_  32
#define L_   4
#define ED_  16
#define FFN_ 512
#define EPS_ 64
#define E_   (S_*EPS_)

#define LDA2 520    // XN2 row stride (bf16): hi 256 | lo 256 | pad 8
#define LDB2 1032   // BUF2 row stride (bf16): hi 512 | lo 512 | pad 8
#define LDQ  772    // qkv fp32 row stride

// ---------------- device scratch ----------------
__device__ __nv_bfloat16 g_bias16[(size_t)S_ * NH_ * K_ * K_];   // [S][h][k][q]
// weights in mma B-fragment order, hi/lo: N*2*KA bf16 each
__device__ unsigned g_w2_qkv[(size_t)L_ * 768 * 256];   // u32 words = N*2KA/2
__device__ unsigned g_w2_out[(size_t)L_ * 256 * 256];
__device__ unsigned g_w2_ff1[(size_t)L_ * 512 * 256];
__device__ unsigned g_w2_ff2[(size_t)L_ * 256 * 512];

// ---------------------------------------------------------------------------
// Weight conversion: fp32 [L][N][KA] row-major -> B-fragment layout.
// Unit (16 B = 4 words) uid = ((((pass*T + kt)*8 + ng)*2 + j)*2 + hl)*32 + lane
//   n = pass*128 + ng*16 + j*8 + (lane>>2)
//   word w: k = kt*32 + (w>>1)*16 + (lane&3)*2 + (w&1)*8, covers {k, k+1}
//   hl=0: hi part, hl=1: lo residual
// ---------------------------------------------------------------------------
__global__ void wconv_frag(const float* __restrict__ src, uint4* __restrict__ dst,
                           int N, int KA, int total_units)
{
    const int e = blockIdx.x*256 + threadIdx.x;
    if (e >= total_units) return;
    const int UPL = N*KA/4;            // units per layer
    const int l = e / UPL;
    int u = e - l*UPL;
    const int lane = u & 31; u >>= 5;
    const int hl = u & 1; u >>= 1;
    const int j = u & 1; u >>= 1;
    const int ng = u & 7; u >>= 3;
    const int T = KA/32;
    const int kt = u % T;
    const int pass = u / T;
    const int n = pass*128 + ng*16 + j*8 + (lane>>2);
    const float* sp = src + ((size_t)l*N + n)*KA;

    unsigned words[4];
    #pragma unroll
    for (int w = 0; w < 4; w++) {
        const int k = kt*32 + (w>>1)*16 + (lane&3)*2 + (w&1)*8;
        const float f0 = sp[k], f1 = sp[k+1];
        __nv_bfloat16 v0, v1;
        if (hl == 0) { v0 = __float2bfloat16(f0); v1 = __float2bfloat16(f1); }
        else {
            const __nv_bfloat16 h0 = __float2bfloat16(f0), h1 = __float2bfloat16(f1);
            v0 = __float2bfloat16(f0 - __bfloat162float(h0));
            v1 = __float2bfloat16(f1 - __bfloat162float(h1));
        }
        unsigned lo16 = (unsigned)*(unsigned short*)&v0;
        unsigned hi16 = (unsigned)*(unsigned short*)&v1;
        words[w] = lo16 | (hi16 << 16);
    }
    dst[e] = make_uint4(words[0], words[1], words[2], words[3]);
}

// ---------------------------------------------------------------------------
// Kernel A: per-subgraph edge bias via shared-memory scatter-add
// ---------------------------------------------------------------------------
__global__ __launch_bounds__(256) void edge_bias_kernel(
    const float* __restrict__ ea, const int* __restrict__ eidx,
    const float* __restrict__ eW, const float* __restrict__ eb)
{
    __shared__ float sb[NH_*K_*K_];   // [h][dst=k][src=q]
    __shared__ float sa[EPS_*ED_];
    __shared__ float sw[NH_*ED_];
    __shared__ float sbv[NH_];
    const int s = blockIdx.x, tid = threadIdx.x;

    if (tid < NH_*ED_) sw[tid] = eW[tid];
    if (tid < NH_)     sbv[tid] = eb[tid];
    for (int i = tid; i < EPS_*ED_;  i += 256) sa[i] = ea[(size_t)s*EPS_*ED_ + i];
    for (int i = tid; i < NH_*K_*K_; i += 256) sb[i] = 0.f;
    __syncthreads();

    for (int t = tid; t < EPS_*NH_; t += 256) {
        const int i  = t >> 3;
        const int hh = t & 7;
        float p = sbv[hh];
        #pragma unroll
        for (int d = 0; d < ED_; d++) p = fmaf(sa[i*ED_+d], sw[hh*ED_+d], p);
        const int e  = s*EPS_ + i;
        const int sr = eidx[e];        // src = query index
        const int ds = eidx[E_ + e];   // dst = key index
        atomicAdd(&sb[hh*K_*K_ + ds*K_ + sr], p);
    }
    __syncthreads();
    for (int i = tid; i < NH_*K_*K_; i += 256)
        g_bias16[(size_t)s*NH_*K_*K_ + i] = __float2bfloat16(sb[i]);
}

// ---------------------------------------------------------------------------
// smem layout (float offsets)
// ---------------------------------------------------------------------------
#define OFF_X    0        /* 8192 f: X fp32 [32][256] */
#define OFF_BUF  8192     /* 24704 f: union { fp32 [32][772] qkv ; bf16 [32][1032] ffn2 } */
#define OFF_XN2  32896    /* 8320 f: bf16 [32][520] */
#define OFF_BS   41216    /* 4096 f: bf16 [8][32][32] */
#define OFF_KM   45312
#define OFF_V01  45344
#define SMEM_FLOATS 45376  /* 181504 bytes */

__device__ __forceinline__ unsigned sptr(const void* p) {
    return (unsigned)__cvta_generic_to_shared(p);
}
__device__ __forceinline__ void ldm_x4(unsigned& a0, unsigned& a1, unsigned& a2,
                                       unsigned& a3, unsigned addr) {
    asm volatile("ldmatrix.sync.aligned.m8n8.x4.shared.b16 {%0,%1,%2,%3},[%4];"
                 : "=r"(a0), "=r"(a1), "=r"(a2), "=r"(a3) : "r"(addr));
}
__device__ __forceinline__ void mma16816(float* c, const unsigned* a,
                                         unsigned b0, unsigned b1) {
    asm volatile("mma.sync.aligned.m16n8k16.row.col.f32.bf16.bf16.f32 "
                 "{%0,%1,%2,%3},{%4,%5,%6,%7},{%8,%9},{%0,%1,%2,%3};"
                 : "+f"(c[0]), "+f"(c[1]), "+f"(c[2]), "+f"(c[3])
                 : "r"(a[0]), "r"(a[1]), "r"(a[2]), "r"(a[3]), "r"(b0), "r"(b1));
}
__device__ __forceinline__ void hilo(float v, __nv_bfloat16& hi, __nv_bfloat16& lo) {
    hi = __float2bfloat16(v);
    lo = __float2bfloat16(v - __bfloat162float(hi));
}

// ---------------------------------------------------------------------------
// Tensor-core GEMM, hi/lo split, B via direct LDG from fragment-layout weights,
// with register double-buffered B prefetch (lookahead ~1.5 steps).
// C = A_hi W_hi^T + A_hi W_lo^T + A_lo W_hi^T + bias
// A: smem bf16 [32][hi KA | lo KA] (ld lda). Warp tile m32 x n16.
// Passes processed in pairs (n256 blocks); steps = (kt, p), p parity static.
// MODE 0: fp32 -> BUFf (ld LDQ); 1: relu -> hi/lo BUF2; 2: += X (ld H_)
// ---------------------------------------------------------------------------
template<int N, int KA, int MODE>
__device__ __forceinline__ void mm3(const __nv_bfloat16* A, int lda,
    const uint4* __restrict__ Wf, const float* __restrict__ bias,
    float* Xd, float* BUFf, __nv_bfloat16* BUF2, int tid)
{
    const int lane = tid & 31, wid = tid >> 5;
    constexpr int T = KA/32;          // k32 stages
    constexpr int NB = N/256;         // pass-pair blocks
    // A ldmatrix base: row = lane&15, 16B col = (lane>>4)
    const unsigned a_s = sptr(A) + (unsigned)(((lane & 15)*lda + ((lane >> 4) << 3))*2);

    for (int blk = 0; blk < NB; blk++) {
        float acc[2][2][2][4];   // [p][mi][j][4]
        #pragma unroll
        for (int p = 0; p < 2; p++)
            #pragma unroll
            for (int mi = 0; mi < 2; mi++)
                #pragma unroll
                for (int j = 0; j < 2; j++)
                    #pragma unroll
                    for (int i = 0; i < 4; i++) acc[p][mi][j][i] = 0.f;

        // B fragment loader: step = 2*kt + p; buf[0]=j0 hi, [1]=j0 lo, [2]=j1 hi, [3]=j1 lo
        #define LDB(step, buf) do {                                                   \
            const int _p = (step) & 1, _kt = (step) >> 1;                             \
            const size_t _b = ((size_t)(((blk*2 + _p)*T + _kt)*8 + wid)*4)*32 + lane; \
            (buf)[0] = Wf[_b];       (buf)[1] = Wf[_b + 32];                          \
            (buf)[2] = Wf[_b + 64];  (buf)[3] = Wf[_b + 96];                          \
        } while (0)

        uint4 b0[4], b1[4];
        LDB(0, b0);
        LDB(1, b1);

        for (int kt = 0; kt < T; kt++) {
            // A fragments for this kt: [mi][ks] hi and lo (8 x ldmatrix.x4)
            unsigned ah[2][2][4], al[2][2][4];
            #pragma unroll
            for (int mi = 0; mi < 2; mi++)
                #pragma unroll
                for (int ks = 0; ks < 2; ks++) {
                    const unsigned base = a_s + (unsigned)((mi*16*lda + kt*32 + ks*16)*2);
                    ldm_x4(ah[mi][ks][0], ah[mi][ks][1], ah[mi][ks][2], ah[mi][ks][3], base);
                    ldm_x4(al[mi][ks][0], al[mi][ks][1], al[mi][ks][2], al[mi][ks][3],
                           base + (unsigned)(KA*2));
                }
            // ---- step p=0: consume b0, then refill b0 for step 2kt+2 ----
            #pragma unroll
            for (int mi = 0; mi < 2; mi++) {
                mma16816(acc[0][mi][0], ah[mi][0], b0[0].x, b0[0].y);
                mma16816(acc[0][mi][1], ah[mi][0], b0[2].x, b0[2].y);
                mma16816(acc[0][mi][0], ah[mi][1], b0[0].z, b0[0].w);
                mma16816(acc[0][mi][1], ah[mi][1], b0[2].z, b0[2].w);
                mma16816(acc[0][mi][0], ah[mi][0], b0[1].x, b0[1].y);
                mma16816(acc[0][mi][1], ah[mi][0], b0[3].x, b0[3].y);
                mma16816(acc[0][mi][0], ah[mi][1], b0[1].z, b0[1].w);
                mma16816(acc[0][mi][1], ah[mi][1], b0[3].z, b0[3].w);
                mma16816(acc[0][mi][0], al[mi][0], b0[0].x, b0[0].y);
                mma16816(acc[0][mi][1], al[mi][0], b0[2].x, b0[2].y);
                mma16816(acc[0][mi][0], al[mi][1], b0[0].z, b0[0].w);
                mma16816(acc[0][mi][1], al[mi][1], b0[2].z, b0[2].w);
            }
            if (kt + 1 < T) LDB(2*kt + 2, b0);
            // ---- step p=1: consume b1, then refill b1 for step 2kt+3 ----
            #pragma unroll
            for (int mi = 0; mi < 2; mi++) {
                mma16816(acc[1][mi][0], ah[mi][0], b1[0].x, b1[0].y);
                mma16816(acc[1][mi][1], ah[mi][0], b1[2].x, b1[2].y);
                mma16816(acc[1][mi][0], ah[mi][1], b1[0].z, b1[0].w);
                mma16816(acc[1][mi][1], ah[mi][1], b1[2].z, b1[2].w);
                mma16816(acc[1][mi][0], ah[mi][0], b1[1].x, b1[1].y);
                mma16816(acc[1][mi][1], ah[mi][0], b1[3].x, b1[3].y);
                mma16816(acc[1][mi][0], ah[mi][1], b1[1].z, b1[1].w);
                mma16816(acc[1][mi][1], ah[mi][1], b1[3].z, b1[3].w);
                mma16816(acc[1][mi][0], al[mi][0], b1[0].x, b1[0].y);
                mma16816(acc[1][mi][1], al[mi][0], b1[2].x, b1[2].y);
                mma16816(acc[1][mi][0], al[mi][1], b1[0].z, b1[0].w);
                mma16816(acc[1][mi][1], al[mi][1], b1[2].z, b1[2].w);
            }
            if (kt + 1 < T) LDB(2*kt + 3, b1);
        }
        #undef LDB
        // epilogue
        #pragma unroll
        for (int p = 0; p < 2; p++)
            #pragma unroll
            for (int mi = 0; mi < 2; mi++)
                #pragma unroll
                for (int j = 0; j < 2; j++) {
                    const int c = (blk*2 + p)*128 + wid*16 + j*8 + 2*(lane & 3);
                    const float bb0 = bias[c], bb1 = bias[c+1];
                    #pragma unroll
                    for (int rr = 0; rr < 2; rr++) {
                        const int r = mi*16 + (lane >> 2) + rr*8;
                        float v0 = acc[p][mi][j][rr*2+0] + bb0;
                        float v1 = acc[p][mi][j][rr*2+1] + bb1;
                        if (MODE == 0) {
                            BUFf[r*LDQ + c]   = v0;
                            BUFf[r*LDQ + c+1] = v1;
                        } else if (MODE == 2) {
                            Xd[r*H_ + c]   += v0;
                            Xd[r*H_ + c+1] += v1;
                        } else {
                            v0 = fmaxf(v0, 0.f); v1 = fmaxf(v1, 0.f);
                            __nv_bfloat16 h0, l0, h1, l1;
                            hilo(v0, h0, l0); hilo(v1, h1, l1);
                            __nv_bfloat16* d = BUF2 + r*LDB2;
                            d[c] = h0;       d[c+1] = h1;
                            d[512 + c] = l0; d[512 + c+1] = l1;
                        }
                    }
                }
    }
}

// ---------------------------------------------------------------------------
// LayerNorm over 32 rows. OM 0: fp32 dst (ld H_); OM 1: hi/lo bf16 (ld LDA2)
// ---------------------------------------------------------------------------
template<int OM>
__device__ __forceinline__ void ln32(const float* src, void* dstv,
                                     const float* __restrict__ g,
                                     const float* __restrict__ b, int tid)
{
    const int w = tid >> 5, lane = tid & 31;
    #pragma unroll
    for (int j = 0; j < 4; j++) {
        const int r = w*4 + j;
        float sum = 0.f, sq = 0.f;
        #pragma unroll
        for (int i = 0; i < 8; i++) {
            const float v = src[r*H_ + lane + i*32];
            sum += v; sq = fmaf(v, v, sq);
        }
        #pragma unroll
        for (int o = 16; o > 0; o >>= 1) {
            sum += __shfl_xor_sync(0xffffffffu, sum, o);
            sq  += __shfl_xor_sync(0xffffffffu, sq,  o);
        }
        const float mu   = sum * (1.f/H_);
        const float var  = sq * (1.f/H_) - mu*mu;
        const float rstd = rsqrtf(var + 1e-5f);
        #pragma unroll
        for (int i = 0; i < 8; i++) {
            const int c = lane + i*32;
            const float y = fmaf((src[r*H_ + c] - mu)*rstd, g[c], b[c]);
            if (OM == 0) {
                ((float*)dstv)[r*H_ + c] = y;
            } else {
                __nv_bfloat16 hi, lo; hilo(y, hi, lo);
                __nv_bfloat16* d = (__nv_bfloat16*)dstv + r*LDA2;
                d[c] = hi; d[256 + c] = lo;
            }
        }
    }
}

// ---------------------------------------------------------------------------
// Attention: warp = head, lane = query row. qkv fp32 in BUFf (ld LDQ);
// output written as hi/lo bf16 into XN2.
// ---------------------------------------------------------------------------
__device__ __forceinline__ void attn32(const float* BUFf, const __nv_bfloat16* BS,
                                       const float* KM, __nv_bfloat16* XN2, int tid)
{
    const int head = tid >> 5, lane = tid & 31;
    const float scale = 0.17677669529663687f;  // 1/sqrt(32)

    float4 q4[8];
    const float4* qp = (const float4*)(BUFf + lane*LDQ + head*32);
    #pragma unroll
    for (int j = 0; j < 8; j++) q4[j] = qp[j];

    float sc[32];
    float m = -3.0e38f;
    #pragma unroll
    for (int kr = 0; kr < 32; kr++) {
        const float4* kp = (const float4*)(BUFf + kr*LDQ + 256 + head*32);
        float s = 0.f;
        #pragma unroll
        for (int j = 0; j < 8; j++) {
            const float4 kk = kp[j];
            s = fmaf(q4[j].x, kk.x, s); s = fmaf(q4[j].y, kk.y, s);
            s = fmaf(q4[j].z, kk.z, s); s = fmaf(q4[j].w, kk.w, s);
        }
        const float bv = __bfloat162float(BS[head*1024 + kr*32 + lane]);
        s = fmaf(s, scale, bv) + KM[kr];
        sc[kr] = s;
        m = fmaxf(m, s);
    }
    float den = 0.f;
    #pragma unroll
    for (int kr = 0; kr < 32; kr++) { const float e = __expf(sc[kr] - m); sc[kr] = e; den += e; }
    const float inv = 1.f / den;
    #pragma unroll
    for (int kr = 0; kr < 32; kr++) sc[kr] *= inv;

    #pragma unroll
    for (int dg = 0; dg < 8; dg++) {
        float4 acc = make_float4(0.f, 0.f, 0.f, 0.f);
        #pragma unroll
        for (int kr = 0; kr < 32; kr++) {
            const float4 v4 = *(const float4*)(BUFf + kr*LDQ + 512 + head*32 + dg*4);
            const float w = sc[kr];
            acc.x = fmaf(w, v4.x, acc.x); acc.y = fmaf(w, v4.y, acc.y);
            acc.z = fmaf(w, v4.z, acc.z); acc.w = fmaf(w, v4.w, acc.w);
        }
        const float av[4] = {acc.x, acc.y, acc.z, acc.w};
        __nv_bfloat16* d = XN2 + lane*LDA2;
        #pragma unroll
        for (int e = 0; e < 4; e++) {
            const int c = head*32 + dg*4 + e;
            __nv_bfloat16 hi, lo; hilo(av[e], hi, lo);
            d[c] = hi; d[256 + c] = lo;
        }
    }
}

// ---------------------------------------------------------------------------
__global__ __launch_bounds__(256, 1) void xf_kernel(
    const float* __restrict__ h, const void* __restrict__ validp,
    const float* __restrict__ ln1g, const float* __restrict__ ln1b,
    const float* __restrict__ qkvb, const float* __restrict__ outb,
    const float* __restrict__ ln2g, const float* __restrict__ ln2b,
    const float* __restrict__ ff1b, const float* __restrict__ ff2b,
    const float* __restrict__ fng, const float* __restrict__ fnb,
    float* __restrict__ out)
{
    extern __shared__ float sm[];
    float* X    = sm + OFF_X;
    float* BUFf = sm + OFF_BUF;
    __nv_bfloat16* BUF2 = (__nv_bfloat16*)(sm + OFF_BUF);
    __nv_bfloat16* XN2  = (__nv_bfloat16*)(sm + OFF_XN2);
    __nv_bfloat16* BS   = (__nv_bfloat16*)(sm + OFF_BS);
    float* KM  = sm + OFF_KM;
    float* V01 = sm + OFF_V01;
    const int s = blockIdx.x, tid = threadIdx.x;

    // Detect 'valid' encoding: byte bools vs 32-bit words.
    const unsigned char* vb = (const unsigned char*)validp;
    bool bytemode = false;
    #pragma unroll
    for (int i = 1; i < 128; i += 4) bytemode |= (vb[i] != 0);

    if (tid < K_) {
        bool v;
        if (bytemode) v = vb[s*K_ + tid] != 0;
        else          v = ((const unsigned int*)validp)[s*K_ + tid] != 0u;
        KM[tid]  = v ? 0.f : -1e30f;
        V01[tid] = v ? 1.f : 0.f;
    }
    for (int i = tid; i < K_*H_/4; i += 256)
        ((float4*)X)[i] = ((const float4*)(h + (size_t)s*K_*H_))[i];
    {
        const uint4* gb = (const uint4*)(g_bias16 + (size_t)s*NH_*K_*K_);
        uint4* sb = (uint4*)BS;
        for (int i = tid; i < 1024; i += 256) sb[i] = gb[i];
    }
    __syncthreads();

    for (int l = 0; l < L_; l++) {
        ln32<1>(X, XN2, ln1g + l*H_, ln1b + l*H_, tid);
        __syncthreads();
        mm3<768, 256, 0>(XN2, LDA2, (const uint4*)(g_w2_qkv + (size_t)l*768*256),
                         qkvb + l*768, X, BUFf, BUF2, tid);
        __syncthreads();
        attn32(BUFf, BS, KM, XN2, tid);
        __syncthreads();
        mm3<256, 256, 2>(XN2, LDA2, (const uint4*)(g_w2_out + (size_t)l*256*256),
                         outb + l*H_, X, BUFf, BUF2, tid);
        __syncthreads();
        ln32<1>(X, XN2, ln2g + l*H_, ln2b + l*H_, tid);
        __syncthreads();
        mm3<512, 256, 1>(XN2, LDA2, (const uint4*)(g_w2_ff1 + (size_t)l*512*256),
                         ff1b + l*FFN_, X, BUFf, BUF2, tid);
        __syncthreads();
        mm3<256, 512, 2>(BUF2, LDB2, (const uint4*)(g_w2_ff2 + (size_t)l*256*512),
                         ff2b + l*H_, X, BUFf, BUF2, tid);
        __syncthreads();
    }

    // final LN (fp32 into BUFf region, ld H_) + masked mean over k
    ln32<0>(X, BUFf, fng, fnb, tid);
    __syncthreads();
    float sum = 0.f, cnt = 0.f;
    #pragma unroll
    for (int r = 0; r < K_; r++) {
        sum = fmaf(BUFf[r*H_ + tid], V01[r], sum);
        cnt += V01[r];
    }
    out[(size_t)s*H_ + tid] = sum / fmaxf(cnt, 1.f);
}

// ---------------------------------------------------------------------------
extern "C" void kernel_launch(void* const* d_in, const int* in_sizes, int n_in,
                              void* d_out, int out_size)
{
    // inputs: 0 h, 1 valid, 2 edge_index, 3 ea_flat, 4 edge_ptr, 5 S, 6 k,
    // 7 edge_W, 8 edge_b, 9 ln1_g, 10 ln1_b, 11 qkv_W, 12 qkv_b, 13 out_W,
    // 14 out_b, 15 ln2_g, 16 ln2_b, 17 ff1_W, 18 ff1_b, 19 ff2_W, 20 ff2_b,
    // 21 fnorm_g, 22 fnorm_b
    cudaFuncSetAttribute(xf_kernel, cudaFuncAttributeMaxDynamicSharedMemorySize,
                         SMEM_FLOATS * (int)sizeof(float));

    unsigned *w2_qkv, *w2_out, *w2_ff1, *w2_ff2;
    cudaGetSymbolAddress((void**)&w2_qkv, g_w2_qkv);
    cudaGetSymbolAddress((void**)&w2_out, g_w2_out);
    cudaGetSymbolAddress((void**)&w2_ff1, g_w2_ff1);
    cudaGetSymbolAddress((void**)&w2_ff2, g_w2_ff2);

    // total_units = L * N*KA/4 per gemm
    wconv_frag<<<(L_*768*256/4 + 255)/256, 256>>>(
        (const float*)d_in[11], (uint4*)w2_qkv, 768, 256, L_*768*256/4);
    wconv_frag<<<(L_*256*256/4 + 255)/256, 256>>>(
        (const float*)d_in[13], (uint4*)w2_out, 256, 256, L_*256*256/4);
    wconv_frag<<<(L_*512*256/4 + 255)/256, 256>>>(
        (const float*)d_in[17], (uint4*)w2_ff1, 512, 256, L_*512*256/4);
    wconv_frag<<<(L_*256*512/4 + 255)/256, 256>>>(
        (const float*)d_in[19], (uint4*)w2_ff2, 256, 512, L_*256*512/4);

    edge_bias_kernel<<<S_, 256>>>(
        (const float*)d_in[3], (const int*)d_in[2],
        (const float*)d_in[7], (const float*)d_in[8]);

    xf_kernel<<<S_, 256, SMEM_FLOATS * sizeof(float)>>>(
        (const float*)d_in[0], d_in[1],
        (const float*)d_in[9],  (const float*)d_in[10],
        (const float*)d_in[12], (const float*)d_in[14],
        (const float*)d_in[15], (const float*)d_in[16],
        (const float*)d_in[18], (const float*)d_in[20],
        (const float*)d_in[21], (const float*)d_in[22],
        (float*)d_out);
}

// round 11
// speedup vs baseline: 3.1887x; 1.0002x over previous
#include <cuda_runtime.h>
#include <cuda_bf16.h>
#include <math.h>

// Problem constants (LocalSubgraphTransformer)
#define S_   2048
#define K_   32
#define H_   256
#define NH_  8
#define DH_  32
#define L_   4
#define ED_  16
#define FFN_ 512
#define EPS_ 64
#define E_   (S_*EPS_)

#define LDA2 520    // XN2 row stride (bf16): hi 256 | lo 256 | pad 8
#define LDB2 1032   // BUF2 row stride (bf16): hi 512 | lo 512 | pad 8
#define LDQ  772    // qkv fp32 row stride

// ---------------- device scratch ----------------
__device__ __nv_bfloat16 g_bias16[(size_t)S_ * NH_ * K_ * K_];   // [S][h][k][q]
// weights in mma B-fragment order, hi/lo: N*2*KA bf16 each
__device__ unsigned g_w2_qkv[(size_t)L_ * 768 * 256];   // u32 words = N*2KA/2
__device__ unsigned g_w2_out[(size_t)L_ * 256 * 256];
__device__ unsigned g_w2_ff1[(size_t)L_ * 512 * 256];
__device__ unsigned g_w2_ff2[(size_t)L_ * 256 * 512];

// ---------------------------------------------------------------------------
// Weight conversion: fp32 [L][N][KA] row-major -> B-fragment layout.
// Unit (16 B = 4 words) uid = ((((pass*T + kt)*8 + ng)*2 + j)*2 + hl)*32 + lane
//   n = pass*128 + ng*16 + j*8 + (lane>>2)
//   word w: k = kt*32 + (w>>1)*16 + (lane&3)*2 + (w&1)*8, covers {k, k+1}
//   hl=0: hi part, hl=1: lo residual
// ---------------------------------------------------------------------------
__global__ void wconv_frag(const float* __restrict__ src, uint4* __restrict__ dst,
                           int N, int KA, int total_units)
{
    const int e = blockIdx.x*256 + threadIdx.x;
    if (e >= total_units) return;
    const int UPL = N*KA/4;            // units per layer
    const int l = e / UPL;
    int u = e - l*UPL;
    const int lane = u & 31; u >>= 5;
    const int hl = u & 1; u >>= 1;
    const int j = u & 1; u >>= 1;
    const int ng = u & 7; u >>= 3;
    const int T = KA/32;
    const int kt = u % T;
    const int pass = u / T;
    const int n = pass*128 + ng*16 + j*8 + (lane>>2);
    const float* sp = src + ((size_t)l*N + n)*KA;

    unsigned words[4];
    #pragma unroll
    for (int w = 0; w < 4; w++) {
        const int k = kt*32 + (w>>1)*16 + (lane&3)*2 + (w&1)*8;
        const float f0 = sp[k], f1 = sp[k+1];
        __nv_bfloat16 v0, v1;
        if (hl == 0) { v0 = __float2bfloat16(f0); v1 = __float2bfloat16(f1); }
        else {
            const __nv_bfloat16 h0 = __float2bfloat16(f0), h1 = __float2bfloat16(f1);
            v0 = __float2bfloat16(f0 - __bfloat162float(h0));
            v1 = __float2bfloat16(f1 - __bfloat162float(h1));
        }
        unsigned lo16 = (unsigned)*(unsigned short*)&v0;
        unsigned hi16 = (unsigned)*(unsigned short*)&v1;
        words[w] = lo16 | (hi16 << 16);
    }
    dst[e] = make_uint4(words[0], words[1], words[2], words[3]);
}

// ---------------------------------------------------------------------------
// Kernel A: per-subgraph edge bias via shared-memory scatter-add
// ---------------------------------------------------------------------------
__global__ __launch_bounds__(256) void edge_bias_kernel(
    const float* __restrict__ ea, const int* __restrict__ eidx,
    const float* __restrict__ eW, const float* __restrict__ eb)
{
    __shared__ float sb[NH_*K_*K_];   // [h][dst=k][src=q]
    __shared__ float sa[EPS_*ED_];
    __shared__ float sw[NH_*ED_];
    __shared__ float sbv[NH_];
    const int s = blockIdx.x, tid = threadIdx.x;

    if (tid < NH_*ED_) sw[tid] = eW[tid];
    if (tid < NH_)     sbv[tid] = eb[tid];
    for (int i = tid; i < EPS_*ED_;  i += 256) sa[i] = ea[(size_t)s*EPS_*ED_ + i];
    for (int i = tid; i < NH_*K_*K_; i += 256) sb[i] = 0.f;
    __syncthreads();

    for (int t = tid; t < EPS_*NH_; t += 256) {
        const int i  = t >> 3;
        const int hh = t & 7;
        float p = sbv[hh];
        #pragma unroll
        for (int d = 0; d < ED_; d++) p = fmaf(sa[i*ED_+d], sw[hh*ED_+d], p);
        const int e  = s*EPS_ + i;
        const int sr = eidx[e];        // src = query index
        const int ds = eidx[E_ + e];   // dst = key index
        atomicAdd(&sb[hh*K_*K_ + ds*K_ + sr], p);
    }
    __syncthreads();
    for (int i = tid; i < NH_*K_*K_; i += 256)
        g_bias16[(size_t)s*NH_*K_*K_ + i] = __float2bfloat16(sb[i]);
}

// ---------------------------------------------------------------------------
// smem layout (float offsets)
// ---------------------------------------------------------------------------
#define OFF_X    0        /* 8192 f: X fp32 [32][256] */
#define OFF_BUF  8192     /* 24704 f: union { fp32 [32][772] qkv ; bf16 [32][1032] ffn2 } */
#define OFF_XN2  32896    /* 8320 f: bf16 [32][520] */
#define OFF_BS   41216    /* 4096 f: bf16 [8][32][32] */
#define OFF_KM   45312
#define OFF_V01  45344
#define SMEM_FLOATS 45376  /* 181504 bytes */

__device__ __forceinline__ unsigned sptr(const void* p) {
    return (unsigned)__cvta_generic_to_shared(p);
}
__device__ __forceinline__ void ldm_x4(unsigned& a0, unsigned& a1, unsigned& a2,
                                       unsigned& a3, unsigned addr) {
    asm volatile("ldmatrix.sync.aligned.m8n8.x4.shared.b16 {%0,%1,%2,%3},[%4];"
                 : "=r"(a0), "=r"(a1), "=r"(a2), "=r"(a3) : "r"(addr));
}
__device__ __forceinline__ void mma16816(float* c, const unsigned* a,
                                         unsigned b0, unsigned b1) {
    asm volatile("mma.sync.aligned.m16n8k16.row.col.f32.bf16.bf16.f32 "
                 "{%0,%1,%2,%3},{%4,%5,%6,%7},{%8,%9},{%0,%1,%2,%3};"
                 : "+f"(c[0]), "+f"(c[1]), "+f"(c[2]), "+f"(c[3])
                 : "r"(a[0]), "r"(a[1]), "r"(a[2]), "r"(a[3]), "r"(b0), "r"(b1));
}
__device__ __forceinline__ void hilo(float v, __nv_bfloat16& hi, __nv_bfloat16& lo) {
    hi = __float2bfloat16(v);
    lo = __float2bfloat16(v - __bfloat162float(hi));
}

// ---------------------------------------------------------------------------
// Tensor-core GEMM, hi/lo split, B via direct LDG from fragment-layout weights,
// with register double-buffered B prefetch (lookahead ~1.5 steps).
// C = A_hi W_hi^T + A_hi W_lo^T + A_lo W_hi^T + bias
// A: smem bf16 [32][hi KA | lo KA] (ld lda). Warp tile m32 x n16.
// Passes processed in pairs (n256 blocks); steps = (kt, p), p parity static.
// MODE 0: fp32 -> BUFf (ld LDQ); 1: relu -> hi/lo BUF2; 2: += X (ld H_)
// ---------------------------------------------------------------------------
template<int N, int KA, int MODE>
__device__ __forceinline__ void mm3(const __nv_bfloat16* A, int lda,
    const uint4* __restrict__ Wf, const float* __restrict__ bias,
    float* Xd, float* BUFf, __nv_bfloat16* BUF2, int tid)
{
    const int lane = tid & 31, wid = tid >> 5;
    constexpr int T = KA/32;          // k32 stages
    constexpr int NB = N/256;         // pass-pair blocks
    // A ldmatrix base: row = lane&15, 16B col = (lane>>4)
    const unsigned a_s = sptr(A) + (unsigned)(((lane & 15)*lda + ((lane >> 4) << 3))*2);

    for (int blk = 0; blk < NB; blk++) {
        float acc[2][2][2][4];   // [p][mi][j][4]
        #pragma unroll
        for (int p = 0; p < 2; p++)
            #pragma unroll
            for (int mi = 0; mi < 2; mi++)
                #pragma unroll
                for (int j = 0; j < 2; j++)
                    #pragma unroll
                    for (int i = 0; i < 4; i++) acc[p][mi][j][i] = 0.f;

        // B fragment loader: step = 2*kt + p; buf[0]=j0 hi, [1]=j0 lo, [2]=j1 hi, [3]=j1 lo
        #define LDB(step, buf) do {                                                   \
            const int _p = (step) & 1, _kt = (step) >> 1;                             \
            const size_t _b = ((size_t)(((blk*2 + _p)*T + _kt)*8 + wid)*4)*32 + lane; \
            (buf)[0] = Wf[_b];       (buf)[1] = Wf[_b + 32];                          \
            (buf)[2] = Wf[_b + 64];  (buf)[3] = Wf[_b + 96];                          \
        } while (0)

        uint4 b0[4], b1[4];
        LDB(0, b0);
        LDB(1, b1);

        for (int kt = 0; kt < T; kt++) {
            // A fragments for this kt: [mi][ks] hi and lo (8 x ldmatrix.x4)
            unsigned ah[2][2][4], al[2][2][4];
            #pragma unroll
            for (int mi = 0; mi < 2; mi++)
                #pragma unroll
                for (int ks = 0; ks < 2; ks++) {
                    const unsigned base = a_s + (unsigned)((mi*16*lda + kt*32 + ks*16)*2);
                    ldm_x4(ah[mi][ks][0], ah[mi][ks][1], ah[mi][ks][2], ah[mi][ks][3], base);
                    ldm_x4(al[mi][ks][0], al[mi][ks][1], al[mi][ks][2], al[mi][ks][3],
                           base + (unsigned)(KA*2));
                }
            // ---- step p=0: consume b0, then refill b0 for step 2kt+2 ----
            #pragma unroll
            for (int mi = 0; mi < 2; mi++) {
                mma16816(acc[0][mi][0], ah[mi][0], b0[0].x, b0[0].y);
                mma16816(acc[0][mi][1], ah[mi][0], b0[2].x, b0[2].y);
                mma16816(acc[0][mi][0], ah[mi][1], b0[0].z, b0[0].w);
                mma16816(acc[0][mi][1], ah[mi][1], b0[2].z, b0[2].w);
                mma16816(acc[0][mi][0], ah[mi][0], b0[1].x, b0[1].y);
                mma16816(acc[0][mi][1], ah[mi][0], b0[3].x, b0[3].y);
                mma16816(acc[0][mi][0], ah[mi][1], b0[1].z, b0[1].w);
                mma16816(acc[0][mi][1], ah[mi][1], b0[3].z, b0[3].w);
                mma16816(acc[0][mi][0], al[mi][0], b0[0].x, b0[0].y);
                mma16816(acc[0][mi][1], al[mi][0], b0[2].x, b0[2].y);
                mma16816(acc[0][mi][0], al[mi][1], b0[0].z, b0[0].w);
                mma16816(acc[0][mi][1], al[mi][1], b0[2].z, b0[2].w);
            }
            if (kt + 1 < T) LDB(2*kt + 2, b0);
            // ---- step p=1: consume b1, then refill b1 for step 2kt+3 ----
            #pragma unroll
            for (int mi = 0; mi < 2; mi++) {
                mma16816(acc[1][mi][0], ah[mi][0], b1[0].x, b1[0].y);
                mma16816(acc[1][mi][1], ah[mi][0], b1[2].x, b1[2].y);
                mma16816(acc[1][mi][0], ah[mi][1], b1[0].z, b1[0].w);
                mma16816(acc[1][mi][1], ah[mi][1], b1[2].z, b1[2].w);
                mma16816(acc[1][mi][0], ah[mi][0], b1[1].x, b1[1].y);
                mma16816(acc[1][mi][1], ah[mi][0], b1[3].x, b1[3].y);
                mma16816(acc[1][mi][0], ah[mi][1], b1[1].z, b1[1].w);
                mma16816(acc[1][mi][1], ah[mi][1], b1[3].z, b1[3].w);
                mma16816(acc[1][mi][0], al[mi][0], b1[0].x, b1[0].y);
                mma16816(acc[1][mi][1], al[mi][0], b1[2].x, b1[2].y);
                mma16816(acc[1][mi][0], al[mi][1], b1[0].z, b1[0].w);
                mma16816(acc[1][mi][1], al[mi][1], b1[2].z, b1[2].w);
            }
            if (kt + 1 < T) LDB(2*kt + 3, b1);
        }
        #undef LDB
        // epilogue
        #pragma unroll
        for (int p = 0; p < 2; p++)
            #pragma unroll
            for (int mi = 0; mi < 2; mi++)
                #pragma unroll
                for (int j = 0; j < 2; j++) {
                    const int c = (blk*2 + p)*128 + wid*16 + j*8 + 2*(lane & 3);
                    const float bb0 = bias[c], bb1 = bias[c+1];
                    #pragma unroll
                    for (int rr = 0; rr < 2; rr++) {
                        const int r = mi*16 + (lane >> 2) + rr*8;
                        float v0 = acc[p][mi][j][rr*2+0] + bb0;
                        float v1 = acc[p][mi][j][rr*2+1] + bb1;
                        if (MODE == 0) {
                            BUFf[r*LDQ + c]   = v0;
                            BUFf[r*LDQ + c+1] = v1;
                        } else if (MODE == 2) {
                            Xd[r*H_ + c]   += v0;
                            Xd[r*H_ + c+1] += v1;
                        } else {
                            v0 = fmaxf(v0, 0.f); v1 = fmaxf(v1, 0.f);
                            __nv_bfloat16 h0, l0, h1, l1;
                            hilo(v0, h0, l0); hilo(v1, h1, l1);
                            __nv_bfloat16* d = BUF2 + r*LDB2;
                            d[c] = h0;       d[c+1] = h1;
                            d[512 + c] = l0; d[512 + c+1] = l1;
                        }
                    }
                }
    }
}

// ---------------------------------------------------------------------------
// LayerNorm over 32 rows. OM 0: fp32 dst (ld H_); OM 1: hi/lo bf16 (ld LDA2)
// ---------------------------------------------------------------------------
template<int OM>
__device__ __forceinline__ void ln32(const float* src, void* dstv,
                                     const float* __restrict__ g,
                                     const float* __restrict__ b, int tid)
{
    const int w = tid >> 5, lane = tid & 31;
    #pragma unroll
    for (int j = 0; j < 4; j++) {
        const int r = w*4 + j;
        float sum = 0.f, sq = 0.f;
        #pragma unroll
        for (int i = 0; i < 8; i++) {
            const float v = src[r*H_ + lane + i*32];
            sum += v; sq = fmaf(v, v, sq);
        }
        #pragma unroll
        for (int o = 16; o > 0; o >>= 1) {
            sum += __shfl_xor_sync(0xffffffffu, sum, o);
            sq  += __shfl_xor_sync(0xffffffffu, sq,  o);
        }
        const float mu   = sum * (1.f/H_);
        const float var  = sq * (1.f/H_) - mu*mu;
        const float rstd = rsqrtf(var + 1e-5f);
        #pragma unroll
        for (int i = 0; i < 8; i++) {
            const int c = lane + i*32;
            const float y = fmaf((src[r*H_ + c] - mu)*rstd, g[c], b[c]);
            if (OM == 0) {
                ((float*)dstv)[r*H_ + c] = y;
            } else {
                __nv_bfloat16 hi, lo; hilo(y, hi, lo);
                __nv_bfloat16* d = (__nv_bfloat16*)dstv + r*LDA2;
                d[c] = hi; d[256 + c] = lo;
            }
        }
    }
}

// ---------------------------------------------------------------------------
// Attention: warp = head, lane = query row. qkv fp32 in BUFf (ld LDQ);
// output written as hi/lo bf16 into XN2.
// ---------------------------------------------------------------------------
__device__ __forceinline__ void attn32(const float* BUFf, const __nv_bfloat16* BS,
                                       const float* KM, __nv_bfloat16* XN2, int tid)
{
    const int head = tid >> 5, lane = tid & 31;
    const float scale = 0.17677669529663687f;  // 1/sqrt(32)

    float4 q4[8];
    const float4* qp = (const float4*)(BUFf + lane*LDQ + head*32);
    #pragma unroll
    for (int j = 0; j < 8; j++) q4[j] = qp[j];

    float sc[32];
    float m = -3.0e38f;
    #pragma unroll
    for (int kr = 0; kr < 32; kr++) {
        const float4* kp = (const float4*)(BUFf + kr*LDQ + 256 + head*32);
        float s = 0.f;
        #pragma unroll
        for (int j = 0; j < 8; j++) {
            const float4 kk = kp[j];
            s = fmaf(q4[j].x, kk.x, s); s = fmaf(q4[j].y, kk.y, s);
            s = fmaf(q4[j].z, kk.z, s); s = fmaf(q4[j].w, kk.w, s);
        }
        const float bv = __bfloat162float(BS[head*1024 + kr*32 + lane]);
        s = fmaf(s, scale, bv) + KM[kr];
        sc[kr] = s;
        m = fmaxf(m, s);
    }
    float den = 0.f;
    #pragma unroll
    for (int kr = 0; kr < 32; kr++) { const float e = __expf(sc[kr] - m); sc[kr] = e; den += e; }
    const float inv = 1.f / den;
    #pragma unroll
    for (int kr = 0; kr < 32; kr++) sc[kr] *= inv;

    #pragma unroll
    for (int dg = 0; dg < 8; dg++) {
        float4 acc = make_float4(0.f, 0.f, 0.f, 0.f);
        #pragma unroll
        for (int kr = 0; kr < 32; kr++) {
            const float4 v4 = *(const float4*)(BUFf + kr*LDQ + 512 + head*32 + dg*4);
            const float w = sc[kr];
            acc.x = fmaf(w, v4.x, acc.x); acc.y = fmaf(w, v4.y, acc.y);
            acc.z = fmaf(w, v4.z, acc.z); acc.w = fmaf(w, v4.w, acc.w);
        }
        const float av[4] = {acc.x, acc.y, acc.z, acc.w};
        __nv_bfloat16* d = XN2 + lane*LDA2;
        #pragma unroll
        for (int e = 0; e < 4; e++) {
            const int c = head*32 + dg*4 + e;
            __nv_bfloat16 hi, lo; hilo(av[e], hi, lo);
            d[c] = hi; d[256 + c] = lo;
        }
    }
}

// ---------------------------------------------------------------------------
__global__ __launch_bounds__(256, 1) void xf_kernel(
    const float* __restrict__ h, const void* __restrict__ validp,
    const float* __restrict__ ln1g, const float* __restrict__ ln1b,
    const float* __restrict__ qkvb, const float* __restrict__ outb,
    const float* __restrict__ ln2g, const float* __restrict__ ln2b,
    const float* __restrict__ ff1b, const float* __restrict__ ff2b,
    const float* __restrict__ fng, const float* __restrict__ fnb,
    float* __restrict__ out)
{
    extern __shared__ float sm[];
    float* X    = sm + OFF_X;
    float* BUFf = sm + OFF_BUF;
    __nv_bfloat16* BUF2 = (__nv_bfloat16*)(sm + OFF_BUF);
    __nv_bfloat16* XN2  = (__nv_bfloat16*)(sm + OFF_XN2);
    __nv_bfloat16* BS   = (__nv_bfloat16*)(sm + OFF_BS);
    float* KM  = sm + OFF_KM;
    float* V01 = sm + OFF_V01;
    const int s = blockIdx.x, tid = threadIdx.x;

    // Detect 'valid' encoding: byte bools vs 32-bit words.
    const unsigned char* vb = (const unsigned char*)validp;
    bool bytemode = false;
    #pragma unroll
    for (int i = 1; i < 128; i += 4) bytemode |= (vb[i] != 0);

    if (tid < K_) {
        bool v;
        if (bytemode) v = vb[s*K_ + tid] != 0;
        else          v = ((const unsigned int*)validp)[s*K_ + tid] != 0u;
        KM[tid]  = v ? 0.f : -1e30f;
        V01[tid] = v ? 1.f : 0.f;
    }
    for (int i = tid; i < K_*H_/4; i += 256)
        ((float4*)X)[i] = ((const float4*)(h + (size_t)s*K_*H_))[i];
    {
        const uint4* gb = (const uint4*)(g_bias16 + (size_t)s*NH_*K_*K_);
        uint4* sb = (uint4*)BS;
        for (int i = tid; i < 1024; i += 256) sb[i] = gb[i];
    }
    __syncthreads();

    for (int l = 0; l < L_; l++) {
        ln32<1>(X, XN2, ln1g + l*H_, ln1b + l*H_, tid);
        __syncthreads();
        mm3<768, 256, 0>(XN2, LDA2, (const uint4*)(g_w2_qkv + (size_t)l*768*256),
                         qkvb + l*768, X, BUFf, BUF2, tid);
        __syncthreads();
        attn32(BUFf, BS, KM, XN2, tid);
        __syncthreads();
        mm3<256, 256, 2>(XN2, LDA2, (const uint4*)(g_w2_out + (size_t)l*256*256),
                         outb + l*H_, X, BUFf, BUF2, tid);
        __syncthreads();
        ln32<1>(X, XN2, ln2g + l*H_, ln2b + l*H_, tid);
        __syncthreads();
        mm3<512, 256, 1>(XN2, LDA2, (const uint4*)(g_w2_ff1 + (size_t)l*512*256),
                         ff1b + l*FFN_, X, BUFf, BUF2, tid);
        __syncthreads();
        mm3<256, 512, 2>(BUF2, LDB2, (const uint4*)(g_w2_ff2 + (size_t)l*256*512),
                         ff2b + l*H_, X, BUFf, BUF2, tid);
        __syncthreads();
    }

    // final LN (fp32 into BUFf region, ld H_) + masked mean over k
    ln32<0>(X, BUFf, fng, fnb, tid);
    __syncthreads();
    float sum = 0.f, cnt = 0.f;
    #pragma unroll
    for (int r = 0; r < K_; r++) {
        sum = fmaf(BUFf[r*H_ + tid], V01[r], sum);
        cnt += V01[r];
    }
    out[(size_t)s*H_ + tid] = sum / fmaxf(cnt, 1.f);
}

// ---------------------------------------------------------------------------
extern "C" void kernel_launch(void* const* d_in, const int* in_sizes, int n_in,
                              void* d_out, int out_size)
{
    // inputs: 0 h, 1 valid, 2 edge_index, 3 ea_flat, 4 edge_ptr, 5 S, 6 k,
    // 7 edge_W, 8 edge_b, 9 ln1_g, 10 ln1_b, 11 qkv_W, 12 qkv_b, 13 out_W,
    // 14 out_b, 15 ln2_g, 16 ln2_b, 17 ff1_W, 18 ff1_b, 19 ff2_W, 20 ff2_b,
    // 21 fnorm_g, 22 fnorm_b
    cudaFuncSetAttribute(xf_kernel, cudaFuncAttributeMaxDynamicSharedMemorySize,
                         SMEM_FLOATS * (int)sizeof(float));

    unsigned *w2_qkv, *w2_out, *w2_ff1, *w2_ff2;
    cudaGetSymbolAddress((void**)&w2_qkv, g_w2_qkv);
    cudaGetSymbolAddress((void**)&w2_out, g_w2_out);
    cudaGetSymbolAddress((void**)&w2_ff1, g_w2_ff1);
    cudaGetSymbolAddress((void**)&w2_ff2, g_w2_ff2);

    // total_units = L * N*KA/4 per gemm
    wconv_frag<<<(L_*768*256/4 + 255)/256, 256>>>(
        (const float*)d_in[11], (uint4*)w2_qkv, 768, 256, L_*768*256/4);
    wconv_frag<<<(L_*256*256/4 + 255)/256, 256>>>(
        (const float*)d_in[13], (uint4*)w2_out, 256, 256, L_*256*256/4);
    wconv_frag<<<(L_*512*256/4 + 255)/256, 256>>>(
        (const float*)d_in[17], (uint4*)w2_ff1, 512, 256, L_*512*256/4);
    wconv_frag<<<(L_*256*512/4 + 255)/256, 256>>>(
        (const float*)d_in[19], (uint4*)w2_ff2, 256, 512, L_*256*512/4);

    edge_bias_kernel<<<S_, 256>>>(
        (const float*)d_in[3], (const int*)d_in[2],
        (const float*)d_in[7], (const float*)d_in[8]);

    xf_kernel<<<S_, 256, SMEM_FLOATS * sizeof(float)>>>(
        (const float*)d_in[0], d_in[1],
        (const float*)d_in[9],  (const float*)d_in[10],
        (const float*)d_in[12], (const float*)d_in[14],
        (const float*)d_in[15], (const float*)d_in[16],
        (const float*)d_in[18], (const float*)d_in[20],
        (const float*)d_in[21], (const float*)d_in[22],
        (float*)d_out);
}

// round 12
// speedup vs baseline: 3.1905x; 1.0005x over previous
#include <cuda_runtime.h>
#include <cuda_bf16.h>
#include <math.h>

// Problem constants (LocalSubgraphTransformer)
#define S_   2048
#define K_   32
#define H_   256
#define NH_  8
#define DH_  32
#define L_   4
#define ED_  16
#define FFN_ 512
#define EPS_ 64
#define E_   (S_*EPS_)

#define LDA2 520    // XN2 row stride (bf16): hi 256 | lo 256 | pad 8
#define LDB2 1032   // BUF2 row stride (bf16): hi 512 | lo 512 | pad 8
#define LDQ  772    // qkv fp32 row stride

// ---------------- device scratch ----------------
__device__ __nv_bfloat16 g_bias16[(size_t)S_ * NH_ * K_ * K_];   // [S][h][k][q]
// weights in mma B-fragment order, hi/lo: N*2*KA bf16 each
__device__ unsigned g_w2_qkv[(size_t)L_ * 768 * 256];   // u32 words = N*2KA/2
__device__ unsigned g_w2_out[(size_t)L_ * 256 * 256];
__device__ unsigned g_w2_ff1[(size_t)L_ * 512 * 256];
__device__ unsigned g_w2_ff2[(size_t)L_ * 256 * 512];

// ---------------------------------------------------------------------------
// Weight conversion: fp32 [L][N][KA] row-major -> B-fragment layout.
// Unit (16 B = 4 words) uid = ((((pass*T + kt)*8 + ng)*2 + j)*2 + hl)*32 + lane
//   n = pass*128 + ng*16 + j*8 + (lane>>2)
//   word w: k = kt*32 + (w>>1)*16 + (lane&3)*2 + (w&1)*8, covers {k, k+1}
//   hl=0: hi part, hl=1: lo residual
// ---------------------------------------------------------------------------
__global__ void wconv_frag(const float* __restrict__ src, uint4* __restrict__ dst,
                           int N, int KA, int total_units)
{
    const int e = blockIdx.x*256 + threadIdx.x;
    if (e >= total_units) return;
    const int UPL = N*KA/4;            // units per layer
    const int l = e / UPL;
    int u = e - l*UPL;
    const int lane = u & 31; u >>= 5;
    const int hl = u & 1; u >>= 1;
    const int j = u & 1; u >>= 1;
    const int ng = u & 7; u >>= 3;
    const int T = KA/32;
    const int kt = u % T;
    const int pass = u / T;
    const int n = pass*128 + ng*16 + j*8 + (lane>>2);
    const float* sp = src + ((size_t)l*N + n)*KA;

    unsigned words[4];
    #pragma unroll
    for (int w = 0; w < 4; w++) {
        const int k = kt*32 + (w>>1)*16 + (lane&3)*2 + (w&1)*8;
        const float f0 = sp[k], f1 = sp[k+1];
        __nv_bfloat16 v0, v1;
        if (hl == 0) { v0 = __float2bfloat16(f0); v1 = __float2bfloat16(f1); }
        else {
            const __nv_bfloat16 h0 = __float2bfloat16(f0), h1 = __float2bfloat16(f1);
            v0 = __float2bfloat16(f0 - __bfloat162float(h0));
            v1 = __float2bfloat16(f1 - __bfloat162float(h1));
        }
        unsigned lo16 = (unsigned)*(unsigned short*)&v0;
        unsigned hi16 = (unsigned)*(unsigned short*)&v1;
        words[w] = lo16 | (hi16 << 16);
    }
    dst[e] = make_uint4(words[0], words[1], words[2], words[3]);
}

// ---------------------------------------------------------------------------
// Kernel A: per-subgraph edge bias via shared-memory scatter-add
// ---------------------------------------------------------------------------
__global__ __launch_bounds__(256) void edge_bias_kernel(
    const float* __restrict__ ea, const int* __restrict__ eidx,
    const float* __restrict__ eW, const float* __restrict__ eb)
{
    __shared__ float sb[NH_*K_*K_];   // [h][dst=k][src=q]
    __shared__ float sa[EPS_*ED_];
    __shared__ float sw[NH_*ED_];
    __shared__ float sbv[NH_];
    const int s = blockIdx.x, tid = threadIdx.x;

    if (tid < NH_*ED_) sw[tid] = eW[tid];
    if (tid < NH_)     sbv[tid] = eb[tid];
    for (int i = tid; i < EPS_*ED_;  i += 256) sa[i] = ea[(size_t)s*EPS_*ED_ + i];
    for (int i = tid; i < NH_*K_*K_; i += 256) sb[i] = 0.f;
    __syncthreads();

    for (int t = tid; t < EPS_*NH_; t += 256) {
        const int i  = t >> 3;
        const int hh = t & 7;
        float p = sbv[hh];
        #pragma unroll
        for (int d = 0; d < ED_; d++) p = fmaf(sa[i*ED_+d], sw[hh*ED_+d], p);
        const int e  = s*EPS_ + i;
        const int sr = eidx[e];        // src = query index
        const int ds = eidx[E_ + e];   // dst = key index
        atomicAdd(&sb[hh*K_*K_ + ds*K_ + sr], p);
    }
    __syncthreads();
    for (int i = tid; i < NH_*K_*K_; i += 256)
        g_bias16[(size_t)s*NH_*K_*K_ + i] = __float2bfloat16(sb[i]);
}

// ---------------------------------------------------------------------------
// smem layout (float offsets)
// ---------------------------------------------------------------------------
#define OFF_X    0        /* 8192 f: X fp32 [32][256] */
#define OFF_BUF  8192     /* 24704 f: union { fp32 [32][772] qkv ; bf16 [32][1032] ffn2 } */
#define OFF_XN2  32896    /* 8320 f: bf16 [32][520] */
#define OFF_BS   41216    /* 4096 f: bf16 [8][32][32] */
#define OFF_KM   45312
#define OFF_V01  45344
#define SMEM_FLOATS 45376  /* 181504 bytes */

__device__ __forceinline__ unsigned sptr(const void* p) {
    return (unsigned)__cvta_generic_to_shared(p);
}
__device__ __forceinline__ void ldm_x4(unsigned& a0, unsigned& a1, unsigned& a2,
                                       unsigned& a3, unsigned addr) {
    asm volatile("ldmatrix.sync.aligned.m8n8.x4.shared.b16 {%0,%1,%2,%3},[%4];"
                 : "=r"(a0), "=r"(a1), "=r"(a2), "=r"(a3) : "r"(addr));
}
__device__ __forceinline__ void mma16816(float* c, const unsigned* a,
                                         unsigned b0, unsigned b1) {
    asm volatile("mma.sync.aligned.m16n8k16.row.col.f32.bf16.bf16.f32 "
                 "{%0,%1,%2,%3},{%4,%5,%6,%7},{%8,%9},{%0,%1,%2,%3};"
                 : "+f"(c[0]), "+f"(c[1]), "+f"(c[2]), "+f"(c[3])
                 : "r"(a[0]), "r"(a[1]), "r"(a[2]), "r"(a[3]), "r"(b0), "r"(b1));
}
__device__ __forceinline__ void hilo(float v, __nv_bfloat16& hi, __nv_bfloat16& lo) {
    hi = __float2bfloat16(v);
    lo = __float2bfloat16(v - __bfloat162float(hi));
}

// ---------------------------------------------------------------------------
// Tensor-core GEMM, hi/lo split, B via direct LDG from fragment-layout weights,
// with register double-buffered B prefetch (lookahead ~1.5 steps).
// C = A_hi W_hi^T + A_hi W_lo^T + A_lo W_hi^T + bias
// A: smem bf16 [32][hi KA | lo KA] (ld lda). Warp tile m32 x n16.
// Passes processed in pairs (n256 blocks); steps = (kt, p), p parity static.
// MODE 0: fp32 -> BUFf (ld LDQ); 1: relu -> hi/lo BUF2; 2: += X (ld H_)
// ---------------------------------------------------------------------------
template<int N, int KA, int MODE>
__device__ __forceinline__ void mm3(const __nv_bfloat16* A, int lda,
    const uint4* __restrict__ Wf, const float* __restrict__ bias,
    float* Xd, float* BUFf, __nv_bfloat16* BUF2, int tid)
{
    const int lane = tid & 31, wid = tid >> 5;
    constexpr int T = KA/32;          // k32 stages
    constexpr int NB = N/256;         // pass-pair blocks
    // A ldmatrix base: row = lane&15, 16B col = (lane>>4)
    const unsigned a_s = sptr(A) + (unsigned)(((lane & 15)*lda + ((lane >> 4) << 3))*2);

    for (int blk = 0; blk < NB; blk++) {
        float acc[2][2][2][4];   // [p][mi][j][4]
        #pragma unroll
        for (int p = 0; p < 2; p++)
            #pragma unroll
            for (int mi = 0; mi < 2; mi++)
                #pragma unroll
                for (int j = 0; j < 2; j++)
                    #pragma unroll
                    for (int i = 0; i < 4; i++) acc[p][mi][j][i] = 0.f;

        // B fragment loader: step = 2*kt + p; buf[0]=j0 hi, [1]=j0 lo, [2]=j1 hi, [3]=j1 lo
        #define LDB(step, buf) do {                                                   \
            const int _p = (step) & 1, _kt = (step) >> 1;                             \
            const size_t _b = ((size_t)(((blk*2 + _p)*T + _kt)*8 + wid)*4)*32 + lane; \
            (buf)[0] = Wf[_b];       (buf)[1] = Wf[_b + 32];                          \
            (buf)[2] = Wf[_b + 64];  (buf)[3] = Wf[_b + 96];                          \
        } while (0)

        uint4 b0[4], b1[4];
        LDB(0, b0);
        LDB(1, b1);

        for (int kt = 0; kt < T; kt++) {
            // A fragments for this kt: [mi][ks] hi and lo (8 x ldmatrix.x4)
            unsigned ah[2][2][4], al[2][2][4];
            #pragma unroll
            for (int mi = 0; mi < 2; mi++)
                #pragma unroll
                for (int ks = 0; ks < 2; ks++) {
                    const unsigned base = a_s + (unsigned)((mi*16*lda + kt*32 + ks*16)*2);
                    ldm_x4(ah[mi][ks][0], ah[mi][ks][1], ah[mi][ks][2], ah[mi][ks][3], base);
                    ldm_x4(al[mi][ks][0], al[mi][ks][1], al[mi][ks][2], al[mi][ks][3],
                           base + (unsigned)(KA*2));
                }
            // ---- step p=0: consume b0, then refill b0 for step 2kt+2 ----
            #pragma unroll
            for (int mi = 0; mi < 2; mi++) {
                mma16816(acc[0][mi][0], ah[mi][0], b0[0].x, b0[0].y);
                mma16816(acc[0][mi][1], ah[mi][0], b0[2].x, b0[2].y);
                mma16816(acc[0][mi][0], ah[mi][1], b0[0].z, b0[0].w);
                mma16816(acc[0][mi][1], ah[mi][1], b0[2].z, b0[2].w);
                mma16816(acc[0][mi][0], ah[mi][0], b0[1].x, b0[1].y);
                mma16816(acc[0][mi][1], ah[mi][0], b0[3].x, b0[3].y);
                mma16816(acc[0][mi][0], ah[mi][1], b0[1].z, b0[1].w);
                mma16816(acc[0][mi][1], ah[mi][1], b0[3].z, b0[3].w);
                mma16816(acc[0][mi][0], al[mi][0], b0[0].x, b0[0].y);
                mma16816(acc[0][mi][1], al[mi][0], b0[2].x, b0[2].y);
                mma16816(acc[0][mi][0], al[mi][1], b0[0].z, b0[0].w);
                mma16816(acc[0][mi][1], al[mi][1], b0[2].z, b0[2].w);
            }
            if (kt + 1 < T) LDB(2*kt + 2, b0);
            // ---- step p=1: consume b1, then refill b1 for step 2kt+3 ----
            #pragma unroll
            for (int mi = 0; mi < 2; mi++) {
                mma16816(acc[1][mi][0], ah[mi][0], b1[0].x, b1[0].y);
                mma16816(acc[1][mi][1], ah[mi][0], b1[2].x, b1[2].y);
                mma16816(acc[1][mi][0], ah[mi][1], b1[0].z, b1[0].w);
                mma16816(acc[1][mi][1], ah[mi][1], b1[2].z, b1[2].w);
                mma16816(acc[1][mi][0], ah[mi][0], b1[1].x, b1[1].y);
                mma16816(acc[1][mi][1], ah[mi][0], b1[3].x, b1[3].y);
                mma16816(acc[1][mi][0], ah[mi][1], b1[1].z, b1[1].w);
                mma16816(acc[1][mi][1], ah[mi][1], b1[3].z, b1[3].w);
                mma16816(acc[1][mi][0], al[mi][0], b1[0].x, b1[0].y);
                mma16816(acc[1][mi][1], al[mi][0], b1[2].x, b1[2].y);
                mma16816(acc[1][mi][0], al[mi][1], b1[0].z, b1[0].w);
                mma16816(acc[1][mi][1], al[mi][1], b1[2].z, b1[2].w);
            }
            if (kt + 1 < T) LDB(2*kt + 3, b1);
        }
        #undef LDB
        // epilogue
        #pragma unroll
        for (int p = 0; p < 2; p++)
            #pragma unroll
            for (int mi = 0; mi < 2; mi++)
                #pragma unroll
                for (int j = 0; j < 2; j++) {
                    const int c = (blk*2 + p)*128 + wid*16 + j*8 + 2*(lane & 3);
                    const float bb0 = bias[c], bb1 = bias[c+1];
                    #pragma unroll
                    for (int rr = 0; rr < 2; rr++) {
                        const int r = mi*16 + (lane >> 2) + rr*8;
                        float v0 = acc[p][mi][j][rr*2+0] + bb0;
                        float v1 = acc[p][mi][j][rr*2+1] + bb1;
                        if (MODE == 0) {
                            BUFf[r*LDQ + c]   = v0;
                            BUFf[r*LDQ + c+1] = v1;
                        } else if (MODE == 2) {
                            Xd[r*H_ + c]   += v0;
                            Xd[r*H_ + c+1] += v1;
                        } else {
                            v0 = fmaxf(v0, 0.f); v1 = fmaxf(v1, 0.f);
                            __nv_bfloat16 h0, l0, h1, l1;
                            hilo(v0, h0, l0); hilo(v1, h1, l1);
                            __nv_bfloat16* d = BUF2 + r*LDB2;
                            d[c] = h0;       d[c+1] = h1;
                            d[512 + c] = l0; d[512 + c+1] = l1;
                        }
                    }
                }
    }
}

// ---------------------------------------------------------------------------
// LayerNorm over 32 rows. OM 0: fp32 dst (ld H_); OM 1: hi/lo bf16 (ld LDA2)
// ---------------------------------------------------------------------------
template<int OM>
__device__ __forceinline__ void ln32(const float* src, void* dstv,
                                     const float* __restrict__ g,
                                     const float* __restrict__ b, int tid)
{
    const int w = tid >> 5, lane = tid & 31;
    #pragma unroll
    for (int j = 0; j < 4; j++) {
        const int r = w*4 + j;
        float sum = 0.f, sq = 0.f;
        #pragma unroll
        for (int i = 0; i < 8; i++) {
            const float v = src[r*H_ + lane + i*32];
            sum += v; sq = fmaf(v, v, sq);
        }
        #pragma unroll
        for (int o = 16; o > 0; o >>= 1) {
            sum += __shfl_xor_sync(0xffffffffu, sum, o);
            sq  += __shfl_xor_sync(0xffffffffu, sq,  o);
        }
        const float mu   = sum * (1.f/H_);
        const float var  = sq * (1.f/H_) - mu*mu;
        const float rstd = rsqrtf(var + 1e-5f);
        #pragma unroll
        for (int i = 0; i < 8; i++) {
            const int c = lane + i*32;
            const float y = fmaf((src[r*H_ + c] - mu)*rstd, g[c], b[c]);
            if (OM == 0) {
                ((float*)dstv)[r*H_ + c] = y;
            } else {
                __nv_bfloat16 hi, lo; hilo(y, hi, lo);
                __nv_bfloat16* d = (__nv_bfloat16*)dstv + r*LDA2;
                d[c] = hi; d[256 + c] = lo;
            }
        }
    }
}

// ---------------------------------------------------------------------------
// Attention: warp = head, lane = query row. qkv fp32 in BUFf (ld LDQ);
// output written as hi/lo bf16 into XN2.
// ---------------------------------------------------------------------------
__device__ __forceinline__ void attn32(const float* BUFf, const __nv_bfloat16* BS,
                                       const float* KM, __nv_bfloat16* XN2, int tid)
{
    const int head = tid >> 5, lane = tid & 31;
    const float scale = 0.17677669529663687f;  // 1/sqrt(32)

    float4 q4[8];
    const float4* qp = (const float4*)(BUFf + lane*LDQ + head*32);
    #pragma unroll
    for (int j = 0; j < 8; j++) q4[j] = qp[j];

    float sc[32];
    float m = -3.0e38f;
    #pragma unroll
    for (int kr = 0; kr < 32; kr++) {
        const float4* kp = (const float4*)(BUFf + kr*LDQ + 256 + head*32);
        float s = 0.f;
        #pragma unroll
        for (int j = 0; j < 8; j++) {
            const float4 kk = kp[j];
            s = fmaf(q4[j].x, kk.x, s); s = fmaf(q4[j].y, kk.y, s);
            s = fmaf(q4[j].z, kk.z, s); s = fmaf(q4[j].w, kk.w, s);
        }
        const float bv = __bfloat162float(BS[head*1024 + kr*32 + lane]);
        s = fmaf(s, scale, bv) + KM[kr];
        sc[kr] = s;
        m = fmaxf(m, s);
    }
    float den = 0.f;
    #pragma unroll
    for (int kr = 0; kr < 32; kr++) { const float e = __expf(sc[kr] - m); sc[kr] = e; den += e; }
    const float inv = 1.f / den;
    #pragma unroll
    for (int kr = 0; kr < 32; kr++) sc[kr] *= inv;

    #pragma unroll
    for (int dg = 0; dg < 8; dg++) {
        float4 acc = make_float4(0.f, 0.f, 0.f, 0.f);
        #pragma unroll
        for (int kr = 0; kr < 32; kr++) {
            const float4 v4 = *(const float4*)(BUFf + kr*LDQ + 512 + head*32 + dg*4);
            const float w = sc[kr];
            acc.x = fmaf(w, v4.x, acc.x); acc.y = fmaf(w, v4.y, acc.y);
            acc.z = fmaf(w, v4.z, acc.z); acc.w = fmaf(w, v4.w, acc.w);
        }
        const float av[4] = {acc.x, acc.y, acc.z, acc.w};
        __nv_bfloat16* d = XN2 + lane*LDA2;
        #pragma unroll
        for (int e = 0; e < 4; e++) {
            const int c = head*32 + dg*4 + e;
            __nv_bfloat16 hi, lo; hilo(av[e], hi, lo);
            d[c] = hi; d[256 + c] = lo;
        }
    }
}

// ---------------------------------------------------------------------------
__global__ __launch_bounds__(256, 1) void xf_kernel(
    const float* __restrict__ h, const void* __restrict__ validp,
    const float* __restrict__ ln1g, const float* __restrict__ ln1b,
    const float* __restrict__ qkvb, const float* __restrict__ outb,
    const float* __restrict__ ln2g, const float* __restrict__ ln2b,
    const float* __restrict__ ff1b, const float* __restrict__ ff2b,
    const float* __restrict__ fng, const float* __restrict__ fnb,
    float* __restrict__ out)
{
    extern __shared__ float sm[];
    float* X    = sm + OFF_X;
    float* BUFf = sm + OFF_BUF;
    __nv_bfloat16* BUF2 = (__nv_bfloat16*)(sm + OFF_BUF);
    __nv_bfloat16* XN2  = (__nv_bfloat16*)(sm + OFF_XN2);
    __nv_bfloat16* BS   = (__nv_bfloat16*)(sm + OFF_BS);
    float* KM  = sm + OFF_KM;
    float* V01 = sm + OFF_V01;
    const int s = blockIdx.x, tid = threadIdx.x;

    // Detect 'valid' encoding: byte bools vs 32-bit words.
    const unsigned char* vb = (const unsigned char*)validp;
    bool bytemode = false;
    #pragma unroll
    for (int i = 1; i < 128; i += 4) bytemode |= (vb[i] != 0);

    if (tid < K_) {
        bool v;
        if (bytemode) v = vb[s*K_ + tid] != 0;
        else          v = ((const unsigned int*)validp)[s*K_ + tid] != 0u;
        KM[tid]  = v ? 0.f : -1e30f;
        V01[tid] = v ? 1.f : 0.f;
    }
    for (int i = tid; i < K_*H_/4; i += 256)
        ((float4*)X)[i] = ((const float4*)(h + (size_t)s*K_*H_))[i];
    {
        const uint4* gb = (const uint4*)(g_bias16 + (size_t)s*NH_*K_*K_);
        uint4* sb = (uint4*)BS;
        for (int i = tid; i < 1024; i += 256) sb[i] = gb[i];
    }
    __syncthreads();

    for (int l = 0; l < L_; l++) {
        ln32<1>(X, XN2, ln1g + l*H_, ln1b + l*H_, tid);
        __syncthreads();
        mm3<768, 256, 0>(XN2, LDA2, (const uint4*)(g_w2_qkv + (size_t)l*768*256),
                         qkvb + l*768, X, BUFf, BUF2, tid);
        __syncthreads();
        attn32(BUFf, BS, KM, XN2, tid);
        __syncthreads();
        mm3<256, 256, 2>(XN2, LDA2, (const uint4*)(g_w2_out + (size_t)l*256*256),
                         outb + l*H_, X, BUFf, BUF2, tid);
        __syncthreads();
        ln32<1>(X, XN2, ln2g + l*H_, ln2b + l*H_, tid);
        __syncthreads();
        mm3<512, 256, 1>(XN2, LDA2, (const uint4*)(g_w2_ff1 + (size_t)l*512*256),
                         ff1b + l*FFN_, X, BUFf, BUF2, tid);
        __syncthreads();
        mm3<256, 512, 2>(BUF2, LDB2, (const uint4*)(g_w2_ff2 + (size_t)l*256*512),
                         ff2b + l*H_, X, BUFf, BUF2, tid);
        __syncthreads();
    }

    // final LN (fp32 into BUFf region, ld H_) + masked mean over k
    ln32<0>(X, BUFf, fng, fnb, tid);
    __syncthreads();
    float sum = 0.f, cnt = 0.f;
    #pragma unroll
    for (int r = 0; r < K_; r++) {
        sum = fmaf(BUFf[r*H_ + tid], V01[r], sum);
        cnt += V01[r];
    }
    out[(size_t)s*H_ + tid] = sum / fmaxf(cnt, 1.f);
}

// ---------------------------------------------------------------------------
extern "C" void kernel_launch(void* const* d_in, const int* in_sizes, int n_in,
                              void* d_out, int out_size)
{
    // inputs: 0 h, 1 valid, 2 edge_index, 3 ea_flat, 4 edge_ptr, 5 S, 6 k,
    // 7 edge_W, 8 edge_b, 9 ln1_g, 10 ln1_b, 11 qkv_W, 12 qkv_b, 13 out_W,
    // 14 out_b, 15 ln2_g, 16 ln2_b, 17 ff1_W, 18 ff1_b, 19 ff2_W, 20 ff2_b,
    // 21 fnorm_g, 22 fnorm_b
    cudaFuncSetAttribute(xf_kernel, cudaFuncAttributeMaxDynamicSharedMemorySize,
                         SMEM_FLOATS * (int)sizeof(float));

    unsigned *w2_qkv, *w2_out, *w2_ff1, *w2_ff2;
    cudaGetSymbolAddress((void**)&w2_qkv, g_w2_qkv);
    cudaGetSymbolAddress((void**)&w2_out, g_w2_out);
    cudaGetSymbolAddress((void**)&w2_ff1, g_w2_ff1);
    cudaGetSymbolAddress((void**)&w2_ff2, g_w2_ff2);

    // total_units = L * N*KA/4 per gemm
    wconv_frag<<<(L_*768*256/4 + 255)/256, 256>>>(
        (const float*)d_in[11], (uint4*)w2_qkv, 768, 256, L_*768*256/4);
    wconv_frag<<<(L_*256*256/4 + 255)/256, 256>>>(
        (const float*)d_in[13], (uint4*)w2_out, 256, 256, L_*256*256/4);
    wconv_frag<<<(L_*512*256/4 + 255)/256, 256>>>(
        (const float*)d_in[17], (uint4*)w2_ff1, 512, 256, L_*512*256/4);
    wconv_frag<<<(L_*256*512/4 + 255)/256, 256>>>(
        (const float*)d_in[19], (uint4*)w2_ff2, 256, 512, L_*256*512/4);

    edge_bias_kernel<<<S_, 256>>>(
        (const float*)d_in[3], (const int*)d_in[2],
        (const float*)d_in[7], (const float*)d_in[8]);

    xf_kernel<<<S_, 256, SMEM_FLOATS * sizeof(float)>>>(
        (const float*)d_in[0], d_in[1],
        (const float*)d_in[9],  (const float*)d_in[10],
        (const float*)d_in[12], (const float*)d_in[14],
        (const float*)d_in[15], (const float*)d_in[16],
        (const float*)d_in[18], (const float*)d_in[20],
        (const float*)d_in[21], (const float*)d_in[22],
        (float*)d_out);
}

// round 13
// speedup vs baseline: 4.1291x; 1.2942x over previous
#include <cuda_runtime.h>
#include <cuda_bf16.h>
#include <cuda_fp16.h>
#include <math.h>

// Problem constants (LocalSubgraphTransformer)
#define S_   2048
#define K_   32
#define H_   256
#define NH_  8
#define DH_  32
#define L_   4
#define ED_  16
#define FFN_ 512
#define EPS_ 64
#define E_   (S_*EPS_)

#define LDA2 520    // XN2 row stride (fp16): hi 256 | lo 256 | pad 8
#define LDB2 1032   // BUF2 row stride (fp16): hi 512 | lo 512 | pad 8
#define LDQ  772    // qkv fp32 row stride

// ---------------- device scratch ----------------
__device__ __nv_bfloat16 g_bias16[(size_t)S_ * NH_ * K_ * K_];   // [S][h][k][q]
// weights in mma B-fragment order, single fp16: N*KA fp16 = N*KA/2 u32 words
__device__ unsigned g_w2_qkv[(size_t)L_ * 768 * 128];
__device__ unsigned g_w2_out[(size_t)L_ * 256 * 128];
__device__ unsigned g_w2_ff1[(size_t)L_ * 512 * 128];
__device__ unsigned g_w2_ff2[(size_t)L_ * 256 * 256];

// ---------------------------------------------------------------------------
// Weight conversion: fp32 [L][N][KA] row-major -> fp16 B-fragment layout.
// Unit (16 B = 4 words) uid = (((pass*T + kt)*8 + ng)*2 + j)*32 + lane
//   n = pass*128 + ng*16 + j*8 + (lane>>2)
//   word w: k = kt*32 + (w>>1)*16 + (lane&3)*2 + (w&1)*8, covers {k, k+1}
// ---------------------------------------------------------------------------
__global__ void wconv_frag(const float* __restrict__ src, uint4* __restrict__ dst,
                           int N, int KA, int total_units)
{
    const int e = blockIdx.x*256 + threadIdx.x;
    if (e >= total_units) return;
    const int UPL = N*KA/8;            // units per layer
    const int l = e / UPL;
    int u = e - l*UPL;
    const int lane = u & 31; u >>= 5;
    const int j = u & 1; u >>= 1;
    const int ng = u & 7; u >>= 3;
    const int T = KA/32;
    const int kt = u % T;
    const int pass = u / T;
    const int n = pass*128 + ng*16 + j*8 + (lane>>2);
    const float* sp = src + ((size_t)l*N + n)*KA;

    unsigned words[4];
    #pragma unroll
    for (int w = 0; w < 4; w++) {
        const int k = kt*32 + (w>>1)*16 + (lane&3)*2 + (w&1)*8;
        const __half v0 = __float2half(sp[k]);
        const __half v1 = __float2half(sp[k+1]);
        unsigned lo16 = (unsigned)*(const unsigned short*)&v0;
        unsigned hi16 = (unsigned)*(const unsigned short*)&v1;
        words[w] = lo16 | (hi16 << 16);
    }
    dst[e] = make_uint4(words[0], words[1], words[2], words[3]);
}

// ---------------------------------------------------------------------------
// Kernel A: per-subgraph edge bias via shared-memory scatter-add
// ---------------------------------------------------------------------------
__global__ __launch_bounds__(256) void edge_bias_kernel(
    const float* __restrict__ ea, const int* __restrict__ eidx,
    const float* __restrict__ eW, const float* __restrict__ eb)
{
    __shared__ float sb[NH_*K_*K_];   // [h][dst=k][src=q]
    __shared__ float sa[EPS_*ED_];
    __shared__ float sw[NH_*ED_];
    __shared__ float sbv[NH_];
    const int s = blockIdx.x, tid = threadIdx.x;

    if (tid < NH_*ED_) sw[tid] = eW[tid];
    if (tid < NH_)     sbv[tid] = eb[tid];
    for (int i = tid; i < EPS_*ED_;  i += 256) sa[i] = ea[(size_t)s*EPS_*ED_ + i];
    for (int i = tid; i < NH_*K_*K_; i += 256) sb[i] = 0.f;
    __syncthreads();

    for (int t = tid; t < EPS_*NH_; t += 256) {
        const int i  = t >> 3;
        const int hh = t & 7;
        float p = sbv[hh];
        #pragma unroll
        for (int d = 0; d < ED_; d++) p = fmaf(sa[i*ED_+d], sw[hh*ED_+d], p);
        const int e  = s*EPS_ + i;
        const int sr = eidx[e];        // src = query index
        const int ds = eidx[E_ + e];   // dst = key index
        atomicAdd(&sb[hh*K_*K_ + ds*K_ + sr], p);
    }
    __syncthreads();
    for (int i = tid; i < NH_*K_*K_; i += 256)
        g_bias16[(size_t)s*NH_*K_*K_ + i] = __float2bfloat16(sb[i]);
}

// ---------------------------------------------------------------------------
// smem layout (float offsets)
// ---------------------------------------------------------------------------
#define OFF_X    0        /* 8192 f: X fp32 [32][256] */
#define OFF_BUF  8192     /* 24704 f: union { fp32 [32][772] qkv ; fp16 [32][1032] ffn2 } */
#define OFF_XN2  32896    /* 8320 f: fp16 [32][520] */
#define OFF_BS   41216    /* 4096 f: bf16 [8][32][32] */
#define OFF_KM   45312
#define OFF_V01  45344
#define SMEM_FLOATS 45376  /* 181504 bytes */

__device__ __forceinline__ unsigned sptr(const void* p) {
    return (unsigned)__cvta_generic_to_shared(p);
}
__device__ __forceinline__ void ldm_x4(unsigned& a0, unsigned& a1, unsigned& a2,
                                       unsigned& a3, unsigned addr) {
    asm volatile("ldmatrix.sync.aligned.m8n8.x4.shared.b16 {%0,%1,%2,%3},[%4];"
                 : "=r"(a0), "=r"(a1), "=r"(a2), "=r"(a3) : "r"(addr));
}
__device__ __forceinline__ void mma16816h(float* c, const unsigned* a,
                                          unsigned b0, unsigned b1) {
    asm volatile("mma.sync.aligned.m16n8k16.row.col.f32.f16.f16.f32 "
                 "{%0,%1,%2,%3},{%4,%5,%6,%7},{%8,%9},{%0,%1,%2,%3};"
                 : "+f"(c[0]), "+f"(c[1]), "+f"(c[2]), "+f"(c[3])
                 : "r"(a[0]), "r"(a[1]), "r"(a[2]), "r"(a[3]), "r"(b0), "r"(b1));
}
__device__ __forceinline__ void hilo16(float v, __half& hi, __half& lo) {
    hi = __float2half(v);
    lo = __float2half(v - __half2float(hi));
}

// ---------------------------------------------------------------------------
// Tensor-core GEMM: C = (A_hi + A_lo) W^T + bias, fp16 operands, fp32 accum.
// A: smem fp16 [32][hi KA | lo KA] (ld lda). W: gmem fp16 fragment layout.
// Warp tile m32 x n16; passes in pairs (n256); B register double-buffered.
// MODE 0: fp32 -> BUFf (ld LDQ); 1: relu -> hi/lo BUF2; 2: += X (ld H_)
// ---------------------------------------------------------------------------
template<int N, int KA, int MODE>
__device__ __forceinline__ void mm3(const __half* A, int lda,
    const uint4* __restrict__ Wf, const float* __restrict__ bias,
    float* Xd, float* BUFf, __half* BUF2, int tid)
{
    const int lane = tid & 31, wid = tid >> 5;
    constexpr int T = KA/32;          // k32 stages
    constexpr int NB = N/256;         // pass-pair blocks
    // A ldmatrix base: row = lane&15, 16B col = (lane>>4)
    const unsigned a_s = sptr(A) + (unsigned)(((lane & 15)*lda + ((lane >> 4) << 3))*2);

    for (int blk = 0; blk < NB; blk++) {
        float acc[2][2][2][4];   // [p][mi][j][4]
        #pragma unroll
        for (int p = 0; p < 2; p++)
            #pragma unroll
            for (int mi = 0; mi < 2; mi++)
                #pragma unroll
                for (int j = 0; j < 2; j++)
                    #pragma unroll
                    for (int i = 0; i < 4; i++) acc[p][mi][j][i] = 0.f;

        // B fragment loader: step = 2*kt + p; buf[0]=j0, buf[1]=j1
        #define LDB(step, buf) do {                                                   \
            const int _p = (step) & 1, _kt = (step) >> 1;                             \
            const size_t _b = ((size_t)(((blk*2 + _p)*T + _kt)*8 + wid)*2)*32 + lane; \
            (buf)[0] = Wf[_b];  (buf)[1] = Wf[_b + 32];                               \
        } while (0)

        uint4 b0[2], b1[2];
        LDB(0, b0);
        LDB(1, b1);

        for (int kt = 0; kt < T; kt++) {
            // A fragments for this kt: [mi][ks] hi and lo (8 x ldmatrix.x4)
            unsigned ah[2][2][4], al[2][2][4];
            #pragma unroll
            for (int mi = 0; mi < 2; mi++)
                #pragma unroll
                for (int ks = 0; ks < 2; ks++) {
                    const unsigned base = a_s + (unsigned)((mi*16*lda + kt*32 + ks*16)*2);
                    ldm_x4(ah[mi][ks][0], ah[mi][ks][1], ah[mi][ks][2], ah[mi][ks][3], base);
                    ldm_x4(al[mi][ks][0], al[mi][ks][1], al[mi][ks][2], al[mi][ks][3],
                           base + (unsigned)(KA*2));
                }
            // ---- step p=0: consume b0, then refill for step 2kt+2 ----
            #pragma unroll
            for (int mi = 0; mi < 2; mi++) {
                mma16816h(acc[0][mi][0], ah[mi][0], b0[0].x, b0[0].y);
                mma16816h(acc[0][mi][1], ah[mi][0], b0[1].x, b0[1].y);
                mma16816h(acc[0][mi][0], ah[mi][1], b0[0].z, b0[0].w);
                mma16816h(acc[0][mi][1], ah[mi][1], b0[1].z, b0[1].w);
                mma16816h(acc[0][mi][0], al[mi][0], b0[0].x, b0[0].y);
                mma16816h(acc[0][mi][1], al[mi][0], b0[1].x, b0[1].y);
                mma16816h(acc[0][mi][0], al[mi][1], b0[0].z, b0[0].w);
                mma16816h(acc[0][mi][1], al[mi][1], b0[1].z, b0[1].w);
            }
            if (kt + 1 < T) LDB(2*kt + 2, b0);
            // ---- step p=1: consume b1, then refill for step 2kt+3 ----
            #pragma unroll
            for (int mi = 0; mi < 2; mi++) {
                mma16816h(acc[1][mi][0], ah[mi][0], b1[0].x, b1[0].y);
                mma16816h(acc[1][mi][1], ah[mi][0], b1[1].x, b1[1].y);
                mma16816h(acc[1][mi][0], ah[mi][1], b1[0].z, b1[0].w);
                mma16816h(acc[1][mi][1], ah[mi][1], b1[1].z, b1[1].w);
                mma16816h(acc[1][mi][0], al[mi][0], b1[0].x, b1[0].y);
                mma16816h(acc[1][mi][1], al[mi][0], b1[1].x, b1[1].y);
                mma16816h(acc[1][mi][0], al[mi][1], b1[0].z, b1[0].w);
                mma16816h(acc[1][mi][1], al[mi][1], b1[1].z, b1[1].w);
            }
            if (kt + 1 < T) LDB(2*kt + 3, b1);
        }
        #undef LDB
        // epilogue
        #pragma unroll
        for (int p = 0; p < 2; p++)
            #pragma unroll
            for (int mi = 0; mi < 2; mi++)
                #pragma unroll
                for (int j = 0; j < 2; j++) {
                    const int c = (blk*2 + p)*128 + wid*16 + j*8 + 2*(lane & 3);
                    const float bb0 = bias[c], bb1 = bias[c+1];
                    #pragma unroll
                    for (int rr = 0; rr < 2; rr++) {
                        const int r = mi*16 + (lane >> 2) + rr*8;
                        float v0 = acc[p][mi][j][rr*2+0] + bb0;
                        float v1 = acc[p][mi][j][rr*2+1] + bb1;
                        if (MODE == 0) {
                            BUFf[r*LDQ + c]   = v0;
                            BUFf[r*LDQ + c+1] = v1;
                        } else if (MODE == 2) {
                            Xd[r*H_ + c]   += v0;
                            Xd[r*H_ + c+1] += v1;
                        } else {
                            v0 = fmaxf(v0, 0.f); v1 = fmaxf(v1, 0.f);
                            __half h0, l0, h1, l1;
                            hilo16(v0, h0, l0); hilo16(v1, h1, l1);
                            __half* d = BUF2 + r*LDB2;
                            d[c] = h0;       d[c+1] = h1;
                            d[512 + c] = l0; d[512 + c+1] = l1;
                        }
                    }
                }
    }
}

// ---------------------------------------------------------------------------
// LayerNorm over 32 rows. OM 0: fp32 dst (ld H_); OM 1: hi/lo fp16 (ld LDA2)
// ---------------------------------------------------------------------------
template<int OM>
__device__ __forceinline__ void ln32(const float* src, void* dstv,
                                     const float* __restrict__ g,
                                     const float* __restrict__ b, int tid)
{
    const int w = tid >> 5, lane = tid & 31;
    #pragma unroll
    for (int j = 0; j < 4; j++) {
        const int r = w*4 + j;
        float sum = 0.f, sq = 0.f;
        #pragma unroll
        for (int i = 0; i < 8; i++) {
            const float v = src[r*H_ + lane + i*32];
            sum += v; sq = fmaf(v, v, sq);
        }
        #pragma unroll
        for (int o = 16; o > 0; o >>= 1) {
            sum += __shfl_xor_sync(0xffffffffu, sum, o);
            sq  += __shfl_xor_sync(0xffffffffu, sq,  o);
        }
        const float mu   = sum * (1.f/H_);
        const float var  = sq * (1.f/H_) - mu*mu;
        const float rstd = rsqrtf(var + 1e-5f);
        #pragma unroll
        for (int i = 0; i < 8; i++) {
            const int c = lane + i*32;
            const float y = fmaf((src[r*H_ + c] - mu)*rstd, g[c], b[c]);
            if (OM == 0) {
                ((float*)dstv)[r*H_ + c] = y;
            } else {
                __half hi, lo; hilo16(y, hi, lo);
                __half* d = (__half*)dstv + r*LDA2;
                d[c] = hi; d[256 + c] = lo;
            }
        }
    }
}

// ---------------------------------------------------------------------------
// Attention: warp = head, lane = query row. qkv fp32 in BUFf (ld LDQ);
// output written as hi/lo fp16 into XN2.
// ---------------------------------------------------------------------------
__device__ __forceinline__ void attn32(const float* BUFf, const __nv_bfloat16* BS,
                                       const float* KM, __half* XN2, int tid)
{
    const int head = tid >> 5, lane = tid & 31;
    const float scale = 0.17677669529663687f;  // 1/sqrt(32)

    float4 q4[8];
    const float4* qp = (const float4*)(BUFf + lane*LDQ + head*32);
    #pragma unroll
    for (int j = 0; j < 8; j++) q4[j] = qp[j];

    float sc[32];
    float m = -3.0e38f;
    #pragma unroll
    for (int kr = 0; kr < 32; kr++) {
        const float4* kp = (const float4*)(BUFf + kr*LDQ + 256 + head*32);
        float s = 0.f;
        #pragma unroll
        for (int j = 0; j < 8; j++) {
            const float4 kk = kp[j];
            s = fmaf(q4[j].x, kk.x, s); s = fmaf(q4[j].y, kk.y, s);
            s = fmaf(q4[j].z, kk.z, s); s = fmaf(q4[j].w, kk.w, s);
        }
        const float bv = __bfloat162float(BS[head*1024 + kr*32 + lane]);
        s = fmaf(s, scale, bv) + KM[kr];
        sc[kr] = s;
        m = fmaxf(m, s);
    }
    float den = 0.f;
    #pragma unroll
    for (int kr = 0; kr < 32; kr++) { const float e = __expf(sc[kr] - m); sc[kr] = e; den += e; }
    const float inv = 1.f / den;
    #pragma unroll
    for (int kr = 0; kr < 32; kr++) sc[kr] *= inv;

    #pragma unroll
    for (int dg = 0; dg < 8; dg++) {
        float4 acc = make_float4(0.f, 0.f, 0.f, 0.f);
        #pragma unroll
        for (int kr = 0; kr < 32; kr++) {
            const float4 v4 = *(const float4*)(BUFf + kr*LDQ + 512 + head*32 + dg*4);
            const float w = sc[kr];
            acc.x = fmaf(w, v4.x, acc.x); acc.y = fmaf(w, v4.y, acc.y);
            acc.z = fmaf(w, v4.z, acc.z); acc.w = fmaf(w, v4.w, acc.w);
        }
        const float av[4] = {acc.x, acc.y, acc.z, acc.w};
        __half* d = XN2 + lane*LDA2;
        #pragma unroll
        for (int e = 0; e < 4; e++) {
            const int c = head*32 + dg*4 + e;
            __half hi, lo; hilo16(av[e], hi, lo);
            d[c] = hi; d[256 + c] = lo;
        }
    }
}

// ---------------------------------------------------------------------------
__global__ __launch_bounds__(256, 1) void xf_kernel(
    const float* __restrict__ h, const void* __restrict__ validp,
    const float* __restrict__ ln1g, const float* __restrict__ ln1b,
    const float* __restrict__ qkvb, const float* __restrict__ outb,
    const float* __restrict__ ln2g, const float* __restrict__ ln2b,
    const float* __restrict__ ff1b, const float* __restrict__ ff2b,
    const float* __restrict__ fng, const float* __restrict__ fnb,
    float* __restrict__ out)
{
    extern __shared__ float sm[];
    float* X    = sm + OFF_X;
    float* BUFf = sm + OFF_BUF;
    __half* BUF2 = (__half*)(sm + OFF_BUF);
    __half* XN2  = (__half*)(sm + OFF_XN2);
    __nv_bfloat16* BS = (__nv_bfloat16*)(sm + OFF_BS);
    float* KM  = sm + OFF_KM;
    float* V01 = sm + OFF_V01;
    const int s = blockIdx.x, tid = threadIdx.x;

    // Detect 'valid' encoding: byte bools vs 32-bit words.
    const unsigned char* vb = (const unsigned char*)validp;
    bool bytemode = false;
    #pragma unroll
    for (int i = 1; i < 128; i += 4) bytemode |= (vb[i] != 0);

    if (tid < K_) {
        bool v;
        if (bytemode) v = vb[s*K_ + tid] != 0;
        else          v = ((const unsigned int*)validp)[s*K_ + tid] != 0u;
        KM[tid]  = v ? 0.f : -1e30f;
        V01[tid] = v ? 1.f : 0.f;
    }
    for (int i = tid; i < K_*H_/4; i += 256)
        ((float4*)X)[i] = ((const float4*)(h + (size_t)s*K_*H_))[i];
    {
        const uint4* gb = (const uint4*)(g_bias16 + (size_t)s*NH_*K_*K_);
        uint4* sb = (uint4*)BS;
        for (int i = tid; i < 1024; i += 256) sb[i] = gb[i];
    }
    __syncthreads();

    for (int l = 0; l < L_; l++) {
        ln32<1>(X, XN2, ln1g + l*H_, ln1b + l*H_, tid);
        __syncthreads();
        mm3<768, 256, 0>(XN2, LDA2, (const uint4*)(g_w2_qkv + (size_t)l*768*128),
                         qkvb + l*768, X, BUFf, BUF2, tid);
        __syncthreads();
        attn32(BUFf, BS, KM, XN2, tid);
        __syncthreads();
        mm3<256, 256, 2>(XN2, LDA2, (const uint4*)(g_w2_out + (size_t)l*256*128),
                         outb + l*H_, X, BUFf, BUF2, tid);
        __syncthreads();
        ln32<1>(X, XN2, ln2g + l*H_, ln2b + l*H_, tid);
        __syncthreads();
        mm3<512, 256, 1>(XN2, LDA2, (const uint4*)(g_w2_ff1 + (size_t)l*512*128),
                         ff1b + l*FFN_, X, BUFf, BUF2, tid);
        __syncthreads();
        mm3<256, 512, 2>(BUF2, LDB2, (const uint4*)(g_w2_ff2 + (size_t)l*256*256),
                         ff2b + l*H_, X, BUFf, BUF2, tid);
        __syncthreads();
    }

    // final LN (fp32 into BUFf region, ld H_) + masked mean over k
    ln32<0>(X, BUFf, fng, fnb, tid);
    __syncthreads();
    float sum = 0.f, cnt = 0.f;
    #pragma unroll
    for (int r = 0; r < K_; r++) {
        sum = fmaf(BUFf[r*H_ + tid], V01[r], sum);
        cnt += V01[r];
    }
    out[(size_t)s*H_ + tid] = sum / fmaxf(cnt, 1.f);
}

// ---------------------------------------------------------------------------
extern "C" void kernel_launch(void* const* d_in, const int* in_sizes, int n_in,
                              void* d_out, int out_size)
{
    // inputs: 0 h, 1 valid, 2 edge_index, 3 ea_flat, 4 edge_ptr, 5 S, 6 k,
    // 7 edge_W, 8 edge_b, 9 ln1_g, 10 ln1_b, 11 qkv_W, 12 qkv_b, 13 out_W,
    // 14 out_b, 15 ln2_g, 16 ln2_b, 17 ff1_W, 18 ff1_b, 19 ff2_W, 20 ff2_b,
    // 21 fnorm_g, 22 fnorm_b
    cudaFuncSetAttribute(xf_kernel, cudaFuncAttributeMaxDynamicSharedMemorySize,
                         SMEM_FLOATS * (int)sizeof(float));

    unsigned *w2_qkv, *w2_out, *w2_ff1, *w2_ff2;
    cudaGetSymbolAddress((void**)&w2_qkv, g_w2_qkv);
    cudaGetSymbolAddress((void**)&w2_out, g_w2_out);
    cudaGetSymbolAddress((void**)&w2_ff1, g_w2_ff1);
    cudaGetSymbolAddress((void**)&w2_ff2, g_w2_ff2);

    // total_units = L * N*KA/8 per gemm
    wconv_frag<<<(L_*768*256/8 + 255)/256, 256>>>(
        (const float*)d_in[11], (uint4*)w2_qkv, 768, 256, L_*768*256/8);
    wconv_frag<<<(L_*256*256/8 + 255)/256, 256>>>(
        (const float*)d_in[13], (uint4*)w2_out, 256, 256, L_*256*256/8);
    wconv_frag<<<(L_*512*256/8 + 255)/256, 256>>>(
        (const float*)d_in[17], (uint4*)w2_ff1, 512, 256, L_*512*256/8);
    wconv_frag<<<(L_*256*512/8 + 255)/256, 256>>>(
        (const float*)d_in[19], (uint4*)w2_ff2, 256, 512, L_*256*512/8);

    edge_bias_kernel<<<S_, 256>>>(
        (const float*)d_in[3], (const int*)d_in[2],
        (const float*)d_in[7], (const float*)d_in[8]);

    xf_kernel<<<S_, 256, SMEM_FLOATS * sizeof(float)>>>(
        (const float*)d_in[0], d_in[1],
        (const float*)d_in[9],  (const float*)d_in[10],
        (const float*)d_in[12], (const float*)d_in[14],
        (const float*)d_in[15], (const float*)d_in[16],
        (const float*)d_in[18], (const float*)d_in[20],
        (const float*)d_in[21], (const float*)d_in[22],
        (float*)d_out);
}

// round 14
// speedup vs baseline: 4.2081x; 1.0191x over previous
#include <cuda_runtime.h>
#include <cuda_bf16.h>
#include <cuda_fp16.h>
#include <math.h>

// Problem constants (LocalSubgraphTransformer)
#define S_   2048
#define K_   32
#define H_   256
#define NH_  8
#define DH_  32
#define L_   4
#define ED_  16
#define FFN_ 512
#define EPS_ 64
#define E_   (S_*EPS_)

#define LDA2 520    // XN2 row stride (fp16): hi 256 | lo 256 | pad 8
#define LDB2 1032   // BUF2 row stride (fp16): hi 512 | lo 512 | pad 8
#define LDQ  772    // qkv fp32 row stride

// ---------------- device scratch ----------------
__device__ __nv_bfloat16 g_bias16[(size_t)S_ * NH_ * K_ * K_];   // [S][h][k][q]
// weights in mma B-fragment order, single fp16: N*KA fp16 = N*KA/2 u32 words
__device__ unsigned g_w2_qkv[(size_t)L_ * 768 * 128];
__device__ unsigned g_w2_out[(size_t)L_ * 256 * 128];
__device__ unsigned g_w2_ff1[(size_t)L_ * 512 * 128];
__device__ unsigned g_w2_ff2[(size_t)L_ * 256 * 256];

// ---------------------------------------------------------------------------
// Weight conversion: fp32 [L][N][KA] row-major -> fp16 B-fragment layout.
// Unit (16 B = 4 words) uid = (((pass*T + kt)*8 + ng)*2 + j)*32 + lane
//   n = pass*128 + ng*16 + j*8 + (lane>>2)
//   word w: k = kt*32 + (w>>1)*16 + (lane&3)*2 + (w&1)*8, covers {k, k+1}
// ---------------------------------------------------------------------------
__global__ void wconv_frag(const float* __restrict__ src, uint4* __restrict__ dst,
                           int N, int KA, int total_units)
{
    const int e = blockIdx.x*256 + threadIdx.x;
    if (e >= total_units) return;
    const int UPL = N*KA/8;            // units per layer
    const int l = e / UPL;
    int u = e - l*UPL;
    const int lane = u & 31; u >>= 5;
    const int j = u & 1; u >>= 1;
    const int ng = u & 7; u >>= 3;
    const int T = KA/32;
    const int kt = u % T;
    const int pass = u / T;
    const int n = pass*128 + ng*16 + j*8 + (lane>>2);
    const float* sp = src + ((size_t)l*N + n)*KA;

    unsigned words[4];
    #pragma unroll
    for (int w = 0; w < 4; w++) {
        const int k = kt*32 + (w>>1)*16 + (lane&3)*2 + (w&1)*8;
        const __half v0 = __float2half(sp[k]);
        const __half v1 = __float2half(sp[k+1]);
        unsigned lo16 = (unsigned)*(const unsigned short*)&v0;
        unsigned hi16 = (unsigned)*(const unsigned short*)&v1;
        words[w] = lo16 | (hi16 << 16);
    }
    dst[e] = make_uint4(words[0], words[1], words[2], words[3]);
}

// ---------------------------------------------------------------------------
// Kernel A: per-subgraph edge bias via shared-memory scatter-add
// ---------------------------------------------------------------------------
__global__ __launch_bounds__(256) void edge_bias_kernel(
    const float* __restrict__ ea, const int* __restrict__ eidx,
    const float* __restrict__ eW, const float* __restrict__ eb)
{
    __shared__ float sb[NH_*K_*K_];   // [h][dst=k][src=q]
    __shared__ float sa[EPS_*ED_];
    __shared__ float sw[NH_*ED_];
    __shared__ float sbv[NH_];
    const int s = blockIdx.x, tid = threadIdx.x;

    if (tid < NH_*ED_) sw[tid] = eW[tid];
    if (tid < NH_)     sbv[tid] = eb[tid];
    for (int i = tid; i < EPS_*ED_;  i += 256) sa[i] = ea[(size_t)s*EPS_*ED_ + i];
    for (int i = tid; i < NH_*K_*K_; i += 256) sb[i] = 0.f;
    __syncthreads();

    for (int t = tid; t < EPS_*NH_; t += 256) {
        const int i  = t >> 3;
        const int hh = t & 7;
        float p = sbv[hh];
        #pragma unroll
        for (int d = 0; d < ED_; d++) p = fmaf(sa[i*ED_+d], sw[hh*ED_+d], p);
        const int e  = s*EPS_ + i;
        const int sr = eidx[e];        // src = query index
        const int ds = eidx[E_ + e];   // dst = key index
        atomicAdd(&sb[hh*K_*K_ + ds*K_ + sr], p);
    }
    __syncthreads();
    for (int i = tid; i < NH_*K_*K_; i += 256)
        g_bias16[(size_t)s*NH_*K_*K_ + i] = __float2bfloat16(sb[i]);
}

// ---------------------------------------------------------------------------
// smem layout (float offsets)
// ---------------------------------------------------------------------------
#define OFF_X    0        /* 8192 f: X fp32 [32][256] */
#define OFF_BUF  8192     /* 24704 f: union { fp32 [32][772] qkv ; fp16 [32][1032] ffn2 } */
#define OFF_XN2  32896    /* 8320 f: fp16 [32][520] */
#define OFF_BS   41216    /* 4096 f: bf16 [8][32][32] */
#define OFF_KM   45312
#define OFF_V01  45344
#define SMEM_FLOATS 45376  /* 181504 bytes */

__device__ __forceinline__ unsigned sptr(const void* p) {
    return (unsigned)__cvta_generic_to_shared(p);
}
__device__ __forceinline__ void ldm_x4(unsigned& a0, unsigned& a1, unsigned& a2,
                                       unsigned& a3, unsigned addr) {
    asm volatile("ldmatrix.sync.aligned.m8n8.x4.shared.b16 {%0,%1,%2,%3},[%4];"
                 : "=r"(a0), "=r"(a1), "=r"(a2), "=r"(a3) : "r"(addr));
}
__device__ __forceinline__ void mma16816h(float* c, const unsigned* a,
                                          unsigned b0, unsigned b1) {
    asm volatile("mma.sync.aligned.m16n8k16.row.col.f32.f16.f16.f32 "
                 "{%0,%1,%2,%3},{%4,%5,%6,%7},{%8,%9},{%0,%1,%2,%3};"
                 : "+f"(c[0]), "+f"(c[1]), "+f"(c[2]), "+f"(c[3])
                 : "r"(a[0]), "r"(a[1]), "r"(a[2]), "r"(a[3]), "r"(b0), "r"(b1));
}
__device__ __forceinline__ void hilo16(float v, __half& hi, __half& lo) {
    hi = __float2half(v);
    lo = __float2half(v - __half2float(hi));
}

// ---------------------------------------------------------------------------
// Tensor-core GEMM: C = (A_hi + A_lo) W^T + bias, fp16 operands, fp32 accum.
// A: smem fp16 [32][hi KA | lo KA] (ld lda). W: gmem fp16 fragment layout.
// Warp tile m32 x n16; passes in pairs (n256 blocks).
// B operands: 4-slot register ring indexed by GLOBAL step (pipelines across
// blocks; lookahead 4 steps hides the ~250-cycle L2 latency).
// MODE 0: fp32 -> BUFf (ld LDQ); 1: relu -> hi/lo BUF2; 2: += X (ld H_)
// ---------------------------------------------------------------------------
template<int N, int KA, int MODE>
__device__ __forceinline__ void mm3(const __half* A, int lda,
    const uint4* __restrict__ Wf, const float* __restrict__ bias,
    float* Xd, float* BUFf, __half* BUF2, int tid)
{
    const int lane = tid & 31, wid = tid >> 5;
    constexpr int T  = KA/32;          // k32 stages per pass
    constexpr int NB = N/256;          // pass-pair blocks
    constexpr int TOT = NB*2*T;        // total global steps
    // A ldmatrix base: row = lane&15, 16B col = (lane>>4)
    const unsigned a_s = sptr(A) + (unsigned)(((lane & 15)*lda + ((lane >> 4) << 3))*2);

    // 4-slot B ring; 2T is a multiple of 4, so slot = local_step & 3 globally.
    uint4 ring[4][2];
    #define LDB_G(sg, slot) do {                                                    \
        if ((sg) < TOT) {                                                           \
            const int _blk = (sg) / (2*T);                                          \
            const int _sl  = (sg) - _blk*2*T;                                       \
            const int _p = _sl & 1, _kt = _sl >> 1;                                 \
            const size_t _b = ((size_t)(((_blk*2 + _p)*T + _kt)*8 + wid)*2)*32 + lane; \
            ring[slot][0] = Wf[_b];  ring[slot][1] = Wf[_b + 32];                   \
        }                                                                           \
    } while (0)

    LDB_G(0, 0); LDB_G(1, 1); LDB_G(2, 2); LDB_G(3, 3);

    for (int blk = 0; blk < NB; blk++) {
        float acc[2][2][2][4];   // [p][mi][j][4]
        #pragma unroll
        for (int p = 0; p < 2; p++)
            #pragma unroll
            for (int mi = 0; mi < 2; mi++)
                #pragma unroll
                for (int j = 0; j < 2; j++)
                    #pragma unroll
                    for (int i = 0; i < 4; i++) acc[p][mi][j][i] = 0.f;

        const int g0 = blk*2*T;
        #pragma unroll
        for (int kt = 0; kt < T; kt++) {
            // A fragments for this kt: [mi][ks] hi and lo (8 x ldmatrix.x4)
            unsigned ah[2][2][4], al[2][2][4];
            #pragma unroll
            for (int mi = 0; mi < 2; mi++)
                #pragma unroll
                for (int ks = 0; ks < 2; ks++) {
                    const unsigned base = a_s + (unsigned)((mi*16*lda + kt*32 + ks*16)*2);
                    ldm_x4(ah[mi][ks][0], ah[mi][ks][1], ah[mi][ks][2], ah[mi][ks][3], base);
                    ldm_x4(al[mi][ks][0], al[mi][ks][1], al[mi][ks][2], al[mi][ks][3],
                           base + (unsigned)(KA*2));
                }
            // ---- step p=0 (slot (2kt)&3): consume, then reload step +4 ----
            {
                const uint4* b = ring[(2*kt) & 3];
                #pragma unroll
                for (int mi = 0; mi < 2; mi++) {
                    mma16816h(acc[0][mi][0], ah[mi][0], b[0].x, b[0].y);
                    mma16816h(acc[0][mi][1], ah[mi][0], b[1].x, b[1].y);
                    mma16816h(acc[0][mi][0], ah[mi][1], b[0].z, b[0].w);
                    mma16816h(acc[0][mi][1], ah[mi][1], b[1].z, b[1].w);
                    mma16816h(acc[0][mi][0], al[mi][0], b[0].x, b[0].y);
                    mma16816h(acc[0][mi][1], al[mi][0], b[1].x, b[1].y);
                    mma16816h(acc[0][mi][0], al[mi][1], b[0].z, b[0].w);
                    mma16816h(acc[0][mi][1], al[mi][1], b[1].z, b[1].w);
                }
                LDB_G(g0 + 2*kt + 4, (2*kt) & 3);
            }
            // ---- step p=1 (slot (2kt+1)&3): consume, then reload step +4 ----
            {
                const uint4* b = ring[(2*kt + 1) & 3];
                #pragma unroll
                for (int mi = 0; mi < 2; mi++) {
                    mma16816h(acc[1][mi][0], ah[mi][0], b[0].x, b[0].y);
                    mma16816h(acc[1][mi][1], ah[mi][0], b[1].x, b[1].y);
                    mma16816h(acc[1][mi][0], ah[mi][1], b[0].z, b[0].w);
                    mma16816h(acc[1][mi][1], ah[mi][1], b[1].z, b[1].w);
                    mma16816h(acc[1][mi][0], al[mi][0], b[0].x, b[0].y);
                    mma16816h(acc[1][mi][1], al[mi][0], b[1].x, b[1].y);
                    mma16816h(acc[1][mi][0], al[mi][1], b[0].z, b[0].w);
                    mma16816h(acc[1][mi][1], al[mi][1], b[1].z, b[1].w);
                }
                LDB_G(g0 + 2*kt + 5, (2*kt + 1) & 3);
            }
        }
        // epilogue (next block's first B loads are already in flight)
        #pragma unroll
        for (int p = 0; p < 2; p++)
            #pragma unroll
            for (int mi = 0; mi < 2; mi++)
                #pragma unroll
                for (int j = 0; j < 2; j++) {
                    const int c = (blk*2 + p)*128 + wid*16 + j*8 + 2*(lane & 3);
                    const float bb0 = bias[c], bb1 = bias[c+1];
                    #pragma unroll
                    for (int rr = 0; rr < 2; rr++) {
                        const int r = mi*16 + (lane >> 2) + rr*8;
                        float v0 = acc[p][mi][j][rr*2+0] + bb0;
                        float v1 = acc[p][mi][j][rr*2+1] + bb1;
                        if (MODE == 0) {
                            BUFf[r*LDQ + c]   = v0;
                            BUFf[r*LDQ + c+1] = v1;
                        } else if (MODE == 2) {
                            Xd[r*H_ + c]   += v0;
                            Xd[r*H_ + c+1] += v1;
                        } else {
                            v0 = fmaxf(v0, 0.f); v1 = fmaxf(v1, 0.f);
                            __half h0, l0, h1, l1;
                            hilo16(v0, h0, l0); hilo16(v1, h1, l1);
                            __half* d = BUF2 + r*LDB2;
                            d[c] = h0;       d[c+1] = h1;
                            d[512 + c] = l0; d[512 + c+1] = l1;
                        }
                    }
                }
    }
    #undef LDB_G
}

// ---------------------------------------------------------------------------
// LayerNorm over 32 rows. OM 0: fp32 dst (ld H_); OM 1: hi/lo fp16 (ld LDA2)
// ---------------------------------------------------------------------------
template<int OM>
__device__ __forceinline__ void ln32(const float* src, void* dstv,
                                     const float* __restrict__ g,
                                     const float* __restrict__ b, int tid)
{
    const int w = tid >> 5, lane = tid & 31;
    #pragma unroll
    for (int j = 0; j < 4; j++) {
        const int r = w*4 + j;
        float sum = 0.f, sq = 0.f;
        #pragma unroll
        for (int i = 0; i < 8; i++) {
            const float v = src[r*H_ + lane + i*32];
            sum += v; sq = fmaf(v, v, sq);
        }
        #pragma unroll
        for (int o = 16; o > 0; o >>= 1) {
            sum += __shfl_xor_sync(0xffffffffu, sum, o);
            sq  += __shfl_xor_sync(0xffffffffu, sq,  o);
        }
        const float mu   = sum * (1.f/H_);
        const float var  = sq * (1.f/H_) - mu*mu;
        const float rstd = rsqrtf(var + 1e-5f);
        #pragma unroll
        for (int i = 0; i < 8; i++) {
            const int c = lane + i*32;
            const float y = fmaf((src[r*H_ + c] - mu)*rstd, g[c], b[c]);
            if (OM == 0) {
                ((float*)dstv)[r*H_ + c] = y;
            } else {
                __half hi, lo; hilo16(y, hi, lo);
                __half* d = (__half*)dstv + r*LDA2;
                d[c] = hi; d[256 + c] = lo;
            }
        }
    }
}

// ---------------------------------------------------------------------------
// Attention: warp = head, lane = query row. qkv fp32 in BUFf (ld LDQ);
// output written as hi/lo fp16 into XN2.
// ---------------------------------------------------------------------------
__device__ __forceinline__ void attn32(const float* BUFf, const __nv_bfloat16* BS,
                                       const float* KM, __half* XN2, int tid)
{
    const int head = tid >> 5, lane = tid & 31;
    const float scale = 0.17677669529663687f;  // 1/sqrt(32)

    float4 q4[8];
    const float4* qp = (const float4*)(BUFf + lane*LDQ + head*32);
    #pragma unroll
    for (int j = 0; j < 8; j++) q4[j] = qp[j];

    float sc[32];
    float m = -3.0e38f;
    #pragma unroll
    for (int kr = 0; kr < 32; kr++) {
        const float4* kp = (const float4*)(BUFf + kr*LDQ + 256 + head*32);
        float s = 0.f;
        #pragma unroll
        for (int j = 0; j < 8; j++) {
            const float4 kk = kp[j];
            s = fmaf(q4[j].x, kk.x, s); s = fmaf(q4[j].y, kk.y, s);
            s = fmaf(q4[j].z, kk.z, s); s = fmaf(q4[j].w, kk.w, s);
        }
        const float bv = __bfloat162float(BS[head*1024 + kr*32 + lane]);
        s = fmaf(s, scale, bv) + KM[kr];
        sc[kr] = s;
        m = fmaxf(m, s);
    }
    float den = 0.f;
    #pragma unroll
    for (int kr = 0; kr < 32; kr++) { const float e = __expf(sc[kr] - m); sc[kr] = e; den += e; }
    const float inv = 1.f / den;
    #pragma unroll
    for (int kr = 0; kr < 32; kr++) sc[kr] *= inv;

    #pragma unroll
    for (int dg = 0; dg < 8; dg++) {
        float4 acc = make_float4(0.f, 0.f, 0.f, 0.f);
        #pragma unroll
        for (int kr = 0; kr < 32; kr++) {
            const float4 v4 = *(const float4*)(BUFf + kr*LDQ + 512 + head*32 + dg*4);
            const float w = sc[kr];
            acc.x = fmaf(w, v4.x, acc.x); acc.y = fmaf(w, v4.y, acc.y);
            acc.z = fmaf(w, v4.z, acc.z); acc.w = fmaf(w, v4.w, acc.w);
        }
        const float av[4] = {acc.x, acc.y, acc.z, acc.w};
        __half* d = XN2 + lane*LDA2;
        #pragma unroll
        for (int e = 0; e < 4; e++) {
            const int c = head*32 + dg*4 + e;
            __half hi, lo; hilo16(av[e], hi, lo);
            d[c] = hi; d[256 + c] = lo;
        }
    }
}

// ---------------------------------------------------------------------------
__global__ __launch_bounds__(256, 1) void xf_kernel(
    const float* __restrict__ h, const void* __restrict__ validp,
    const float* __restrict__ ln1g, const float* __restrict__ ln1b,
    const float* __restrict__ qkvb, const float* __restrict__ outb,
    const float* __restrict__ ln2g, const float* __restrict__ ln2b,
    const float* __restrict__ ff1b, const float* __restrict__ ff2b,
    const float* __restrict__ fng, const float* __restrict__ fnb,
    float* __restrict__ out)
{
    extern __shared__ float sm[];
    float* X    = sm + OFF_X;
    float* BUFf = sm + OFF_BUF;
    __half* BUF2 = (__half*)(sm + OFF_BUF);
    __half* XN2  = (__half*)(sm + OFF_XN2);
    __nv_bfloat16* BS = (__nv_bfloat16*)(sm + OFF_BS);
    float* KM  = sm + OFF_KM;
    float* V01 = sm + OFF_V01;
    const int s = blockIdx.x, tid = threadIdx.x;

    // Detect 'valid' encoding: byte bools vs 32-bit words.
    const unsigned char* vb = (const unsigned char*)validp;
    bool bytemode = false;
    #pragma unroll
    for (int i = 1; i < 128; i += 4) bytemode |= (vb[i] != 0);

    if (tid < K_) {
        bool v;
        if (bytemode) v = vb[s*K_ + tid] != 0;
        else          v = ((const unsigned int*)validp)[s*K_ + tid] != 0u;
        KM[tid]  = v ? 0.f : -1e30f;
        V01[tid] = v ? 1.f : 0.f;
    }
    for (int i = tid; i < K_*H_/4; i += 256)
        ((float4*)X)[i] = ((const float4*)(h + (size_t)s*K_*H_))[i];
    {
        const uint4* gb = (const uint4*)(g_bias16 + (size_t)s*NH_*K_*K_);
        uint4* sb = (uint4*)BS;
        for (int i = tid; i < 1024; i += 256) sb[i] = gb[i];
    }
    __syncthreads();

    for (int l = 0; l < L_; l++) {
        ln32<1>(X, XN2, ln1g + l*H_, ln1b + l*H_, tid);
        __syncthreads();
        mm3<768, 256, 0>(XN2, LDA2, (const uint4*)(g_w2_qkv + (size_t)l*768*128),
                         qkvb + l*768, X, BUFf, BUF2, tid);
        __syncthreads();
        attn32(BUFf, BS, KM, XN2, tid);
        __syncthreads();
        mm3<256, 256, 2>(XN2, LDA2, (const uint4*)(g_w2_out + (size_t)l*256*128),
                         outb + l*H_, X, BUFf, BUF2, tid);
        __syncthreads();
        ln32<1>(X, XN2, ln2g + l*H_, ln2b + l*H_, tid);
        __syncthreads();
        mm3<512, 256, 1>(XN2, LDA2, (const uint4*)(g_w2_ff1 + (size_t)l*512*128),
                         ff1b + l*FFN_, X, BUFf, BUF2, tid);
        __syncthreads();
        mm3<256, 512, 2>(BUF2, LDB2, (const uint4*)(g_w2_ff2 + (size_t)l*256*256),
                         ff2b + l*H_, X, BUFf, BUF2, tid);
        __syncthreads();
    }

    // final LN (fp32 into BUFf region, ld H_) + masked mean over k
    ln32<0>(X, BUFf, fng, fnb, tid);
    __syncthreads();
    float sum = 0.f, cnt = 0.f;
    #pragma unroll
    for (int r = 0; r < K_; r++) {
        sum = fmaf(BUFf[r*H_ + tid], V01[r], sum);
        cnt += V01[r];
    }
    out[(size_t)s*H_ + tid] = sum / fmaxf(cnt, 1.f);
}

// ---------------------------------------------------------------------------
extern "C" void kernel_launch(void* const* d_in, const int* in_sizes, int n_in,
                              void* d_out, int out_size)
{
    // inputs: 0 h, 1 valid, 2 edge_index, 3 ea_flat, 4 edge_ptr, 5 S, 6 k,
    // 7 edge_W, 8 edge_b, 9 ln1_g, 10 ln1_b, 11 qkv_W, 12 qkv_b, 13 out_W,
    // 14 out_b, 15 ln2_g, 16 ln2_b, 17 ff1_W, 18 ff1_b, 19 ff2_W, 20 ff2_b,
    // 21 fnorm_g, 22 fnorm_b
    cudaFuncSetAttribute(xf_kernel, cudaFuncAttributeMaxDynamicSharedMemorySize,
                         SMEM_FLOATS * (int)sizeof(float));

    unsigned *w2_qkv, *w2_out, *w2_ff1, *w2_ff2;
    cudaGetSymbolAddress((void**)&w2_qkv, g_w2_qkv);
    cudaGetSymbolAddress((void**)&w2_out, g_w2_out);
    cudaGetSymbolAddress((void**)&w2_ff1, g_w2_ff1);
    cudaGetSymbolAddress((void**)&w2_ff2, g_w2_ff2);

    // total_units = L * N*KA/8 per gemm
    wconv_frag<<<(L_*768*256/8 + 255)/256, 256>>>(
        (const float*)d_in[11], (uint4*)w2_qkv, 768, 256, L_*768*256/8);
    wconv_frag<<<(L_*256*256/8 + 255)/256, 256>>>(
        (const float*)d_in[13], (uint4*)w2_out, 256, 256, L_*256*256/8);
    wconv_frag<<<(L_*512*256/8 + 255)/256, 256>>>(
        (const float*)d_in[17], (uint4*)w2_ff1, 512, 256, L_*512*256/8);
    wconv_frag<<<(L_*256*512/8 + 255)/256, 256>>>(
        (const float*)d_in[19], (uint4*)w2_ff2, 256, 512, L_*256*512/8);

    edge_bias_kernel<<<S_, 256>>>(
        (const float*)d_in[3], (const int*)d_in[2],
        (const float*)d_in[7], (const float*)d_in[8]);

    xf_kernel<<<S_, 256, SMEM_FLOATS * sizeof(float)>>>(
        (const float*)d_in[0], d_in[1],
        (const float*)d_in[9],  (const float*)d_in[10],
        (const float*)d_in[12], (const float*)d_in[14],
        (const float*)d_in[15], (const float*)d_in[16],
        (const float*)d_in[18], (const float*)d_in[20],
        (const float*)d_in[21], (const float*)d_in[22],
        (float*)d_out);
}